// round 5
// baseline (speedup 1.0000x reference)
#include <cuda_runtime.h>
#include <math.h>

// ---------------- problem constants ----------------
#define KK 50
#define TT 50
#define VV 3000
#define LL 300
#define TH 800
#define EH 200
#define DD 256
#define SS 8

// ---------------- device scratch (static, no allocs) ----------------
__device__ double g_acc[4];                  // nll, kl_alpha, kl_eta, kl_theta
__device__ float  g_x[TT * EH];              // embedded rnn input
__device__ float  g_xw0[TT * 4 * EH];
__device__ float  g_xw1[TT * 4 * EH];
__device__ float  g_hs0[TT * EH];
__device__ float  g_hs1[TT * EH];
__device__ float  g_etas[TT * KK];
__device__ float  g_eta_td[DD * KK];
__device__ float  g_cat[DD * (VV + KK)];
__device__ float  g_h1[DD * TH];
__device__ float  g_h2[DD * TH];
__device__ float  g_theta[DD * KK];
__device__ float  g_wa[DD * KK * LL];        // alpha[k,t_d,:] * lam[s_d,:]
__device__ float  g_rhoT[LL * VV];           // rho transposed: [l][v]
__device__ float  g_E[DD * KK * VV];         // exp(logit)  (153.6 MB)
__device__ float  g_Z[DD * KK];              // sum_v exp(logit)

// ---------------- helpers ----------------
__device__ __forceinline__ unsigned long long pack2(float lo, float hi) {
    unsigned long long r;
    asm("mov.b64 %0, {%1, %2};" : "=l"(r) : "f"(lo), "f"(hi));
    return r;
}
__device__ __forceinline__ void unpack2(unsigned long long v, float& lo, float& hi) {
    asm("mov.b64 {%0, %1}, %2;" : "=f"(lo), "=f"(hi) : "l"(v));
}
__device__ __forceinline__ unsigned long long fma2(unsigned long long a,
                                                   unsigned long long b,
                                                   unsigned long long c) {
    unsigned long long d;
    asm("fma.rn.f32x2 %0, %1, %2, %3;" : "=l"(d) : "l"(a), "l"(b), "l"(c));
    return d;
}
__device__ __forceinline__ float sigm(float x) { return 1.0f / (1.0f + expf(-x)); }

// block reduce for 256 threads; valid on tid 0
__device__ __forceinline__ float block_reduce_256(float v, float* sr) {
    int tid = threadIdx.x;
#pragma unroll
    for (int off = 16; off; off >>= 1) v += __shfl_down_sync(0xffffffffu, v, off);
    if ((tid & 31) == 0) sr[tid >> 5] = v;
    __syncthreads();
    if (tid < 8) {
        v = sr[tid];
#pragma unroll
        for (int off = 4; off; off >>= 1) v += __shfl_down_sync(0xffu, v, off);
    }
    return v;
}

// ---------------- kernels ----------------
__global__ void k_zero() {
    int i = threadIdx.x;
    if (i < 4) g_acc[i] = 0.0;
}

// kl_alpha: elementwise over (K,T,L)
__global__ void k_kl_alpha(const float* __restrict__ mu, const float* __restrict__ ls) {
    const int N = KK * TT * LL;
    int idx = blockIdx.x * 256 + threadIdx.x;
    float c = 0.0f;
    if (idx < N) {
        int r = idx % (TT * LL);
        int t = r / LL;
        float qm = mu[idx], ql = ls[idx];
        if (t == 0) {
            c = (expf(ql) + qm * qm) / (1.0f + 1e-6f) - 1.0f - ql;
        } else {
            const float LOGD = -5.2983174f;          // log(0.005)
            float den = expf(LOGD) + 1e-6f;
            float dm = qm - mu[idx - LL];
            c = (expf(ql) + dm * dm) / den - 1.0f + LOGD - ql;
        }
    }
    __shared__ float sr[8];
    float s = block_reduce_256(c, sr);
    if (threadIdx.x == 0) atomicAdd(&g_acc[1], 0.5 * (double)s);
}

// tiled transpose: rhoT[l][v] = rho[v][l]
__global__ void k_rhoT(const float* __restrict__ rho) {
    __shared__ float tile[32][33];
    int v0 = blockIdx.x * 32, l0 = blockIdx.y * 32;
    int tx = threadIdx.x, ty = threadIdx.y;
    int v = v0 + tx, l = l0 + ty;
    if (v < VV && l < LL) tile[ty][tx] = rho[v * LL + l];
    __syncthreads();
    int vo = v0 + ty, lo = l0 + tx;
    if (vo < VV && lo < LL) g_rhoT[lo * VV + vo] = tile[tx][ty];
}

// generic tiled GEMM: C(MxN) = A(MxK) @ B(KxN) + bias, optional relu
__global__ void k_gemm(const float* __restrict__ A, const float* __restrict__ B,
                       const float* __restrict__ bias, float* __restrict__ C,
                       int M, int N, int Kd, int relu) {
    __shared__ float sA[16][65];
    __shared__ float sB[16][64];
    int tid = threadIdx.x;
    int tx = tid & 15, ty = tid >> 4;
    int row0 = blockIdx.y * 64 + ty * 4;
    int col0 = blockIdx.x * 64 + tx * 4;
    float acc[4][4];
#pragma unroll
    for (int i = 0; i < 4; i++)
#pragma unroll
        for (int j = 0; j < 4; j++) acc[i][j] = 0.0f;

    for (int k0 = 0; k0 < Kd; k0 += 16) {
#pragma unroll
        for (int i = 0; i < 4; i++) {
            int idx = tid + i * 256;
            int m = idx >> 4, kk = idx & 15;
            int gm = blockIdx.y * 64 + m, gk = k0 + kk;
            float v = 0.0f;
            if (gm < M && gk < Kd) v = A[gm * Kd + gk];
            sA[kk][m] = v;
        }
#pragma unroll
        for (int i = 0; i < 4; i++) {
            int idx = tid + i * 256;
            int kk = idx >> 6, n = idx & 63;
            int gk = k0 + kk, gn = blockIdx.x * 64 + n;
            float v = 0.0f;
            if (gk < Kd && gn < N) v = B[gk * N + gn];
            sB[kk][n] = v;
        }
        __syncthreads();
#pragma unroll
        for (int kk = 0; kk < 16; kk++) {
            float a[4], b[4];
#pragma unroll
            for (int i = 0; i < 4; i++) a[i] = sA[kk][ty * 4 + i];
#pragma unroll
            for (int j = 0; j < 4; j++) b[j] = sB[kk][tx * 4 + j];
#pragma unroll
            for (int i = 0; i < 4; i++)
#pragma unroll
                for (int j = 0; j < 4; j++) acc[i][j] += a[i] * b[j];
        }
        __syncthreads();
    }
#pragma unroll
    for (int i = 0; i < 4; i++)
#pragma unroll
        for (int j = 0; j < 4; j++) {
            int m = row0 + i, n = col0 + j;
            if (m < M && n < N) {
                float v = acc[i][j] + bias[n];
                if (relu) v = fmaxf(v, 0.0f);
                C[m * N + n] = v;
            }
        }
}

// LSTM recurrence: g = xw[t] + h @ Whh, gates, h/c update. Single block, 256 thr.
__global__ void __launch_bounds__(256) k_lstm(const float* __restrict__ xw,
                                              const float* __restrict__ Whh,
                                              float* __restrict__ hs) {
    __shared__ float h_s[EH];
    __shared__ float g_s[4 * EH];
    int tid = threadIdx.x;
    if (tid < EH) h_s[tid] = 0.0f;
    float c = 0.0f;
    __syncthreads();
    const float4* W4 = (const float4*)Whh;   // rows of 200 float4 (800 floats)
    const float4* xw4 = (const float4*)xw;
    for (int t = 0; t < TT; t++) {
        if (tid < EH) {
            float4 a = xw4[t * (4 * EH / 4) + tid];
#pragma unroll 4
            for (int i = 0; i < EH; i++) {
                float hv = h_s[i];
                float4 w = W4[i * (4 * EH / 4) + tid];
                a.x += hv * w.x; a.y += hv * w.y; a.z += hv * w.z; a.w += hv * w.w;
            }
            ((float4*)g_s)[tid] = a;
        }
        __syncthreads();
        if (tid < EH) {
            float ig = sigm(g_s[tid]);
            float fg = sigm(g_s[tid + EH]);
            float gg = tanhf(g_s[tid + 2 * EH]);
            float og = sigm(g_s[tid + 3 * EH]);
            c = fg * c + ig * gg;
            float h = og * tanhf(c);
            h_s[tid] = h;
            hs[t * EH + tid] = h;
        }
        __syncthreads();
    }
}

// eta scan: 50 sequential steps; computes etas and kl_eta. Single block 256 thr.
__global__ void __launch_bounds__(256) k_eta(const float* __restrict__ hs,
                                             const float* __restrict__ Wmu,
                                             const float* __restrict__ bmu,
                                             const float* __restrict__ Wls,
                                             const float* __restrict__ bls) {
    __shared__ float cat_s[256];
    __shared__ float mu_s[KK], ls_s[KK];
    int tid = threadIdx.x, warp = tid >> 5, lane = tid & 31;
    if (tid >= EH && tid < 256) cat_s[tid] = 0.0f;   // eta part init 0
    __syncthreads();
    double kl_acc = 0.0;
    const float LOGD = -5.2983174f;
    for (int t = 0; t < TT; t++) {
        if (tid < EH) cat_s[tid] = hs[t * EH + tid];
        __syncthreads();
        for (int job = warp; job < 2 * KK; job += 8) {
            int k = job >> 1, isls = job & 1;
            const float* W = isls ? Wls : Wmu;
            float s = 0.0f;
            for (int i = lane; i < EH + KK; i += 32) s += cat_s[i] * W[i * KK + k];
#pragma unroll
            for (int off = 16; off; off >>= 1) s += __shfl_down_sync(0xffffffffu, s, off);
            if (lane == 0) {
                s += isls ? bls[k] : bmu[k];
                if (isls) ls_s[k] = s; else mu_s[k] = s;
            }
        }
        __syncthreads();
        if (tid == 0) {
            float pls = (t == 0) ? 0.0f : LOGD;
            float den = expf(pls) + 1e-6f;
            double st = 0.0;
            for (int k = 0; k < KK; k++) {
                float mu = mu_s[k], ls = ls_s[k], ep = cat_s[EH + k];
                float dm = mu - ep;
                st += (double)((expf(ls) + dm * dm) / den - 1.0f + pls - ls);
            }
            kl_acc += st;
        }
        __syncthreads();
        if (tid < KK) {
            cat_s[EH + tid] = mu_s[tid];
            g_etas[t * KK + tid] = mu_s[tid];
        }
        __syncthreads();
    }
    if (tid == 0) g_acc[2] = 0.5 * kl_acc;
}

// build cat = [bows | eta_td], also scatter eta_td
__global__ void k_cat(const float* __restrict__ bows, const int* __restrict__ times) {
    int idx = blockIdx.x * 256 + threadIdx.x;
    if (idx >= DD * (VV + KK)) return;
    int d = idx / (VV + KK);
    int i = idx - d * (VV + KK);
    float v;
    if (i < VV) v = bows[d * VV + i];
    else {
        int t = times[d];
        v = g_etas[t * KK + (i - VV)];
        g_eta_td[d * KK + (i - VV)] = v;
    }
    g_cat[idx] = v;
}

// mu_th / ls_th + softmax theta + kl_theta, one block per document
__global__ void __launch_bounds__(128) k_muls(const float* __restrict__ Wmu,
                                              const float* __restrict__ bmu,
                                              const float* __restrict__ Wls,
                                              const float* __restrict__ bls) {
    int d = blockIdx.x;
    __shared__ float h_s[TH];
    __shared__ float mu_s[KK], ls_s[KK];
    int tid = threadIdx.x, warp = tid >> 5, lane = tid & 31;
    for (int i = tid; i < TH; i += 128) h_s[i] = g_h2[d * TH + i];
    __syncthreads();
    for (int job = warp; job < 2 * KK; job += 4) {
        int k = job >> 1, isls = job & 1;
        const float* W = isls ? Wls : Wmu;
        float s = 0.0f;
        for (int i = lane; i < TH; i += 32) s += h_s[i] * W[i * KK + k];
#pragma unroll
        for (int off = 16; off; off >>= 1) s += __shfl_down_sync(0xffffffffu, s, off);
        if (lane == 0) {
            s += isls ? bls[k] : bmu[k];
            if (isls) ls_s[k] = s; else mu_s[k] = s;
        }
    }
    __syncthreads();
    if (tid == 0) {
        float m = -1e30f;
        for (int k = 0; k < KK; k++) m = fmaxf(m, mu_s[k]);
        float sum = 0.0f;
        for (int k = 0; k < KK; k++) sum += expf(mu_s[k] - m);
        float inv = 1.0f / sum;
        double kl = 0.0;
        for (int k = 0; k < KK; k++) {
            g_theta[d * KK + k] = expf(mu_s[k] - m) * inv;
            float mu = mu_s[k], ls = ls_s[k], eta = g_eta_td[d * KK + k];
            float dm = mu - eta;
            kl += (double)((expf(ls) + dm * dm) / (1.0f + 1e-6f) - 1.0f - ls);
        }
        atomicAdd(&g_acc[3], 0.5 * kl);
    }
}

// build per-doc weight: wa[d,k,l] = alpha[k, t_d, l] * lam[s_d, l]
__global__ void k_wa(const float* __restrict__ alpha, const float* __restrict__ lam,
                     const int* __restrict__ times, const int* __restrict__ sources) {
    int idx = blockIdx.x * 256 + threadIdx.x;
    if (idx >= DD * KK * LL) return;
    int d = idx / (KK * LL);
    int r = idx - d * (KK * LL);
    int k = r / LL;
    int l = r - k * LL;
    int t = times[d], s = sources[d];
    g_wa[idx] = alpha[(k * TT + t) * LL + l] * lam[s * LL + l];
}

// big batched GEMM: E[d,k,v] = exp( rho[v,:] . wa[d,k,:] ), f32x2 packed FMA.
// 128 threads, each owns (v0+tid, v0+128+tid) packed in f32x2 halves,
// all 50 k accumulators in regs. Static smem < 48KB.
#define G1_LC 30
__global__ void __launch_bounds__(128) k_g1() {
    __shared__ unsigned long long rho2_s[G1_LC * 128];   // [c][tid]   30720 B
    __shared__ unsigned long long w2_s[G1_LC * KK];      // [c][k]     12000 B
    const int d = blockIdx.y;
    const int v0 = blockIdx.x * 256;
    const int tid = threadIdx.x;
    const int vlo = v0 + tid, vhi = v0 + 128 + tid;
    unsigned long long acc[KK];
#pragma unroll
    for (int k = 0; k < KK; k++) acc[k] = 0ull;
    const float* __restrict__ wa = g_wa + d * KK * LL;
    for (int chunk = 0; chunk < LL / G1_LC; chunk++) {
        const int l0 = chunk * G1_LC;
        // weights: w2_s[c*KK + k] = {w,w}
        for (int idx = tid; idx < KK * G1_LC; idx += 128) {
            int c = idx / KK, k = idx - c * KK;
            float w = wa[k * LL + l0 + c];
            w2_s[idx] = pack2(w, w);
        }
        // rho: coalesced from transposed copy, pre-packed per thread
#pragma unroll
        for (int c = 0; c < G1_LC; c++) {
            const float* rT = g_rhoT + (l0 + c) * VV;
            float rlo = (vlo < VV) ? rT[vlo] : 0.0f;
            float rhi = (vhi < VV) ? rT[vhi] : 0.0f;
            rho2_s[c * 128 + tid] = pack2(rlo, rhi);
        }
        __syncthreads();
#pragma unroll 1
        for (int c = 0; c < G1_LC; c++) {
            unsigned long long r2 = rho2_s[c * 128 + tid];
            const ulonglong2* w2p = (const ulonglong2*)&w2_s[c * KK];
#pragma unroll
            for (int j = 0; j < KK / 2; j++) {
                ulonglong2 w = w2p[j];
                acc[2 * j]     = fma2(r2, w.x, acc[2 * j]);
                acc[2 * j + 1] = fma2(r2, w.y, acc[2 * j + 1]);
            }
        }
        __syncthreads();
    }
    float* E = g_E + d * KK * VV;
#pragma unroll
    for (int k = 0; k < KK; k++) {
        float lo, hi;
        unpack2(acc[k], lo, hi);
        if (vlo < VV) E[k * VV + vlo] = expf(lo);
        if (vhi < VV) E[k * VV + vhi] = expf(hi);
    }
}

// Z[d,k] = sum_v E[d,k,v]
__global__ void k_z() {
    int row = blockIdx.x;          // d*KK + k
    const float* E = g_E + row * VV;
    float s = 0.0f;
    for (int v = threadIdx.x; v < VV; v += 256) s += E[v];
    __shared__ float sr[8];
    s = block_reduce_256(s, sr);
    if (threadIdx.x == 0) g_Z[row] = s;
}

// nll: lik[d,v] = sum_k (theta/Z) * E ;  acc -= log(lik+1e-6)*bows
__global__ void k_nll(const float* __restrict__ bows) {
    int d = blockIdx.y;
    int v = blockIdx.x * 256 + threadIdx.x;
    __shared__ float wk[KK];
    if (threadIdx.x < KK)
        wk[threadIdx.x] = g_theta[d * KK + threadIdx.x] / g_Z[d * KK + threadIdx.x];
    __syncthreads();
    float term = 0.0f;
    if (v < VV) {
        const float* E = g_E + d * KK * VV + v;
        float lik = 0.0f;
#pragma unroll
        for (int k = 0; k < KK; k++) lik += wk[k] * E[k * VV];
        term = logf(lik + 1e-6f) * bows[d * VV + v];
    }
    __shared__ float sr[8];
    float s = block_reduce_256(term, sr);
    if (threadIdx.x == 0) atomicAdd(&g_acc[0], -(double)s);
}

__global__ void k_final(float* out) {
    int i = threadIdx.x;
    if (i < 4) out[i] = (float)g_acc[i];
}

// ---------------- launch ----------------
extern "C" void kernel_launch(void* const* d_in, const int* in_sizes, int n_in,
                              void* d_out, int out_size) {
    const float* bows    = (const float*)d_in[0];
    const float* rnn_inp = (const float*)d_in[1];
    const int*   times   = (const int*)d_in[2];
    const int*   sources = (const int*)d_in[3];
    const float* rho     = (const float*)d_in[4];
    const float* lam     = (const float*)d_in[5];
    const float* mu_qa   = (const float*)d_in[6];
    const float* ls_qa   = (const float*)d_in[7];
    const float* W_t1    = (const float*)d_in[8];
    const float* b_t1    = (const float*)d_in[9];
    const float* W_t2    = (const float*)d_in[10];
    const float* b_t2    = (const float*)d_in[11];
    const float* W_mu_th = (const float*)d_in[12];
    const float* b_mu_th = (const float*)d_in[13];
    const float* W_ls_th = (const float*)d_in[14];
    const float* b_ls_th = (const float*)d_in[15];
    const float* W_em    = (const float*)d_in[16];
    const float* b_em    = (const float*)d_in[17];
    const float* Wih0    = (const float*)d_in[18];
    const float* Whh0    = (const float*)d_in[19];
    const float* bl0     = (const float*)d_in[20];
    const float* Wih1    = (const float*)d_in[21];
    const float* Whh1    = (const float*)d_in[22];
    const float* bl1     = (const float*)d_in[23];
    const float* W_mu_e  = (const float*)d_in[24];
    const float* b_mu_e  = (const float*)d_in[25];
    const float* W_ls_e  = (const float*)d_in[26];
    const float* b_ls_e  = (const float*)d_in[27];

    float *p_x, *p_xw0, *p_xw1, *p_hs0, *p_hs1, *p_cat, *p_h1, *p_h2;
    cudaGetSymbolAddress((void**)&p_x, g_x);
    cudaGetSymbolAddress((void**)&p_xw0, g_xw0);
    cudaGetSymbolAddress((void**)&p_xw1, g_xw1);
    cudaGetSymbolAddress((void**)&p_hs0, g_hs0);
    cudaGetSymbolAddress((void**)&p_hs1, g_hs1);
    cudaGetSymbolAddress((void**)&p_cat, g_cat);
    cudaGetSymbolAddress((void**)&p_h1, g_h1);
    cudaGetSymbolAddress((void**)&p_h2, g_h2);

    k_zero<<<1, 32>>>();
    k_kl_alpha<<<(KK * TT * LL + 255) / 256, 256>>>(mu_qa, ls_qa);

    // transpose rho for coalesced k_g1 fills
    k_rhoT<<<dim3((VV + 31) / 32, (LL + 31) / 32), dim3(32, 32)>>>(rho);

    // embedding:  x = rnn_inp @ W_em + b_em   (50 x 3000 @ 3000 x 200)
    k_gemm<<<dim3((EH + 63) / 64, (TT + 63) / 64), 256>>>(rnn_inp, W_em, b_em, p_x, TT, EH, VV, 0);
    // xw0 = x @ Wih0 + bl0
    k_gemm<<<dim3((4 * EH + 63) / 64, (TT + 63) / 64), 256>>>(p_x, Wih0, bl0, p_xw0, TT, 4 * EH, EH, 0);
    k_lstm<<<1, 256>>>(p_xw0, Whh0, p_hs0);
    k_gemm<<<dim3((4 * EH + 63) / 64, (TT + 63) / 64), 256>>>(p_hs0, Wih1, bl1, p_xw1, TT, 4 * EH, EH, 0);
    k_lstm<<<1, 256>>>(p_xw1, Whh1, p_hs1);

    k_eta<<<1, 256>>>(p_hs1, W_mu_e, b_mu_e, W_ls_e, b_ls_e);
    k_cat<<<(DD * (VV + KK) + 255) / 256, 256>>>(bows, times);

    // theta MLP
    k_gemm<<<dim3((TH + 63) / 64, (DD + 63) / 64), 256>>>(p_cat, W_t1, b_t1, p_h1, DD, TH, VV + KK, 1);
    k_gemm<<<dim3((TH + 63) / 64, (DD + 63) / 64), 256>>>(p_h1, W_t2, b_t2, p_h2, DD, TH, TH, 1);
    k_muls<<<DD, 128>>>(W_mu_th, b_mu_th, W_ls_th, b_ls_th);

    // beta / likelihood path
    k_wa<<<(DD * KK * LL + 255) / 256, 256>>>(mu_qa, lam, times, sources);
    k_g1<<<dim3((VV + 255) / 256, DD), 128>>>();
    k_z<<<DD * KK, 256>>>();
    k_nll<<<dim3((VV + 255) / 256, DD), 256>>>(bows);

    k_final<<<1, 4>>>((float*)d_out);
    (void)in_sizes; (void)n_in; (void)out_size;
}

// round 7
// speedup vs baseline: 2.2306x; 2.2306x over previous
#include <cuda_runtime.h>
#include <math.h>

// ---------------- problem constants ----------------
#define KK 50
#define TT 50
#define VV 3000
#define LL 300
#define TH 800
#define EH 200
#define DD 256
#define SS 8

// ---------------- device scratch (static, no allocs) ----------------
__device__ double   g_acc[4];                 // nll, kl_alpha, kl_eta, kl_theta
__device__ unsigned g_lbar[2];                // lstm spin barriers (per layer launch)
__device__ float  g_x[TT * EH];
__device__ float  g_xw0[TT * 4 * EH];
__device__ float  g_xw1[TT * 4 * EH];
__device__ float  g_hs0[TT * EH];
__device__ float  g_hs1[TT * EH];
__device__ float  g_gbuf[2][4 * EH];          // double-buffered gate exchange
__device__ float  g_etas[TT * KK];
__device__ float  g_eta_td[DD * KK];
__device__ float  g_cat[DD * (VV + KK)];
__device__ float  g_h1[DD * TH];
__device__ float  g_h2[DD * TH];
__device__ float  g_theta[DD * KK];
__device__ float  g_wa[DD * KK * LL];
__device__ float  g_rhoT[LL * VV];
__device__ float  g_WmueT[KK * (EH + KK)];
__device__ float  g_WlseT[KK * (EH + KK)];
__device__ float  g_WmuthT[KK * TH];
__device__ float  g_WlsthT[KK * TH];
__device__ float  g_E[DD * KK * VV];          // exp(logit), 153.6 MB
__device__ float  g_Z[DD * KK];

// ---------------- helpers ----------------
__device__ __forceinline__ unsigned long long pack2(float lo, float hi) {
    unsigned long long r;
    asm("mov.b64 %0, {%1, %2};" : "=l"(r) : "f"(lo), "f"(hi));
    return r;
}
__device__ __forceinline__ void unpack2(unsigned long long v, float& lo, float& hi) {
    asm("mov.b64 {%0, %1}, %2;" : "=f"(lo), "=f"(hi) : "l"(v));
}
__device__ __forceinline__ unsigned long long fma2(unsigned long long a,
                                                   unsigned long long b,
                                                   unsigned long long c) {
    unsigned long long d;
    asm("fma.rn.f32x2 %0, %1, %2, %3;" : "=l"(d) : "l"(a), "l"(b), "l"(c));
    return d;
}
__device__ __forceinline__ float sigm(float x) { return 1.0f / (1.0f + expf(-x)); }

__device__ __forceinline__ float block_reduce_256(float v, float* sr) {
    int tid = threadIdx.x;
#pragma unroll
    for (int off = 16; off; off >>= 1) v += __shfl_down_sync(0xffffffffu, v, off);
    if ((tid & 31) == 0) sr[tid >> 5] = v;
    __syncthreads();
    if (tid < 8) {
        v = sr[tid];
#pragma unroll
        for (int off = 4; off; off >>= 1) v += __shfl_down_sync(0xffu, v, off);
    }
    return v;
}

// ---------------- init ----------------
__global__ void k_zero() {
    int idx = blockIdx.x * 256 + threadIdx.x;
    if (idx < DD * KK) g_Z[idx] = 0.0f;
    if (idx < 4) g_acc[idx] = 0.0;
    if (idx < 2) g_lbar[idx] = 0u;
}

// kl_alpha: elementwise over (K,T,L)
__global__ void k_kl_alpha(const float* __restrict__ mu, const float* __restrict__ ls) {
    const int N = KK * TT * LL;
    int idx = blockIdx.x * 256 + threadIdx.x;
    float c = 0.0f;
    if (idx < N) {
        int r = idx % (TT * LL);
        int t = r / LL;
        float qm = mu[idx], ql = ls[idx];
        if (t == 0) {
            c = (expf(ql) + qm * qm) / (1.0f + 1e-6f) - 1.0f - ql;
        } else {
            const float LOGD = -5.2983174f;
            float den = expf(LOGD) + 1e-6f;
            float dm = qm - mu[idx - LL];
            c = (expf(ql) + dm * dm) / den - 1.0f + LOGD - ql;
        }
    }
    __shared__ float sr[8];
    float s = block_reduce_256(c, sr);
    if (threadIdx.x == 0) atomicAdd(&g_acc[1], 0.5 * (double)s);
}

// generic transpose: B[n*M+m] = A[m*N+n]   (A is MxN, B is NxM)
__global__ void k_transpose(const float* __restrict__ A, float* __restrict__ B,
                            int M, int N) {
    __shared__ float tile[32][33];
    int m0 = blockIdx.x * 32, n0 = blockIdx.y * 32;
    int tx = threadIdx.x, ty = threadIdx.y;
    int m = m0 + ty, n = n0 + tx;
    if (m < M && n < N) tile[ty][tx] = A[m * N + n];
    __syncthreads();
    int nb = n0 + ty, mb = m0 + tx;
    if (nb < N && mb < M) B[nb * M + mb] = tile[tx][ty];
}

// fill C with bias (row-broadcast)
__global__ void k_fill(float* __restrict__ C, const float* __restrict__ bias,
                       int M, int N) {
    int idx = blockIdx.x * 256 + threadIdx.x;
    if (idx < M * N) C[idx] = bias[idx % N];
}

__global__ void k_relu(float* __restrict__ C, int n) {
    int idx = blockIdx.x * 256 + threadIdx.x;
    if (idx < n) C[idx] = fmaxf(C[idx], 0.0f);
}

// split-K tiled GEMM: C += A(MxK) @ B(KxN) over k-slice, atomic epilogue
__global__ void k_gemm_sk(const float* __restrict__ A, const float* __restrict__ B,
                          float* __restrict__ C, int M, int N, int Kd, int kchunk) {
    __shared__ float sA[16][65];
    __shared__ float sB[16][64];
    int tid = threadIdx.x;
    int tx = tid & 15, ty = tid >> 4;
    int row0 = blockIdx.y * 64 + ty * 4;
    int col0 = blockIdx.x * 64 + tx * 4;
    int kb = blockIdx.z * kchunk;
    int ke = min(kb + kchunk, Kd);
    float acc[4][4];
#pragma unroll
    for (int i = 0; i < 4; i++)
#pragma unroll
        for (int j = 0; j < 4; j++) acc[i][j] = 0.0f;

    for (int k0 = kb; k0 < ke; k0 += 16) {
#pragma unroll
        for (int i = 0; i < 4; i++) {
            int idx = tid + i * 256;
            int m = idx >> 4, kk = idx & 15;
            int gm = blockIdx.y * 64 + m, gk = k0 + kk;
            float v = 0.0f;
            if (gm < M && gk < ke) v = A[gm * Kd + gk];
            sA[kk][m] = v;
        }
#pragma unroll
        for (int i = 0; i < 4; i++) {
            int idx = tid + i * 256;
            int kk = idx >> 6, n = idx & 63;
            int gk = k0 + kk, gn = blockIdx.x * 64 + n;
            float v = 0.0f;
            if (gk < ke && gn < N) v = B[gk * N + gn];
            sB[kk][n] = v;
        }
        __syncthreads();
#pragma unroll
        for (int kk = 0; kk < 16; kk++) {
            float a[4], b[4];
#pragma unroll
            for (int i = 0; i < 4; i++) a[i] = sA[kk][ty * 4 + i];
#pragma unroll
            for (int j = 0; j < 4; j++) b[j] = sB[kk][tx * 4 + j];
#pragma unroll
            for (int i = 0; i < 4; i++)
#pragma unroll
                for (int j = 0; j < 4; j++) acc[i][j] += a[i] * b[j];
        }
        __syncthreads();
    }
#pragma unroll
    for (int i = 0; i < 4; i++)
#pragma unroll
        for (int j = 0; j < 4; j++) {
            int m = row0 + i, n = col0 + j;
            if (m < M && n < N) atomicAdd(&C[m * N + n], acc[i][j]);
        }
}

// ---------------- 4-block LSTM with spin barrier ----------------
// Block b computes gate b (cols [b*200, b*200+200)) each step; gate vectors
// exchanged via L2 (double-buffered); h/c replicated per block.
__global__ void __launch_bounds__(512) k_lstm4(const float* __restrict__ xw,
                                               const float* __restrict__ Whh,
                                               float* __restrict__ hs, int L) {
    __shared__ float h_s[EH];
    __shared__ float c_s[EH];
    __shared__ float4 p_s[8][52];
    const int b = blockIdx.x;
    const int tid = threadIdx.x;
    const int iq = tid / 50, c4 = tid % 50;      // 8 x 50 = 400 dot threads
    if (tid < EH) { h_s[tid] = 0.0f; c_s[tid] = 0.0f; }
    __syncthreads();
    const float4* W4 = (const float4*)Whh;       // (EH, 800) -> rows of 200 float4
    unsigned* bar = &g_lbar[L];
    for (int t = 0; t < TT; t++) {
        // dot phase: partial over i in [iq*25, iq*25+25)
        if (tid < 400) {
            float4 a = make_float4(0.f, 0.f, 0.f, 0.f);
            int base = b * 50 + c4;
#pragma unroll
            for (int u = 0; u < 25; u++) {
                int i = iq * 25 + u;
                float hv = h_s[i];
                float4 w = W4[i * 200 + base];
                a.x += hv * w.x; a.y += hv * w.y; a.z += hv * w.z; a.w += hv * w.w;
            }
            p_s[iq][c4] = a;
        }
        __syncthreads();
        // reduce 8 partials, add xw, publish gate vector
        if (tid < 200) {
            const float* ps = (const float*)p_s;
            float g = xw[t * 800 + b * 200 + tid];
#pragma unroll
            for (int q = 0; q < 8; q++) g += ps[q * 208 + tid];
            __stcg(&g_gbuf[t & 1][b * 200 + tid], g);
        }
        __threadfence();
        __syncthreads();
        if (tid == 0) {
            atomicAdd(bar, 1u);
            while (atomicAdd(bar, 0u) < 4u * (unsigned)(t + 1)) {}
        }
        __syncthreads();
        __threadfence();
        // combine (replicated in every block)
        if (tid < EH) {
            const float* gb = g_gbuf[t & 1];
            float ig = sigm(__ldcg(&gb[tid]));
            float fg = sigm(__ldcg(&gb[EH + tid]));
            float gg = tanhf(__ldcg(&gb[2 * EH + tid]));
            float og = sigm(__ldcg(&gb[3 * EH + tid]));
            float c = fg * c_s[tid] + ig * gg;
            float h = og * tanhf(c);
            c_s[tid] = c;
            h_s[tid] = h;
            if (b == 0) hs[t * EH + tid] = h;
        }
        __syncthreads();
    }
}

// eta scan with k-major (transposed) weights + parallel KL
__global__ void __launch_bounds__(256) k_eta(const float* __restrict__ hs,
                                             const float* __restrict__ bmu,
                                             const float* __restrict__ bls) {
    __shared__ float cat_s[256];
    __shared__ float mu_s[KK], ls_s[KK];
    __shared__ float kl_s[64];
    int tid = threadIdx.x, warp = tid >> 5, lane = tid & 31;
    if (tid >= EH && tid < 256) cat_s[tid] = 0.0f;
    if (tid < 64) kl_s[tid] = 0.0f;
    __syncthreads();
    double kl_acc = 0.0;
    const float LOGD = -5.2983174f;
    const int CW = EH + KK;     // 250
    for (int t = 0; t < TT; t++) {
        if (tid < EH) cat_s[tid] = hs[t * EH + tid];
        __syncthreads();
        for (int job = warp; job < 2 * KK; job += 8) {
            int k = job >> 1, isls = job & 1;
            const float* W = isls ? g_WlseT : g_WmueT;
            float s = 0.0f;
            for (int i = lane; i < CW; i += 32) s += cat_s[i] * W[k * CW + i];
#pragma unroll
            for (int off = 16; off; off >>= 1) s += __shfl_down_sync(0xffffffffu, s, off);
            if (lane == 0) {
                s += isls ? bls[k] : bmu[k];
                if (isls) ls_s[k] = s; else mu_s[k] = s;
            }
        }
        __syncthreads();
        if (tid < KK) {
            float pls = (t == 0) ? 0.0f : LOGD;
            float den = expf(pls) + 1e-6f;
            float mu = mu_s[tid], ls = ls_s[tid], ep = cat_s[EH + tid];
            float dm = mu - ep;
            kl_s[tid] = (expf(ls) + dm * dm) / den - 1.0f + pls - ls;
        }
        __syncthreads();
        if (tid < 32) {
            float v = kl_s[tid] + kl_s[tid + 32];
#pragma unroll
            for (int off = 16; off; off >>= 1) v += __shfl_down_sync(0xffffffffu, v, off);
            if (tid == 0) kl_acc += (double)v;
        }
        __syncthreads();
        if (tid < KK) {
            cat_s[EH + tid] = mu_s[tid];
            g_etas[t * KK + tid] = mu_s[tid];
        }
        __syncthreads();
    }
    if (tid == 0) g_acc[2] = 0.5 * kl_acc;
}

// build cat = [bows | eta_td], also scatter eta_td
__global__ void k_cat(const float* __restrict__ bows, const int* __restrict__ times) {
    int idx = blockIdx.x * 256 + threadIdx.x;
    if (idx >= DD * (VV + KK)) return;
    int d = idx / (VV + KK);
    int i = idx - d * (VV + KK);
    float v;
    if (i < VV) v = bows[d * VV + i];
    else {
        int t = times[d];
        v = g_etas[t * KK + (i - VV)];
        g_eta_td[d * KK + (i - VV)] = v;
    }
    g_cat[idx] = v;
}

// mu_th / ls_th + softmax theta + kl_theta, one block per document (k-major W)
__global__ void __launch_bounds__(128) k_muls(const float* __restrict__ bmu,
                                              const float* __restrict__ bls) {
    int d = blockIdx.x;
    __shared__ float h_s[TH];
    __shared__ float mu_s[KK], ls_s[KK];
    int tid = threadIdx.x, warp = tid >> 5, lane = tid & 31;
    for (int i = tid; i < TH; i += 128) h_s[i] = g_h2[d * TH + i];
    __syncthreads();
    for (int job = warp; job < 2 * KK; job += 4) {
        int k = job >> 1, isls = job & 1;
        const float* W = isls ? g_WlsthT : g_WmuthT;
        float s = 0.0f;
        for (int i = lane; i < TH; i += 32) s += h_s[i] * W[k * TH + i];
#pragma unroll
        for (int off = 16; off; off >>= 1) s += __shfl_down_sync(0xffffffffu, s, off);
        if (lane == 0) {
            s += isls ? bls[k] : bmu[k];
            if (isls) ls_s[k] = s; else mu_s[k] = s;
        }
    }
    __syncthreads();
    if (tid == 0) {
        float m = -1e30f;
        for (int k = 0; k < KK; k++) m = fmaxf(m, mu_s[k]);
        float sum = 0.0f;
        for (int k = 0; k < KK; k++) sum += expf(mu_s[k] - m);
        float inv = 1.0f / sum;
        double kl = 0.0;
        for (int k = 0; k < KK; k++) {
            g_theta[d * KK + k] = expf(mu_s[k] - m) * inv;
            float mu = mu_s[k], ls = ls_s[k], eta = g_eta_td[d * KK + k];
            float dm = mu - eta;
            kl += (double)((expf(ls) + dm * dm) / (1.0f + 1e-6f) - 1.0f - ls);
        }
        atomicAdd(&g_acc[3], 0.5 * kl);
    }
}

// wa[d,k,l] = alpha[k, t_d, l] * lam[s_d, l]
__global__ void k_wa(const float* __restrict__ alpha, const float* __restrict__ lam,
                     const int* __restrict__ times, const int* __restrict__ sources) {
    int idx = blockIdx.x * 256 + threadIdx.x;
    if (idx >= DD * KK * LL) return;
    int d = idx / (KK * LL);
    int r = idx - d * (KK * LL);
    int k = r / LL;
    int l = r - k * LL;
    int t = times[d], s = sources[d];
    g_wa[idx] = alpha[(k * TT + t) * LL + l] * lam[s * LL + l];
}

// big batched GEMM: E[d,k,v] = exp(rho[v,:].wa[d,k,:]), f32x2 FMA; Z fused
#define G1_LC 30
__global__ void __launch_bounds__(128) k_g1() {
    __shared__ unsigned long long rho2_s[G1_LC * 128];
    __shared__ unsigned long long w2_s[G1_LC * KK];
    __shared__ float zred[KK * 4];
    const int d = blockIdx.y;
    const int v0 = blockIdx.x * 256;
    const int tid = threadIdx.x;
    const int warp = tid >> 5, lane = tid & 31;
    const int vlo = v0 + tid, vhi = v0 + 128 + tid;
    unsigned long long acc[KK];
#pragma unroll
    for (int k = 0; k < KK; k++) acc[k] = 0ull;
    const float* __restrict__ wa = g_wa + d * KK * LL;
    for (int chunk = 0; chunk < LL / G1_LC; chunk++) {
        const int l0 = chunk * G1_LC;
        for (int idx = tid; idx < KK * G1_LC; idx += 128) {
            int c = idx / KK, k = idx - c * KK;
            float w = wa[k * LL + l0 + c];
            w2_s[idx] = pack2(w, w);
        }
#pragma unroll
        for (int c = 0; c < G1_LC; c++) {
            const float* rT = g_rhoT + (l0 + c) * VV;
            float rlo = (vlo < VV) ? rT[vlo] : 0.0f;
            float rhi = (vhi < VV) ? rT[vhi] : 0.0f;
            rho2_s[c * 128 + tid] = pack2(rlo, rhi);
        }
        __syncthreads();
#pragma unroll 1
        for (int c = 0; c < G1_LC; c++) {
            unsigned long long r2 = rho2_s[c * 128 + tid];
            const ulonglong2* w2p = (const ulonglong2*)&w2_s[c * KK];
#pragma unroll
            for (int j = 0; j < KK / 2; j++) {
                ulonglong2 w = w2p[j];
                acc[2 * j]     = fma2(r2, w.x, acc[2 * j]);
                acc[2 * j + 1] = fma2(r2, w.y, acc[2 * j + 1]);
            }
        }
        __syncthreads();
    }
    float* E = g_E + d * KK * VV;
#pragma unroll
    for (int k = 0; k < KK; k++) {
        float lo, hi;
        unpack2(acc[k], lo, hi);
        float elo = expf(lo), ehi = expf(hi);
        float zp = 0.0f;
        if (vlo < VV) { E[k * VV + vlo] = elo; zp += elo; }
        if (vhi < VV) { E[k * VV + vhi] = ehi; zp += ehi; }
#pragma unroll
        for (int off = 16; off; off >>= 1) zp += __shfl_down_sync(0xffffffffu, zp, off);
        if (lane == 0) zred[k * 4 + warp] = zp;
    }
    __syncthreads();
    if (tid < KK) {
        float z = zred[tid * 4] + zred[tid * 4 + 1] + zred[tid * 4 + 2] + zred[tid * 4 + 3];
        atomicAdd(&g_Z[d * KK + tid], z);
    }
}

// nll: lik[d,v] = sum_k (theta/Z) * E ;  acc -= log(lik+1e-6)*bows
__global__ void k_nll(const float* __restrict__ bows) {
    int d = blockIdx.y;
    int v = blockIdx.x * 256 + threadIdx.x;
    __shared__ float wk[KK];
    if (threadIdx.x < KK)
        wk[threadIdx.x] = g_theta[d * KK + threadIdx.x] / g_Z[d * KK + threadIdx.x];
    __syncthreads();
    float term = 0.0f;
    if (v < VV) {
        const float* E = g_E + d * KK * VV + v;
        float lik = 0.0f;
#pragma unroll
        for (int k = 0; k < KK; k++) lik += wk[k] * E[k * VV];
        term = logf(lik + 1e-6f) * bows[d * VV + v];
    }
    __shared__ float sr[8];
    float s = block_reduce_256(term, sr);
    if (threadIdx.x == 0) atomicAdd(&g_acc[0], -(double)s);
}

__global__ void k_final(float* out) {
    int i = threadIdx.x;
    if (i < 4) out[i] = (float)g_acc[i];
}

// ---------------- launch ----------------
extern "C" void kernel_launch(void* const* d_in, const int* in_sizes, int n_in,
                              void* d_out, int out_size) {
    const float* bows    = (const float*)d_in[0];
    const float* rnn_inp = (const float*)d_in[1];
    const int*   times   = (const int*)d_in[2];
    const int*   sources = (const int*)d_in[3];
    const float* rho     = (const float*)d_in[4];
    const float* lam     = (const float*)d_in[5];
    const float* mu_qa   = (const float*)d_in[6];
    const float* ls_qa   = (const float*)d_in[7];
    const float* W_t1    = (const float*)d_in[8];
    const float* b_t1    = (const float*)d_in[9];
    const float* W_t2    = (const float*)d_in[10];
    const float* b_t2    = (const float*)d_in[11];
    const float* W_mu_th = (const float*)d_in[12];
    const float* b_mu_th = (const float*)d_in[13];
    const float* W_ls_th = (const float*)d_in[14];
    const float* b_ls_th = (const float*)d_in[15];
    const float* W_em    = (const float*)d_in[16];
    const float* b_em    = (const float*)d_in[17];
    const float* Wih0    = (const float*)d_in[18];
    const float* Whh0    = (const float*)d_in[19];
    const float* bl0     = (const float*)d_in[20];
    const float* Wih1    = (const float*)d_in[21];
    const float* Whh1    = (const float*)d_in[22];
    const float* bl1     = (const float*)d_in[23];
    const float* W_mu_e  = (const float*)d_in[24];
    const float* b_mu_e  = (const float*)d_in[25];
    const float* W_ls_e  = (const float*)d_in[26];
    const float* b_ls_e  = (const float*)d_in[27];

    float *p_x, *p_xw0, *p_xw1, *p_hs0, *p_hs1, *p_cat, *p_h1, *p_h2;
    float *p_rhoT, *p_WmueT, *p_WlseT, *p_WmuthT, *p_WlsthT;
    cudaGetSymbolAddress((void**)&p_x, g_x);
    cudaGetSymbolAddress((void**)&p_xw0, g_xw0);
    cudaGetSymbolAddress((void**)&p_xw1, g_xw1);
    cudaGetSymbolAddress((void**)&p_hs0, g_hs0);
    cudaGetSymbolAddress((void**)&p_hs1, g_hs1);
    cudaGetSymbolAddress((void**)&p_cat, g_cat);
    cudaGetSymbolAddress((void**)&p_h1, g_h1);
    cudaGetSymbolAddress((void**)&p_h2, g_h2);
    cudaGetSymbolAddress((void**)&p_rhoT, g_rhoT);
    cudaGetSymbolAddress((void**)&p_WmueT, g_WmueT);
    cudaGetSymbolAddress((void**)&p_WlseT, g_WlseT);
    cudaGetSymbolAddress((void**)&p_WmuthT, g_WmuthT);
    cudaGetSymbolAddress((void**)&p_WlsthT, g_WlsthT);

    dim3 t32(32, 32);

    k_zero<<<(DD * KK + 255) / 256, 256>>>();
    k_kl_alpha<<<(KK * TT * LL + 255) / 256, 256>>>(mu_qa, ls_qa);

    // transposes
    k_transpose<<<dim3((VV + 31) / 32, (LL + 31) / 32), t32>>>(rho, p_rhoT, VV, LL);
    k_transpose<<<dim3((EH + KK + 31) / 32, (KK + 31) / 32), t32>>>(W_mu_e, p_WmueT, EH + KK, KK);
    k_transpose<<<dim3((EH + KK + 31) / 32, (KK + 31) / 32), t32>>>(W_ls_e, p_WlseT, EH + KK, KK);
    k_transpose<<<dim3((TH + 31) / 32, (KK + 31) / 32), t32>>>(W_mu_th, p_WmuthT, TH, KK);
    k_transpose<<<dim3((TH + 31) / 32, (KK + 31) / 32), t32>>>(W_ls_th, p_WlsthT, TH, KK);

    k_wa<<<(DD * KK * LL + 255) / 256, 256>>>(mu_qa, lam, times, sources);

    // embedding: x = rnn_inp @ W_em + b_em   (50x200, K=3000, S=6)
    k_fill<<<(TT * EH + 255) / 256, 256>>>(p_x, b_em, TT, EH);
    k_gemm_sk<<<dim3((EH + 63) / 64, 1, 6), 256>>>(rnn_inp, W_em, p_x, TT, EH, VV, (VV + 5) / 6);

    // xw0 = x @ Wih0 + bl0   (50x800, K=200, S=2)
    k_fill<<<(TT * 4 * EH + 255) / 256, 256>>>(p_xw0, bl0, TT, 4 * EH);
    k_gemm_sk<<<dim3((4 * EH + 63) / 64, 1, 2), 256>>>(p_x, Wih0, p_xw0, TT, 4 * EH, EH, EH / 2);
    k_lstm4<<<4, 512>>>(p_xw0, Whh0, p_hs0, 0);

    k_fill<<<(TT * 4 * EH + 255) / 256, 256>>>(p_xw1, bl1, TT, 4 * EH);
    k_gemm_sk<<<dim3((4 * EH + 63) / 64, 1, 2), 256>>>(p_hs0, Wih1, p_xw1, TT, 4 * EH, EH, EH / 2);
    k_lstm4<<<4, 512>>>(p_xw1, Whh1, p_hs1, 1);

    k_eta<<<1, 256>>>(p_hs1, b_mu_e, b_ls_e);
    k_cat<<<(DD * (VV + KK) + 255) / 256, 256>>>(bows, times);

    // theta MLP (split-K + relu)
    k_fill<<<(DD * TH + 255) / 256, 256>>>(p_h1, b_t1, DD, TH);
    k_gemm_sk<<<dim3((TH + 63) / 64, (DD + 63) / 64, 6), 256>>>(p_cat, W_t1, p_h1, DD, TH, VV + KK, (VV + KK + 5) / 6);
    k_relu<<<(DD * TH + 255) / 256, 256>>>(p_h1, DD * TH);
    k_fill<<<(DD * TH + 255) / 256, 256>>>(p_h2, b_t2, DD, TH);
    k_gemm_sk<<<dim3((TH + 63) / 64, (DD + 63) / 64, 3), 256>>>(p_h1, W_t2, p_h2, DD, TH, TH, (TH + 2) / 3);
    k_relu<<<(DD * TH + 255) / 256, 256>>>(p_h2, DD * TH);
    k_muls<<<DD, 128>>>(b_mu_th, b_ls_th);

    // beta / likelihood path (Z fused into k_g1)
    k_g1<<<dim3((VV + 255) / 256, DD), 128>>>();
    k_nll<<<dim3((VV + 255) / 256, DD), 256>>>(bows);

    k_final<<<1, 4>>>((float*)d_out);
    (void)in_sizes; (void)n_in; (void)out_size;
}

// round 8
// speedup vs baseline: 2.4005x; 1.0762x over previous
#include <cuda_runtime.h>
#include <math.h>

// ---------------- problem constants ----------------
#define KK 50
#define TT 50
#define VV 3000
#define LL 300
#define TH 800
#define EH 200
#define DD 256
#define SS 8

// ---------------- device scratch (static, no allocs) ----------------
__device__ double   g_acc[4];                 // nll, kl_alpha, kl_eta, kl_theta
__device__ unsigned g_lbar[2];                // lstm spin barriers
__device__ float  g_x[TT * EH];
__device__ float  g_xw0[TT * 4 * EH];
__device__ float  g_xw1[TT * 4 * EH];
__device__ float  g_hs0[TT * EH];
__device__ float  g_hs1[TT * EH];
__device__ float  g_gbuf[2][4 * EH];
__device__ float  g_etas[TT * KK];
__device__ float  g_Amu[TT * KK];
__device__ float  g_Als[TT * KK];
__device__ float  g_eta_td[DD * KK];
__device__ float  g_cat[DD * (VV + KK)];
__device__ float  g_h1[DD * TH];
__device__ float  g_h2[DD * TH];
__device__ float  g_theta[DD * KK];
__device__ float  g_wa[DD * KK * LL];
__device__ float  g_rhoT[LL * VV];
__device__ float  g_WmueT[KK * (EH + KK)];
__device__ float  g_WlseT[KK * (EH + KK)];
__device__ float  g_WmuthT[KK * TH];
__device__ float  g_WlsthT[KK * TH];
__device__ float  g_E[DD * KK * VV];          // exp(logit), 153.6 MB
__device__ float  g_Z[DD * KK];

// ---------------- helpers ----------------
__device__ __forceinline__ unsigned long long pack2(float lo, float hi) {
    unsigned long long r;
    asm("mov.b64 %0, {%1, %2};" : "=l"(r) : "f"(lo), "f"(hi));
    return r;
}
__device__ __forceinline__ void unpack2(unsigned long long v, float& lo, float& hi) {
    asm("mov.b64 {%0, %1}, %2;" : "=f"(lo), "=f"(hi) : "l"(v));
}
__device__ __forceinline__ unsigned long long fma2(unsigned long long a,
                                                   unsigned long long b,
                                                   unsigned long long c) {
    unsigned long long d;
    asm("fma.rn.f32x2 %0, %1, %2, %3;" : "=l"(d) : "l"(a), "l"(b), "l"(c));
    return d;
}
__device__ __forceinline__ float sigm(float x) { return 1.0f / (1.0f + expf(-x)); }

__device__ __forceinline__ float block_reduce_256(float v, float* sr) {
    int tid = threadIdx.x;
#pragma unroll
    for (int off = 16; off; off >>= 1) v += __shfl_down_sync(0xffffffffu, v, off);
    if ((tid & 31) == 0) sr[tid >> 5] = v;
    __syncthreads();
    if (tid < 8) {
        v = sr[tid];
#pragma unroll
        for (int off = 4; off; off >>= 1) v += __shfl_down_sync(0xffu, v, off);
    }
    return v;
}

// ---------------- init ----------------
__global__ void k_warm() {}

__global__ void k_zero() {
    int idx = blockIdx.x * 256 + threadIdx.x;
    if (idx < DD * KK) g_Z[idx] = 0.0f;
    if (idx < 4) g_acc[idx] = 0.0;
    if (idx < 2) g_lbar[idx] = 0u;
}

// kl_alpha: elementwise over (K,T,L)
__global__ void k_kl_alpha(const float* __restrict__ mu, const float* __restrict__ ls) {
    const int N = KK * TT * LL;
    int idx = blockIdx.x * 256 + threadIdx.x;
    float c = 0.0f;
    if (idx < N) {
        int r = idx % (TT * LL);
        int t = r / LL;
        float qm = mu[idx], ql = ls[idx];
        if (t == 0) {
            c = (expf(ql) + qm * qm) / (1.0f + 1e-6f) - 1.0f - ql;
        } else {
            const float LOGD = -5.2983174f;
            float den = expf(LOGD) + 1e-6f;
            float dm = qm - mu[idx - LL];
            c = (expf(ql) + dm * dm) / den - 1.0f + LOGD - ql;
        }
    }
    __shared__ float sr[8];
    float s = block_reduce_256(c, sr);
    if (threadIdx.x == 0) atomicAdd(&g_acc[1], 0.5 * (double)s);
}

// generic transpose: B[n*M+m] = A[m*N+n]
__global__ void k_transpose(const float* __restrict__ A, float* __restrict__ B,
                            int M, int N) {
    __shared__ float tile[32][33];
    int m0 = blockIdx.x * 32, n0 = blockIdx.y * 32;
    int tx = threadIdx.x, ty = threadIdx.y;
    int m = m0 + ty, n = n0 + tx;
    if (m < M && n < N) tile[ty][tx] = A[m * N + n];
    __syncthreads();
    int nb = n0 + ty, mb = m0 + tx;
    if (nb < N && mb < M) B[nb * M + mb] = tile[tx][ty];
}

__global__ void k_fill(float* __restrict__ C, const float* __restrict__ bias,
                       int M, int N) {
    int idx = blockIdx.x * 256 + threadIdx.x;
    if (idx < M * N) C[idx] = bias[idx % N];
}

__global__ void k_relu(float* __restrict__ C, int n) {
    int idx = blockIdx.x * 256 + threadIdx.x;
    if (idx < n) C[idx] = fmaxf(C[idx], 0.0f);
}

// split-K tiled GEMM: C += A(MxK) @ B(KxN) over k-slice, atomic epilogue
__global__ void k_gemm_sk(const float* __restrict__ A, const float* __restrict__ B,
                          float* __restrict__ C, int M, int N, int Kd, int kchunk) {
    __shared__ float sA[16][65];
    __shared__ float sB[16][64];
    int tid = threadIdx.x;
    int tx = tid & 15, ty = tid >> 4;
    int row0 = blockIdx.y * 64 + ty * 4;
    int col0 = blockIdx.x * 64 + tx * 4;
    int kb = blockIdx.z * kchunk;
    int ke = min(kb + kchunk, Kd);
    float acc[4][4];
#pragma unroll
    for (int i = 0; i < 4; i++)
#pragma unroll
        for (int j = 0; j < 4; j++) acc[i][j] = 0.0f;

    for (int k0 = kb; k0 < ke; k0 += 16) {
#pragma unroll
        for (int i = 0; i < 4; i++) {
            int idx = tid + i * 256;
            int m = idx >> 4, kk = idx & 15;
            int gm = blockIdx.y * 64 + m, gk = k0 + kk;
            float v = 0.0f;
            if (gm < M && gk < ke) v = A[gm * Kd + gk];
            sA[kk][m] = v;
        }
#pragma unroll
        for (int i = 0; i < 4; i++) {
            int idx = tid + i * 256;
            int kk = idx >> 6, n = idx & 63;
            int gk = k0 + kk, gn = blockIdx.x * 64 + n;
            float v = 0.0f;
            if (gk < ke && gn < N) v = B[gk * N + gn];
            sB[kk][n] = v;
        }
        __syncthreads();
#pragma unroll
        for (int kk = 0; kk < 16; kk++) {
            float a[4], b[4];
#pragma unroll
            for (int i = 0; i < 4; i++) a[i] = sA[kk][ty * 4 + i];
#pragma unroll
            for (int j = 0; j < 4; j++) b[j] = sB[kk][tx * 4 + j];
#pragma unroll
            for (int i = 0; i < 4; i++)
#pragma unroll
                for (int j = 0; j < 4; j++) acc[i][j] += a[i] * b[j];
        }
        __syncthreads();
    }
#pragma unroll
    for (int i = 0; i < 4; i++)
#pragma unroll
        for (int j = 0; j < 4; j++) {
            int m = row0 + i, n = col0 + j;
            if (m < M && n < N) atomicAdd(&C[m * N + n], acc[i][j]);
        }
}

// ---------------- 4-block LSTM with spin barrier ----------------
__global__ void __launch_bounds__(512) k_lstm4(const float* __restrict__ xw,
                                               const float* __restrict__ Whh,
                                               float* __restrict__ hs, int L) {
    __shared__ float h_s[EH];
    __shared__ float c_s[EH];
    __shared__ float4 p_s[8][52];
    const int b = blockIdx.x;
    const int tid = threadIdx.x;
    const int iq = tid / 50, c4 = tid % 50;
    if (tid < EH) { h_s[tid] = 0.0f; c_s[tid] = 0.0f; }
    __syncthreads();
    const float4* W4 = (const float4*)Whh;
    unsigned* bar = &g_lbar[L];
    for (int t = 0; t < TT; t++) {
        if (tid < 400) {
            float4 a = make_float4(0.f, 0.f, 0.f, 0.f);
            int base = b * 50 + c4;
#pragma unroll
            for (int u = 0; u < 25; u++) {
                int i = iq * 25 + u;
                float hv = h_s[i];
                float4 w = W4[i * 200 + base];
                a.x += hv * w.x; a.y += hv * w.y; a.z += hv * w.z; a.w += hv * w.w;
            }
            p_s[iq][c4] = a;
        }
        __syncthreads();
        if (tid < 200) {
            const float* ps = (const float*)p_s;
            float g = xw[t * 800 + b * 200 + tid];
#pragma unroll
            for (int q = 0; q < 8; q++) g += ps[q * 208 + tid];
            __stcg(&g_gbuf[t & 1][b * 200 + tid], g);
        }
        __threadfence();
        __syncthreads();
        if (tid == 0) {
            atomicAdd(bar, 1u);
            while (atomicAdd(bar, 0u) < 4u * (unsigned)(t + 1)) {}
        }
        __syncthreads();
        __threadfence();
        if (tid < EH) {
            const float* gb = g_gbuf[t & 1];
            float ig = sigm(__ldcg(&gb[tid]));
            float fg = sigm(__ldcg(&gb[EH + tid]));
            float gg = tanhf(__ldcg(&gb[2 * EH + tid]));
            float og = sigm(__ldcg(&gb[3 * EH + tid]));
            float c = fg * c_s[tid] + ig * gg;
            float h = og * tanhf(c);
            c_s[tid] = c;
            h_s[tid] = h;
            if (b == 0) hs[t * EH + tid] = h;
        }
        __syncthreads();
    }
}

// eta scan v2: only eta_prev @ W2 (50x50) stays sequential; out@W1 precomputed.
__global__ void __launch_bounds__(128) k_eta2(const float* __restrict__ Amu,
                                              const float* __restrict__ Als) {
    __shared__ float eta_s[KK];
    __shared__ float mu_s[KK], ls_s[KK];
    __shared__ float kl_sh[2];
    int tid = threadIdx.x;
    int warp = tid >> 5;
    if (tid < KK) eta_s[tid] = 0.0f;
    __syncthreads();
    double kl_acc = 0.0;
    const float LOGD = -5.2983174f;
    for (int t = 0; t < TT; t++) {
        if (tid < KK) {
            float s = Amu[t * KK + tid];
            const float* W = &g_WmueT[tid * (EH + KK) + EH];
#pragma unroll
            for (int j = 0; j < KK; j++) s += eta_s[j] * W[j];
            mu_s[tid] = s;
        } else if (tid >= 64 && tid < 64 + KK) {
            int k = tid - 64;
            float s = Als[t * KK + k];
            const float* W = &g_WlseT[k * (EH + KK) + EH];
#pragma unroll
            for (int j = 0; j < KK; j++) s += eta_s[j] * W[j];
            ls_s[k] = s;
        }
        __syncthreads();
        if (tid < 64) {
            float term = 0.0f;
            if (tid < KK) {
                float pls = (t == 0) ? 0.0f : LOGD;
                float den = expf(pls) + 1e-6f;
                float dm = mu_s[tid] - eta_s[tid];
                term = (expf(ls_s[tid]) + dm * dm) / den - 1.0f + pls - ls_s[tid];
            }
#pragma unroll
            for (int off = 16; off; off >>= 1) term += __shfl_down_sync(0xffffffffu, term, off);
            if ((tid & 31) == 0) kl_sh[warp] = term;
        }
        __syncthreads();
        if (tid == 0) kl_acc += (double)(kl_sh[0] + kl_sh[1]);
        if (tid < KK) {
            eta_s[tid] = mu_s[tid];
            g_etas[t * KK + tid] = mu_s[tid];
        }
        __syncthreads();
    }
    if (tid == 0) g_acc[2] = 0.5 * kl_acc;
}

// build cat = [bows | eta_td], also scatter eta_td
__global__ void k_cat(const float* __restrict__ bows, const int* __restrict__ times) {
    int idx = blockIdx.x * 256 + threadIdx.x;
    if (idx >= DD * (VV + KK)) return;
    int d = idx / (VV + KK);
    int i = idx - d * (VV + KK);
    float v;
    if (i < VV) v = bows[d * VV + i];
    else {
        int t = times[d];
        v = g_etas[t * KK + (i - VV)];
        g_eta_td[d * KK + (i - VV)] = v;
    }
    g_cat[idx] = v;
}

// mu_th / ls_th + softmax theta + kl_theta, one block per document (k-major W)
__global__ void __launch_bounds__(128) k_muls(const float* __restrict__ bmu,
                                              const float* __restrict__ bls) {
    int d = blockIdx.x;
    __shared__ float h_s[TH];
    __shared__ float mu_s[KK], ls_s[KK];
    int tid = threadIdx.x, warp = tid >> 5, lane = tid & 31;
    for (int i = tid; i < TH; i += 128) h_s[i] = g_h2[d * TH + i];
    __syncthreads();
    for (int job = warp; job < 2 * KK; job += 4) {
        int k = job >> 1, isls = job & 1;
        const float* W = isls ? g_WlsthT : g_WmuthT;
        float s = 0.0f;
        for (int i = lane; i < TH; i += 32) s += h_s[i] * W[k * TH + i];
#pragma unroll
        for (int off = 16; off; off >>= 1) s += __shfl_down_sync(0xffffffffu, s, off);
        if (lane == 0) {
            s += isls ? bls[k] : bmu[k];
            if (isls) ls_s[k] = s; else mu_s[k] = s;
        }
    }
    __syncthreads();
    if (tid == 0) {
        float m = -1e30f;
        for (int k = 0; k < KK; k++) m = fmaxf(m, mu_s[k]);
        float sum = 0.0f;
        for (int k = 0; k < KK; k++) sum += expf(mu_s[k] - m);
        float inv = 1.0f / sum;
        double kl = 0.0;
        for (int k = 0; k < KK; k++) {
            g_theta[d * KK + k] = expf(mu_s[k] - m) * inv;
            float mu = mu_s[k], ls = ls_s[k], eta = g_eta_td[d * KK + k];
            float dm = mu - eta;
            kl += (double)((expf(ls) + dm * dm) / (1.0f + 1e-6f) - 1.0f - ls);
        }
        atomicAdd(&g_acc[3], 0.5 * kl);
    }
}

// wa[d,k,l] = alpha[k, t_d, l] * lam[s_d, l]
__global__ void k_wa(const float* __restrict__ alpha, const float* __restrict__ lam,
                     const int* __restrict__ times, const int* __restrict__ sources) {
    int idx = blockIdx.x * 256 + threadIdx.x;
    if (idx >= DD * KK * LL) return;
    int d = idx / (KK * LL);
    int r = idx - d * (KK * LL);
    int k = r / LL;
    int l = r - k * LL;
    int t = times[d], s = sources[d];
    g_wa[idx] = alpha[(k * TT + t) * LL + l] * lam[s * LL + l];
}

// big batched GEMM: E[d,k,v] = exp(rho[v,:].wa[d,k,:]), f32x2 FMA; Z fused
#define G1_LC 30
__global__ void __launch_bounds__(128) k_g1() {
    __shared__ unsigned long long rho2_s[G1_LC * 128];
    __shared__ unsigned long long w2_s[G1_LC * KK];
    __shared__ float zred[KK * 4];
    const int d = blockIdx.y;
    const int v0 = blockIdx.x * 256;
    const int tid = threadIdx.x;
    const int warp = tid >> 5, lane = tid & 31;
    const int vlo = v0 + tid, vhi = v0 + 128 + tid;
    unsigned long long acc[KK];
#pragma unroll
    for (int k = 0; k < KK; k++) acc[k] = 0ull;
    const float* __restrict__ wa = g_wa + d * KK * LL;
    for (int chunk = 0; chunk < LL / G1_LC; chunk++) {
        const int l0 = chunk * G1_LC;
        for (int idx = tid; idx < KK * G1_LC; idx += 128) {
            int c = idx / KK, k = idx - c * KK;
            float w = wa[k * LL + l0 + c];
            w2_s[idx] = pack2(w, w);
        }
#pragma unroll
        for (int c = 0; c < G1_LC; c++) {
            const float* rT = g_rhoT + (l0 + c) * VV;
            float rlo = (vlo < VV) ? rT[vlo] : 0.0f;
            float rhi = (vhi < VV) ? rT[vhi] : 0.0f;
            rho2_s[c * 128 + tid] = pack2(rlo, rhi);
        }
        __syncthreads();
#pragma unroll 1
        for (int c = 0; c < G1_LC; c++) {
            unsigned long long r2 = rho2_s[c * 128 + tid];
            const ulonglong2* w2p = (const ulonglong2*)&w2_s[c * KK];
#pragma unroll
            for (int j = 0; j < KK / 2; j++) {
                ulonglong2 w = w2p[j];
                acc[2 * j]     = fma2(r2, w.x, acc[2 * j]);
                acc[2 * j + 1] = fma2(r2, w.y, acc[2 * j + 1]);
            }
        }
        __syncthreads();
    }
    float* E = g_E + d * KK * VV;
#pragma unroll
    for (int k = 0; k < KK; k++) {
        float lo, hi;
        unpack2(acc[k], lo, hi);
        float elo = __expf(lo), ehi = __expf(hi);
        float zp = 0.0f;
        if (vlo < VV) { E[k * VV + vlo] = elo; zp += elo; }
        if (vhi < VV) { E[k * VV + vhi] = ehi; zp += ehi; }
#pragma unroll
        for (int off = 16; off; off >>= 1) zp += __shfl_down_sync(0xffffffffu, zp, off);
        if (lane == 0) zred[k * 4 + warp] = zp;
    }
    __syncthreads();
    if (tid < KK) {
        float z = zred[tid * 4] + zred[tid * 4 + 1] + zred[tid * 4 + 2] + zred[tid * 4 + 3];
        atomicAdd(&g_Z[d * KK + tid], z);
    }
}

// nll: lik[d,v] = sum_k (theta/Z) * E ;  acc -= log(lik+1e-6)*bows
__global__ void k_nll(const float* __restrict__ bows) {
    int d = blockIdx.y;
    int v = blockIdx.x * 256 + threadIdx.x;
    __shared__ float wk[KK];
    if (threadIdx.x < KK)
        wk[threadIdx.x] = g_theta[d * KK + threadIdx.x] / g_Z[d * KK + threadIdx.x];
    __syncthreads();
    float term = 0.0f;
    if (v < VV) {
        const float* E = g_E + d * KK * VV + v;
        float lik = 0.0f;
#pragma unroll
        for (int k = 0; k < KK; k++) lik += wk[k] * E[k * VV];
        term = __logf(lik + 1e-6f) * bows[d * VV + v];
    }
    __shared__ float sr[8];
    float s = block_reduce_256(term, sr);
    if (threadIdx.x == 0) atomicAdd(&g_acc[0], -(double)s);
}

__global__ void k_final(float* out) {
    int i = threadIdx.x;
    if (i < 4) out[i] = (float)g_acc[i];
}

// ---------------- stream setup (static init: outside measured window) ----------
struct StreamRes {
    cudaStream_t sB;
    cudaEvent_t evFork, evJoin;
    bool ok;
    StreamRes() {
        ok = true;
        if (cudaStreamCreateWithFlags(&sB, cudaStreamNonBlocking) != cudaSuccess) ok = false;
        if (ok && cudaEventCreateWithFlags(&evFork, cudaEventDisableTiming) != cudaSuccess) ok = false;
        if (ok && cudaEventCreateWithFlags(&evJoin, cudaEventDisableTiming) != cudaSuccess) ok = false;
        if (ok) {
            k_warm<<<1, 1, 0, sB>>>();       // force lazy resource materialization now
            if (cudaStreamSynchronize(sB) != cudaSuccess) ok = false;
        }
    }
};
static StreamRes g_sr;

// ---------------- launch ----------------
extern "C" void kernel_launch(void* const* d_in, const int* in_sizes, int n_in,
                              void* d_out, int out_size) {
    const float* bows    = (const float*)d_in[0];
    const float* rnn_inp = (const float*)d_in[1];
    const int*   times   = (const int*)d_in[2];
    const int*   sources = (const int*)d_in[3];
    const float* rho     = (const float*)d_in[4];
    const float* lam     = (const float*)d_in[5];
    const float* mu_qa   = (const float*)d_in[6];
    const float* ls_qa   = (const float*)d_in[7];
    const float* W_t1    = (const float*)d_in[8];
    const float* b_t1    = (const float*)d_in[9];
    const float* W_t2    = (const float*)d_in[10];
    const float* b_t2    = (const float*)d_in[11];
    const float* W_mu_th = (const float*)d_in[12];
    const float* b_mu_th = (const float*)d_in[13];
    const float* W_ls_th = (const float*)d_in[14];
    const float* b_ls_th = (const float*)d_in[15];
    const float* W_em    = (const float*)d_in[16];
    const float* b_em    = (const float*)d_in[17];
    const float* Wih0    = (const float*)d_in[18];
    const float* Whh0    = (const float*)d_in[19];
    const float* bl0     = (const float*)d_in[20];
    const float* Wih1    = (const float*)d_in[21];
    const float* Whh1    = (const float*)d_in[22];
    const float* bl1     = (const float*)d_in[23];
    const float* W_mu_e  = (const float*)d_in[24];
    const float* b_mu_e  = (const float*)d_in[25];
    const float* W_ls_e  = (const float*)d_in[26];
    const float* b_ls_e  = (const float*)d_in[27];

    float *p_x, *p_xw0, *p_xw1, *p_hs0, *p_hs1, *p_cat, *p_h1, *p_h2;
    float *p_rhoT, *p_WmueT, *p_WlseT, *p_WmuthT, *p_WlsthT, *p_Amu, *p_Als;
    cudaGetSymbolAddress((void**)&p_x, g_x);
    cudaGetSymbolAddress((void**)&p_xw0, g_xw0);
    cudaGetSymbolAddress((void**)&p_xw1, g_xw1);
    cudaGetSymbolAddress((void**)&p_hs0, g_hs0);
    cudaGetSymbolAddress((void**)&p_hs1, g_hs1);
    cudaGetSymbolAddress((void**)&p_cat, g_cat);
    cudaGetSymbolAddress((void**)&p_h1, g_h1);
    cudaGetSymbolAddress((void**)&p_h2, g_h2);
    cudaGetSymbolAddress((void**)&p_rhoT, g_rhoT);
    cudaGetSymbolAddress((void**)&p_WmueT, g_WmueT);
    cudaGetSymbolAddress((void**)&p_WlseT, g_WlseT);
    cudaGetSymbolAddress((void**)&p_WmuthT, g_WmuthT);
    cudaGetSymbolAddress((void**)&p_WlsthT, g_WlsthT);
    cudaGetSymbolAddress((void**)&p_Amu, g_Amu);
    cudaGetSymbolAddress((void**)&p_Als, g_Als);

    dim3 t32(32, 32);
    cudaStream_t sA = 0;
    cudaStream_t sB = g_sr.ok ? g_sr.sB : (cudaStream_t)0;

    // ---- common prologue on stream 0 ----
    k_zero<<<(DD * KK + 255) / 256, 256, 0, sA>>>();

    if (g_sr.ok) {
        cudaEventRecord(g_sr.evFork, sA);
        cudaStreamWaitEvent(sB, g_sr.evFork, 0);
    }

    // ---- chain B (independent, heavy): kl_alpha + rhoT + wa + g1 ----
    k_kl_alpha<<<(KK * TT * LL + 255) / 256, 256, 0, sB>>>(mu_qa, ls_qa);
    k_transpose<<<dim3((VV + 31) / 32, (LL + 31) / 32), t32, 0, sB>>>(rho, p_rhoT, VV, LL);
    k_wa<<<(DD * KK * LL + 255) / 256, 256, 0, sB>>>(mu_qa, lam, times, sources);
    k_g1<<<dim3((VV + 255) / 256, DD), 128, 0, sB>>>();
    if (g_sr.ok) cudaEventRecord(g_sr.evJoin, sB);

    // ---- chain A (sequential, latency-bound) on stream 0 ----
    k_transpose<<<dim3((EH + KK + 31) / 32, (KK + 31) / 32), t32, 0, sA>>>(W_mu_e, p_WmueT, EH + KK, KK);
    k_transpose<<<dim3((EH + KK + 31) / 32, (KK + 31) / 32), t32, 0, sA>>>(W_ls_e, p_WlseT, EH + KK, KK);
    k_transpose<<<dim3((TH + 31) / 32, (KK + 31) / 32), t32, 0, sA>>>(W_mu_th, p_WmuthT, TH, KK);
    k_transpose<<<dim3((TH + 31) / 32, (KK + 31) / 32), t32, 0, sA>>>(W_ls_th, p_WlsthT, TH, KK);

    // embedding: x = rnn_inp @ W_em + b_em
    k_fill<<<(TT * EH + 255) / 256, 256, 0, sA>>>(p_x, b_em, TT, EH);
    k_gemm_sk<<<dim3((EH + 63) / 64, 1, 6), 256, 0, sA>>>(rnn_inp, W_em, p_x, TT, EH, VV, (VV + 5) / 6);

    k_fill<<<(TT * 4 * EH + 255) / 256, 256, 0, sA>>>(p_xw0, bl0, TT, 4 * EH);
    k_gemm_sk<<<dim3((4 * EH + 63) / 64, 1, 2), 256, 0, sA>>>(p_x, Wih0, p_xw0, TT, 4 * EH, EH, EH / 2);
    k_lstm4<<<4, 512, 0, sA>>>(p_xw0, Whh0, p_hs0, 0);

    k_fill<<<(TT * 4 * EH + 255) / 256, 256, 0, sA>>>(p_xw1, bl1, TT, 4 * EH);
    k_gemm_sk<<<dim3((4 * EH + 63) / 64, 1, 2), 256, 0, sA>>>(p_hs0, Wih1, p_xw1, TT, 4 * EH, EH, EH / 2);
    k_lstm4<<<4, 512, 0, sA>>>(p_xw1, Whh1, p_hs1, 1);

    // eta precompute: Amu = hs1 @ W_mu_e[0:200,:] + b_mu_e ; Als likewise
    k_fill<<<(TT * KK + 255) / 256, 256, 0, sA>>>(p_Amu, b_mu_e, TT, KK);
    k_gemm_sk<<<dim3(1, 1, 2), 256, 0, sA>>>(p_hs1, W_mu_e, p_Amu, TT, KK, EH, EH / 2);
    k_fill<<<(TT * KK + 255) / 256, 256, 0, sA>>>(p_Als, b_ls_e, TT, KK);
    k_gemm_sk<<<dim3(1, 1, 2), 256, 0, sA>>>(p_hs1, W_ls_e, p_Als, TT, KK, EH, EH / 2);
    k_eta2<<<1, 128, 0, sA>>>(p_Amu, p_Als);

    k_cat<<<(DD * (VV + KK) + 255) / 256, 256, 0, sA>>>(bows, times);

    // theta MLP
    k_fill<<<(DD * TH + 255) / 256, 256, 0, sA>>>(p_h1, b_t1, DD, TH);
    k_gemm_sk<<<dim3((TH + 63) / 64, (DD + 63) / 64, 6), 256, 0, sA>>>(p_cat, W_t1, p_h1, DD, TH, VV + KK, (VV + KK + 5) / 6);
    k_relu<<<(DD * TH + 255) / 256, 256, 0, sA>>>(p_h1, DD * TH);
    k_fill<<<(DD * TH + 255) / 256, 256, 0, sA>>>(p_h2, b_t2, DD, TH);
    k_gemm_sk<<<dim3((TH + 63) / 64, (DD + 63) / 64, 3), 256, 0, sA>>>(p_h1, W_t2, p_h2, DD, TH, TH, (TH + 2) / 3);
    k_relu<<<(DD * TH + 255) / 256, 256, 0, sA>>>(p_h2, DD * TH);
    k_muls<<<DD, 128, 0, sA>>>(b_mu_th, b_ls_th);

    // ---- join, then nll + output ----
    if (g_sr.ok) cudaStreamWaitEvent(sA, g_sr.evJoin, 0);
    k_nll<<<dim3((VV + 255) / 256, DD), 256, 0, sA>>>(bows);
    k_final<<<1, 4, 0, sA>>>((float*)d_out);
    (void)in_sizes; (void)n_in; (void)out_size;
}

// round 10
// speedup vs baseline: 2.7389x; 1.1409x over previous
#include <cuda_runtime.h>
#include <math.h>

// ---------------- problem constants ----------------
#define KK 50
#define TT 50
#define VV 3000
#define LL 300
#define TH 800
#define EH 200
#define DD 256
#define SS 8

// ---------------- device scratch (static, no allocs) ----------------
__device__ double   g_acc[4];                 // nll, kl_alpha, kl_eta, kl_theta
__device__ unsigned g_lbar[2];                // legacy lstm spin barriers (fallback)
__device__ unsigned g_lrdy[2][4];             // per-layer per-block ready counters
__device__ float  g_x[TT * EH];
__device__ float  g_xw0[TT * 4 * EH];
__device__ float  g_xw1[TT * 4 * EH];
__device__ float  g_hs0[TT * EH];
__device__ float  g_hs1[TT * EH];
__device__ float  g_gbuf[2][4 * EH];          // fallback gate exchange
__device__ float  g_etas[TT * KK];
__device__ float  g_Amu[TT * KK];
__device__ float  g_Als[TT * KK];
__device__ float  g_eta_td[DD * KK];
__device__ float  g_h1[DD * TH];
__device__ float  g_h2[DD * TH];
__device__ float  g_theta[DD * KK];
__device__ float  g_wa[DD * KK * LL];
__device__ float  g_rhoT[LL * VV];
__device__ float  g_WmueT[KK * (EH + KK)];
__device__ float  g_WlseT[KK * (EH + KK)];
__device__ float  g_WmuthT[KK * TH];
__device__ float  g_WlsthT[KK * TH];
__device__ float  g_E[DD * KK * VV];          // exp(logit), 153.6 MB
__device__ float  g_Z[DD * KK];

// ---------------- helpers ----------------
__device__ __forceinline__ unsigned long long pack2(float lo, float hi) {
    unsigned long long r;
    asm("mov.b64 %0, {%1, %2};" : "=l"(r) : "f"(lo), "f"(hi));
    return r;
}
__device__ __forceinline__ void unpack2(unsigned long long v, float& lo, float& hi) {
    asm("mov.b64 {%0, %1}, %2;" : "=f"(lo), "=f"(hi) : "l"(v));
}
__device__ __forceinline__ unsigned long long fma2(unsigned long long a,
                                                   unsigned long long b,
                                                   unsigned long long c) {
    unsigned long long d;
    asm("fma.rn.f32x2 %0, %1, %2, %3;" : "=l"(d) : "l"(a), "l"(b), "l"(c));
    return d;
}
__device__ __forceinline__ float sigm(float x) { return 1.0f / (1.0f + expf(-x)); }

__device__ __forceinline__ float block_reduce_256(float v, float* sr) {
    int tid = threadIdx.x;
#pragma unroll
    for (int off = 16; off; off >>= 1) v += __shfl_down_sync(0xffffffffu, v, off);
    if ((tid & 31) == 0) sr[tid >> 5] = v;
    __syncthreads();
    if (tid < 8) {
        v = sr[tid];
#pragma unroll
        for (int off = 4; off; off >>= 1) v += __shfl_down_sync(0xffu, v, off);
    }
    return v;
}

// ---------------- init ----------------
__global__ void k_warm() {}

__global__ void k_zero() {
    int idx = blockIdx.x * 256 + threadIdx.x;
    if (idx < DD * KK) g_Z[idx] = 0.0f;
    if (idx < 4) g_acc[idx] = 0.0;
    if (idx < 2) g_lbar[idx] = 0u;
    if (idx < 8) ((unsigned*)g_lrdy)[idx] = 0u;
}

// kl_alpha: elementwise over (K,T,L)
__global__ void k_kl_alpha(const float* __restrict__ mu, const float* __restrict__ ls) {
    const int N = KK * TT * LL;
    int idx = blockIdx.x * 256 + threadIdx.x;
    float c = 0.0f;
    if (idx < N) {
        int r = idx % (TT * LL);
        int t = r / LL;
        float qm = mu[idx], ql = ls[idx];
        if (t == 0) {
            c = (expf(ql) + qm * qm) / (1.0f + 1e-6f) - 1.0f - ql;
        } else {
            const float LOGD = -5.2983174f;
            float den = expf(LOGD) + 1e-6f;
            float dm = qm - mu[idx - LL];
            c = (expf(ql) + dm * dm) / den - 1.0f + LOGD - ql;
        }
    }
    __shared__ float sr[8];
    float s = block_reduce_256(c, sr);
    if (threadIdx.x == 0) atomicAdd(&g_acc[1], 0.5 * (double)s);
}

// generic transpose: B[n*M+m] = A[m*N+n]
__global__ void k_transpose(const float* __restrict__ A, float* __restrict__ B,
                            int M, int N) {
    __shared__ float tile[32][33];
    int m0 = blockIdx.x * 32, n0 = blockIdx.y * 32;
    int tx = threadIdx.x, ty = threadIdx.y;
    int m = m0 + ty, n = n0 + tx;
    if (m < M && n < N) tile[ty][tx] = A[m * N + n];
    __syncthreads();
    int nb = n0 + ty, mb = m0 + tx;
    if (nb < N && mb < M) B[nb * M + mb] = tile[tx][ty];
}

__global__ void k_fill(float* __restrict__ C, const float* __restrict__ bias,
                       int M, int N) {
    int idx = blockIdx.x * 256 + threadIdx.x;
    if (idx < M * N) C[idx] = bias[idx % N];
}

__global__ void k_relu(float* __restrict__ C, int n) {
    int idx = blockIdx.x * 256 + threadIdx.x;
    if (idx < n) C[idx] = fmaxf(C[idx], 0.0f);
}

// split-K tiled GEMM: C += A(MxK) @ B(KxN) over k-slice, atomic epilogue
__global__ void k_gemm_sk(const float* __restrict__ A, const float* __restrict__ B,
                          float* __restrict__ C, int M, int N, int Kd, int kchunk) {
    __shared__ float sA[16][65];
    __shared__ float sB[16][64];
    int tid = threadIdx.x;
    int tx = tid & 15, ty = tid >> 4;
    int row0 = blockIdx.y * 64 + ty * 4;
    int col0 = blockIdx.x * 64 + tx * 4;
    int kb = blockIdx.z * kchunk;
    int ke = min(kb + kchunk, Kd);
    float acc[4][4];
#pragma unroll
    for (int i = 0; i < 4; i++)
#pragma unroll
        for (int j = 0; j < 4; j++) acc[i][j] = 0.0f;

    for (int k0 = kb; k0 < ke; k0 += 16) {
#pragma unroll
        for (int i = 0; i < 4; i++) {
            int idx = tid + i * 256;
            int m = idx >> 4, kk = idx & 15;
            int gm = blockIdx.y * 64 + m, gk = k0 + kk;
            float v = 0.0f;
            if (gm < M && gk < ke) v = A[gm * Kd + gk];
            sA[kk][m] = v;
        }
#pragma unroll
        for (int i = 0; i < 4; i++) {
            int idx = tid + i * 256;
            int kk = idx >> 6, n = idx & 63;
            int gk = k0 + kk, gn = blockIdx.x * 64 + n;
            float v = 0.0f;
            if (gk < ke && gn < N) v = B[gk * N + gn];
            sB[kk][n] = v;
        }
        __syncthreads();
#pragma unroll
        for (int kk = 0; kk < 16; kk++) {
            float a[4], b[4];
#pragma unroll
            for (int i = 0; i < 4; i++) a[i] = sA[kk][ty * 4 + i];
#pragma unroll
            for (int j = 0; j < 4; j++) b[j] = sB[kk][tx * 4 + j];
#pragma unroll
            for (int i = 0; i < 4; i++)
#pragma unroll
                for (int j = 0; j < 4; j++) acc[i][j] += a[i] * b[j];
        }
        __syncthreads();
    }
#pragma unroll
    for (int i = 0; i < 4; i++)
#pragma unroll
        for (int j = 0; j < 4; j++) {
            int m = row0 + i, n = col0 + j;
            if (m < M && n < N) atomicAdd(&C[m * N + n], acc[i][j]);
        }
}

// ---------------- LSTM v3: element-partitioned, weights in SMEM ----------------
// 4 blocks x 416 threads. Block b owns h elements [b*50, b*50+50) and computes
// all 4 gates for them. Whh slice (200 outputs x 200 inputs = 160KB) staged in
// dynamic smem once. Per step: smem dot + tiny h exchange via L2 + light
// release/acquire counter barrier.
__global__ void __launch_bounds__(416) k_lstm_smem(const float* __restrict__ xw,
                                                   const float* __restrict__ Whh,
                                                   float* __restrict__ hs, int L) {
    extern __shared__ float s_w[];                 // [200][200], row-major by output
    __shared__ __align__(16) float h_s[EH];
    __shared__ float c_s[50];
    __shared__ float g_loc[200];
    const int b = blockIdx.x;
    const int tid = threadIdx.x;

    // stage weight slice: (i, o) order for coalesced global reads
    for (int idx = tid; idx < 200 * 200; idx += 416) {
        int i = idx / 200, o = idx - (idx / 200) * 200;
        int gi = o / 50, e = o - gi * 50;
        int col = gi * 200 + b * 50 + e;
        s_w[o * 200 + i] = Whh[i * 800 + col];
    }
    if (tid < EH) h_s[tid] = 0.0f;
    if (tid < 50) c_s[tid] = 0.0f;
    __syncthreads();

    const int o = ((tid >> 1) % 200);
    const int half = tid & 1;
    const int gi = o / 50, e = o - gi * 50;
    const int col = gi * 200 + b * 50 + e;
    unsigned* rdy = g_lrdy[L];

    for (int t = 0; t < TT; t++) {
        // dot: 100 inputs per thread, LDS.128
        const float4* wv = (const float4*)(s_w + o * 200 + half * 100);
        const float4* hv = ((const float4*)h_s) + half * 25;
        float4 a = make_float4(0.f, 0.f, 0.f, 0.f);
#pragma unroll
        for (int j = 0; j < 25; j++) {
            float4 w = wv[j], h4 = hv[j];
            a.x = fmaf(w.x, h4.x, a.x);
            a.y = fmaf(w.y, h4.y, a.y);
            a.z = fmaf(w.z, h4.z, a.z);
            a.w = fmaf(w.w, h4.w, a.w);
        }
        float s = (a.x + a.y) + (a.z + a.w);
        s += __shfl_down_sync(0xffffffffu, s, 1);
        if (half == 0 && tid < 400) g_loc[o] = s + xw[t * 800 + col];
        __syncthreads();
        // gate combine + own h/c update + publish
        if (tid < 50) {
            float ig = sigm(g_loc[tid]);
            float fg = sigm(g_loc[50 + tid]);
            float gg = tanhf(g_loc[100 + tid]);
            float og = sigm(g_loc[150 + tid]);
            float c = fg * c_s[tid] + ig * gg;
            float h = og * tanhf(c);
            c_s[tid] = c;
            __stcg(&hs[t * EH + b * 50 + tid], h);
        }
        __threadfence();
        __syncthreads();
        if (tid == 0) {
            atomicExch(&rdy[b], (unsigned)(t + 1));
        } else if (tid <= 3) {
            int p = (b + tid) & 3;
            while (atomicAdd(&rdy[p], 0u) < (unsigned)(t + 1)) __nanosleep(20);
        }
        __syncthreads();
        __threadfence();
        if (tid < EH) h_s[tid] = __ldcg(&hs[t * EH + tid]);
        __syncthreads();
    }
}

// ---------------- LSTM fallback (round-8 version) ----------------
__global__ void __launch_bounds__(512) k_lstm4(const float* __restrict__ xw,
                                               const float* __restrict__ Whh,
                                               float* __restrict__ hs, int L) {
    __shared__ float h_s[EH];
    __shared__ float c_s[EH];
    __shared__ float4 p_s[8][52];
    const int b = blockIdx.x;
    const int tid = threadIdx.x;
    const int iq = tid / 50, c4 = tid % 50;
    if (tid < EH) { h_s[tid] = 0.0f; c_s[tid] = 0.0f; }
    __syncthreads();
    const float4* W4 = (const float4*)Whh;
    unsigned* bar = &g_lbar[L];
    for (int t = 0; t < TT; t++) {
        if (tid < 400) {
            float4 a = make_float4(0.f, 0.f, 0.f, 0.f);
            int base = b * 50 + c4;
#pragma unroll
            for (int u = 0; u < 25; u++) {
                int i = iq * 25 + u;
                float hv = h_s[i];
                float4 w = W4[i * 200 + base];
                a.x += hv * w.x; a.y += hv * w.y; a.z += hv * w.z; a.w += hv * w.w;
            }
            p_s[iq][c4] = a;
        }
        __syncthreads();
        if (tid < 200) {
            const float* ps = (const float*)p_s;
            float g = xw[t * 800 + b * 200 + tid];
#pragma unroll
            for (int q = 0; q < 8; q++) g += ps[q * 208 + tid];
            __stcg(&g_gbuf[t & 1][b * 200 + tid], g);
        }
        __threadfence();
        __syncthreads();
        if (tid == 0) {
            atomicAdd(bar, 1u);
            while (atomicAdd(bar, 0u) < 4u * (unsigned)(t + 1)) {}
        }
        __syncthreads();
        __threadfence();
        if (tid < EH) {
            const float* gb = g_gbuf[t & 1];
            float ig = sigm(__ldcg(&gb[tid]));
            float fg = sigm(__ldcg(&gb[EH + tid]));
            float gg = tanhf(__ldcg(&gb[2 * EH + tid]));
            float og = sigm(__ldcg(&gb[3 * EH + tid]));
            float c = fg * c_s[tid] + ig * gg;
            float h = og * tanhf(c);
            c_s[tid] = c;
            h_s[tid] = h;
            if (b == 0) hs[t * EH + tid] = h;
        }
        __syncthreads();
    }
}

// eta scan v2: only eta_prev @ W2 (50x50) stays sequential; out@W1 precomputed.
__global__ void __launch_bounds__(128) k_eta2(const float* __restrict__ Amu,
                                              const float* __restrict__ Als) {
    __shared__ float eta_s[KK];
    __shared__ float mu_s[KK], ls_s[KK];
    __shared__ float kl_sh[2];
    int tid = threadIdx.x;
    int warp = tid >> 5;
    if (tid < KK) eta_s[tid] = 0.0f;
    __syncthreads();
    double kl_acc = 0.0;
    const float LOGD = -5.2983174f;
    for (int t = 0; t < TT; t++) {
        if (tid < KK) {
            float s = Amu[t * KK + tid];
            const float* W = &g_WmueT[tid * (EH + KK) + EH];
#pragma unroll
            for (int j = 0; j < KK; j++) s += eta_s[j] * W[j];
            mu_s[tid] = s;
        } else if (tid >= 64 && tid < 64 + KK) {
            int k = tid - 64;
            float s = Als[t * KK + k];
            const float* W = &g_WlseT[k * (EH + KK) + EH];
#pragma unroll
            for (int j = 0; j < KK; j++) s += eta_s[j] * W[j];
            ls_s[k] = s;
        }
        __syncthreads();
        if (tid < 64) {
            float term = 0.0f;
            if (tid < KK) {
                float pls = (t == 0) ? 0.0f : LOGD;
                float den = expf(pls) + 1e-6f;
                float dm = mu_s[tid] - eta_s[tid];
                term = (expf(ls_s[tid]) + dm * dm) / den - 1.0f + pls - ls_s[tid];
            }
#pragma unroll
            for (int off = 16; off; off >>= 1) term += __shfl_down_sync(0xffffffffu, term, off);
            if ((tid & 31) == 0) kl_sh[warp] = term;
        }
        __syncthreads();
        if (tid == 0) kl_acc += (double)(kl_sh[0] + kl_sh[1]);
        if (tid < KK) {
            eta_s[tid] = mu_s[tid];
            g_etas[t * KK + tid] = mu_s[tid];
        }
        __syncthreads();
    }
    if (tid == 0) g_acc[2] = 0.5 * kl_acc;
}

// eta_td scatter: eta_td[d,k] = etas[times[d], k]
__global__ void k_etatd(const int* __restrict__ times) {
    int idx = blockIdx.x * 256 + threadIdx.x;
    if (idx >= DD * KK) return;
    int d = idx / KK, k = idx - d * KK;
    g_eta_td[idx] = g_etas[times[d] * KK + k];
}

// mu_th / ls_th + softmax theta + kl_theta, one block per document (k-major W)
__global__ void __launch_bounds__(128) k_muls(const float* __restrict__ bmu,
                                              const float* __restrict__ bls) {
    int d = blockIdx.x;
    __shared__ float h_s[TH];
    __shared__ float mu_s[KK], ls_s[KK];
    int tid = threadIdx.x, warp = tid >> 5, lane = tid & 31;
    for (int i = tid; i < TH; i += 128) h_s[i] = g_h2[d * TH + i];
    __syncthreads();
    for (int job = warp; job < 2 * KK; job += 4) {
        int k = job >> 1, isls = job & 1;
        const float* W = isls ? g_WlsthT : g_WmuthT;
        float s = 0.0f;
        for (int i = lane; i < TH; i += 32) s += h_s[i] * W[k * TH + i];
#pragma unroll
        for (int off = 16; off; off >>= 1) s += __shfl_down_sync(0xffffffffu, s, off);
        if (lane == 0) {
            s += isls ? bls[k] : bmu[k];
            if (isls) ls_s[k] = s; else mu_s[k] = s;
        }
    }
    __syncthreads();
    if (tid == 0) {
        float m = -1e30f;
        for (int k = 0; k < KK; k++) m = fmaxf(m, mu_s[k]);
        float sum = 0.0f;
        for (int k = 0; k < KK; k++) sum += expf(mu_s[k] - m);
        float inv = 1.0f / sum;
        double kl = 0.0;
        for (int k = 0; k < KK; k++) {
            g_theta[d * KK + k] = expf(mu_s[k] - m) * inv;
            float mu = mu_s[k], ls = ls_s[k], eta = g_eta_td[d * KK + k];
            float dm = mu - eta;
            kl += (double)((expf(ls) + dm * dm) / (1.0f + 1e-6f) - 1.0f - ls);
        }
        atomicAdd(&g_acc[3], 0.5 * kl);
    }
}

// wa[d,k,l] = alpha[k, t_d, l] * lam[s_d, l]
__global__ void k_wa(const float* __restrict__ alpha, const float* __restrict__ lam,
                     const int* __restrict__ times, const int* __restrict__ sources) {
    int idx = blockIdx.x * 256 + threadIdx.x;
    if (idx >= DD * KK * LL) return;
    int d = idx / (KK * LL);
    int r = idx - d * (KK * LL);
    int k = r / LL;
    int l = r - k * LL;
    int t = times[d], s = sources[d];
    g_wa[idx] = alpha[(k * TT + t) * LL + l] * lam[s * LL + l];
}

// big batched GEMM: E[d,k,v] = exp(rho[v,:].wa[d,k,:]), f32x2 FMA; Z fused
#define G1_LC 30
__global__ void __launch_bounds__(128) k_g1() {
    __shared__ unsigned long long rho2_s[G1_LC * 128];
    __shared__ unsigned long long w2_s[G1_LC * KK];
    __shared__ float zred[KK * 4];
    const int d = blockIdx.y;
    const int v0 = blockIdx.x * 256;
    const int tid = threadIdx.x;
    const int warp = tid >> 5, lane = tid & 31;
    const int vlo = v0 + tid, vhi = v0 + 128 + tid;
    unsigned long long acc[KK];
#pragma unroll
    for (int k = 0; k < KK; k++) acc[k] = 0ull;
    const float* __restrict__ wa = g_wa + d * KK * LL;
    for (int chunk = 0; chunk < LL / G1_LC; chunk++) {
        const int l0 = chunk * G1_LC;
        for (int idx = tid; idx < KK * G1_LC; idx += 128) {
            int c = idx / KK, k = idx - c * KK;
            float w = wa[k * LL + l0 + c];
            w2_s[idx] = pack2(w, w);
        }
#pragma unroll
        for (int c = 0; c < G1_LC; c++) {
            const float* rT = g_rhoT + (l0 + c) * VV;
            float rlo = (vlo < VV) ? rT[vlo] : 0.0f;
            float rhi = (vhi < VV) ? rT[vhi] : 0.0f;
            rho2_s[c * 128 + tid] = pack2(rlo, rhi);
        }
        __syncthreads();
#pragma unroll 1
        for (int c = 0; c < G1_LC; c++) {
            unsigned long long r2 = rho2_s[c * 128 + tid];
            const ulonglong2* w2p = (const ulonglong2*)&w2_s[c * KK];
#pragma unroll
            for (int j = 0; j < KK / 2; j++) {
                ulonglong2 w = w2p[j];
                acc[2 * j]     = fma2(r2, w.x, acc[2 * j]);
                acc[2 * j + 1] = fma2(r2, w.y, acc[2 * j + 1]);
            }
        }
        __syncthreads();
    }
    float* E = g_E + d * KK * VV;
#pragma unroll
    for (int k = 0; k < KK; k++) {
        float lo, hi;
        unpack2(acc[k], lo, hi);
        float elo = __expf(lo), ehi = __expf(hi);
        float zp = 0.0f;
        if (vlo < VV) { E[k * VV + vlo] = elo; zp += elo; }
        if (vhi < VV) { E[k * VV + vhi] = ehi; zp += ehi; }
#pragma unroll
        for (int off = 16; off; off >>= 1) zp += __shfl_down_sync(0xffffffffu, zp, off);
        if (lane == 0) zred[k * 4 + warp] = zp;
    }
    __syncthreads();
    if (tid < KK) {
        float z = zred[tid * 4] + zred[tid * 4 + 1] + zred[tid * 4 + 2] + zred[tid * 4 + 3];
        atomicAdd(&g_Z[d * KK + tid], z);
    }
}

// nll: lik[d,v] = sum_k (theta/Z) * E ;  acc -= log(lik+1e-6)*bows
__global__ void k_nll(const float* __restrict__ bows) {
    int d = blockIdx.y;
    int v = blockIdx.x * 256 + threadIdx.x;
    __shared__ float wk[KK];
    if (threadIdx.x < KK)
        wk[threadIdx.x] = g_theta[d * KK + threadIdx.x] / g_Z[d * KK + threadIdx.x];
    __syncthreads();
    float term = 0.0f;
    if (v < VV) {
        const float* E = g_E + d * KK * VV + v;
        float lik = 0.0f;
#pragma unroll
        for (int k = 0; k < KK; k++) lik += wk[k] * E[k * VV];
        term = __logf(lik + 1e-6f) * bows[d * VV + v];
    }
    __shared__ float sr[8];
    float s = block_reduce_256(term, sr);
    if (threadIdx.x == 0) atomicAdd(&g_acc[0], -(double)s);
}

__global__ void k_final(float* out) {
    int i = threadIdx.x;
    if (i < 4) out[i] = (float)g_acc[i];
}

// ---------------- static setup (outside measured window) ----------------
#define LSTM_SMEM (200 * 200 * 4)
struct StreamRes {
    cudaStream_t sB;
    cudaEvent_t evFork, evJoin, evH1;
    bool ok;
    bool lstm_ok;
    StreamRes() {
        ok = true; lstm_ok = false;
        int loPri = 0, hiPri = 0;
        cudaDeviceGetStreamPriorityRange(&loPri, &hiPri);  // loPri = least priority
        if (cudaStreamCreateWithPriority(&sB, cudaStreamNonBlocking, loPri) != cudaSuccess)
            ok = false;
        if (ok && cudaEventCreateWithFlags(&evFork, cudaEventDisableTiming) != cudaSuccess) ok = false;
        if (ok && cudaEventCreateWithFlags(&evJoin, cudaEventDisableTiming) != cudaSuccess) ok = false;
        if (ok && cudaEventCreateWithFlags(&evH1, cudaEventDisableTiming) != cudaSuccess) ok = false;
        if (cudaFuncSetAttribute(k_lstm_smem,
                                 cudaFuncAttributeMaxDynamicSharedMemorySize,
                                 LSTM_SMEM) == cudaSuccess)
            lstm_ok = true;
        if (ok) {
            k_warm<<<1, 1, 0, sB>>>();
            if (cudaStreamSynchronize(sB) != cudaSuccess) ok = false;
        }
        (void)cudaGetLastError();
    }
};
static StreamRes g_sr;

// ---------------- launch ----------------
extern "C" void kernel_launch(void* const* d_in, const int* in_sizes, int n_in,
                              void* d_out, int out_size) {
    const float* bows    = (const float*)d_in[0];
    const float* rnn_inp = (const float*)d_in[1];
    const int*   times   = (const int*)d_in[2];
    const int*   sources = (const int*)d_in[3];
    const float* rho     = (const float*)d_in[4];
    const float* lam     = (const float*)d_in[5];
    const float* mu_qa   = (const float*)d_in[6];
    const float* ls_qa   = (const float*)d_in[7];
    const float* W_t1    = (const float*)d_in[8];
    const float* b_t1    = (const float*)d_in[9];
    const float* W_t2    = (const float*)d_in[10];
    const float* b_t2    = (const float*)d_in[11];
    const float* W_mu_th = (const float*)d_in[12];
    const float* b_mu_th = (const float*)d_in[13];
    const float* W_ls_th = (const float*)d_in[14];
    const float* b_ls_th = (const float*)d_in[15];
    const float* W_em    = (const float*)d_in[16];
    const float* b_em    = (const float*)d_in[17];
    const float* Wih0    = (const float*)d_in[18];
    const float* Whh0    = (const float*)d_in[19];
    const float* bl0     = (const float*)d_in[20];
    const float* Wih1    = (const float*)d_in[21];
    const float* Whh1    = (const float*)d_in[22];
    const float* bl1     = (const float*)d_in[23];
    const float* W_mu_e  = (const float*)d_in[24];
    const float* b_mu_e  = (const float*)d_in[25];
    const float* W_ls_e  = (const float*)d_in[26];
    const float* b_ls_e  = (const float*)d_in[27];

    float *p_x, *p_xw0, *p_xw1, *p_hs0, *p_hs1, *p_h1, *p_h2;
    float *p_rhoT, *p_WmueT, *p_WlseT, *p_WmuthT, *p_WlsthT, *p_Amu, *p_Als, *p_etd;
    cudaGetSymbolAddress((void**)&p_x, g_x);
    cudaGetSymbolAddress((void**)&p_xw0, g_xw0);
    cudaGetSymbolAddress((void**)&p_xw1, g_xw1);
    cudaGetSymbolAddress((void**)&p_hs0, g_hs0);
    cudaGetSymbolAddress((void**)&p_hs1, g_hs1);
    cudaGetSymbolAddress((void**)&p_h1, g_h1);
    cudaGetSymbolAddress((void**)&p_h2, g_h2);
    cudaGetSymbolAddress((void**)&p_rhoT, g_rhoT);
    cudaGetSymbolAddress((void**)&p_WmueT, g_WmueT);
    cudaGetSymbolAddress((void**)&p_WlseT, g_WlseT);
    cudaGetSymbolAddress((void**)&p_WmuthT, g_WmuthT);
    cudaGetSymbolAddress((void**)&p_WlsthT, g_WlsthT);
    cudaGetSymbolAddress((void**)&p_Amu, g_Amu);
    cudaGetSymbolAddress((void**)&p_Als, g_Als);
    cudaGetSymbolAddress((void**)&p_etd, g_eta_td);

    dim3 t32(32, 32);
    cudaStream_t sA = 0;
    cudaStream_t sB = g_sr.ok ? g_sr.sB : (cudaStream_t)0;

    // ---- common prologue ----
    k_zero<<<(DD * KK + 255) / 256, 256, 0, sA>>>();

    if (g_sr.ok) {
        cudaEventRecord(g_sr.evFork, sA);
        cudaStreamWaitEvent(sB, g_sr.evFork, 0);
    }

    // ---- chain B (low-priority stream): kl_alpha + rhoT + wa + h1(bows) + g1 ----
    k_kl_alpha<<<(KK * TT * LL + 255) / 256, 256, 0, sB>>>(mu_qa, ls_qa);
    k_transpose<<<dim3((VV + 31) / 32, (LL + 31) / 32), t32, 0, sB>>>(rho, p_rhoT, VV, LL);
    k_wa<<<(DD * KK * LL + 255) / 256, 256, 0, sB>>>(mu_qa, lam, times, sources);
    // h1 = b_t1 + bows @ W_t1[0:VV]
    k_fill<<<(DD * TH + 255) / 256, 256, 0, sB>>>(p_h1, b_t1, DD, TH);
    k_gemm_sk<<<dim3((TH + 63) / 64, (DD + 63) / 64, 6), 256, 0, sB>>>(bows, W_t1, p_h1, DD, TH, VV, (VV + 5) / 6);
    if (g_sr.ok) cudaEventRecord(g_sr.evH1, sB);
    k_g1<<<dim3((VV + 255) / 256, DD), 128, 0, sB>>>();
    if (g_sr.ok) cudaEventRecord(g_sr.evJoin, sB);

    // ---- chain A (default stream, higher priority): sequential path ----
    k_transpose<<<dim3((EH + KK + 31) / 32, (KK + 31) / 32), t32, 0, sA>>>(W_mu_e, p_WmueT, EH + KK, KK);
    k_transpose<<<dim3((EH + KK + 31) / 32, (KK + 31) / 32), t32, 0, sA>>>(W_ls_e, p_WlseT, EH + KK, KK);
    k_transpose<<<dim3((TH + 31) / 32, (KK + 31) / 32), t32, 0, sA>>>(W_mu_th, p_WmuthT, TH, KK);
    k_transpose<<<dim3((TH + 31) / 32, (KK + 31) / 32), t32, 0, sA>>>(W_ls_th, p_WlsthT, TH, KK);

    k_fill<<<(TT * EH + 255) / 256, 256, 0, sA>>>(p_x, b_em, TT, EH);
    k_gemm_sk<<<dim3((EH + 63) / 64, 1, 6), 256, 0, sA>>>(rnn_inp, W_em, p_x, TT, EH, VV, (VV + 5) / 6);

    k_fill<<<(TT * 4 * EH + 255) / 256, 256, 0, sA>>>(p_xw0, bl0, TT, 4 * EH);
    k_gemm_sk<<<dim3((4 * EH + 63) / 64, 1, 2), 256, 0, sA>>>(p_x, Wih0, p_xw0, TT, 4 * EH, EH, EH / 2);
    if (g_sr.lstm_ok) k_lstm_smem<<<4, 416, LSTM_SMEM, sA>>>(p_xw0, Whh0, p_hs0, 0);
    else              k_lstm4<<<4, 512, 0, sA>>>(p_xw0, Whh0, p_hs0, 0);

    k_fill<<<(TT * 4 * EH + 255) / 256, 256, 0, sA>>>(p_xw1, bl1, TT, 4 * EH);
    k_gemm_sk<<<dim3((4 * EH + 63) / 64, 1, 2), 256, 0, sA>>>(p_hs0, Wih1, p_xw1, TT, 4 * EH, EH, EH / 2);
    if (g_sr.lstm_ok) k_lstm_smem<<<4, 416, LSTM_SMEM, sA>>>(p_xw1, Whh1, p_hs1, 1);
    else              k_lstm4<<<4, 512, 0, sA>>>(p_xw1, Whh1, p_hs1, 1);

    // eta precompute + scan
    k_fill<<<(TT * KK + 255) / 256, 256, 0, sA>>>(p_Amu, b_mu_e, TT, KK);
    k_gemm_sk<<<dim3(1, 1, 2), 256, 0, sA>>>(p_hs1, W_mu_e, p_Amu, TT, KK, EH, EH / 2);
    k_fill<<<(TT * KK + 255) / 256, 256, 0, sA>>>(p_Als, b_ls_e, TT, KK);
    k_gemm_sk<<<dim3(1, 1, 2), 256, 0, sA>>>(p_hs1, W_ls_e, p_Als, TT, KK, EH, EH / 2);
    k_eta2<<<1, 128, 0, sA>>>(p_Amu, p_Als);
    k_etatd<<<(DD * KK + 255) / 256, 256, 0, sA>>>(times);

    // theta MLP: add eta part to h1, relu, h2, muls
    if (g_sr.ok) cudaStreamWaitEvent(sA, g_sr.evH1, 0);
    k_gemm_sk<<<dim3((TH + 63) / 64, (DD + 63) / 64, 1), 256, 0, sA>>>(p_etd, W_t1 + VV * TH, p_h1, DD, TH, KK, KK);
    k_relu<<<(DD * TH + 255) / 256, 256, 0, sA>>>(p_h1, DD * TH);
    k_fill<<<(DD * TH + 255) / 256, 256, 0, sA>>>(p_h2, b_t2, DD, TH);
    k_gemm_sk<<<dim3((TH + 63) / 64, (DD + 63) / 64, 3), 256, 0, sA>>>(p_h1, W_t2, p_h2, DD, TH, TH, (TH + 2) / 3);
    k_relu<<<(DD * TH + 255) / 256, 256, 0, sA>>>(p_h2, DD * TH);
    k_muls<<<DD, 128, 0, sA>>>(b_mu_th, b_ls_th);

    // ---- join, then nll + output ----
    if (g_sr.ok) cudaStreamWaitEvent(sA, g_sr.evJoin, 0);
    k_nll<<<dim3((VV + 255) / 256, DD), 256, 0, sA>>>(bows);
    k_final<<<1, 4, 0, sA>>>((float*)d_out);
    (void)in_sizes; (void)n_in; (void)out_size;
}

// round 11
// speedup vs baseline: 5.4611x; 1.9939x over previous
#include <cuda_runtime.h>
#include <math.h>

// ---------------- problem constants ----------------
#define KK 50
#define TT 50
#define VV 3000
#define LL 300
#define TH 800
#define EH 200
#define DD 256
#define SS 8

// ---------------- device scratch (static, no allocs) ----------------
__device__ double   g_acc[4];                 // nll, kl_alpha, kl_eta, kl_theta
__device__ unsigned g_lbar[2];                // legacy lstm spin barriers (fallback)
__device__ unsigned g_lrdy[2][4];             // per-layer per-block ready counters
__device__ float  g_x[TT * EH];
__device__ float  g_xw0[TT * 4 * EH];
__device__ float  g_xw1[TT * 4 * EH];
__device__ float  g_hs0[TT * EH];
__device__ float  g_hs1[TT * EH];
__device__ float  g_gbuf[2][4 * EH];          // fallback gate exchange
__device__ float  g_etas[TT * KK];
__device__ float  g_Amu[TT * KK];
__device__ float  g_Als[TT * KK];
__device__ float  g_eta_td[DD * KK];
__device__ float  g_h1[DD * TH];
__device__ float  g_h2[DD * TH];
__device__ float  g_theta[DD * KK];
__device__ float  g_wa[DD * KK * LL];
__device__ float  g_WmueT[KK * (EH + KK)];
__device__ float  g_WlseT[KK * (EH + KK)];
__device__ float  g_WmuthT[KK * TH];
__device__ float  g_WlsthT[KK * TH];
__device__ float  g_E[DD * KK * VV];          // exp(logit), 153.6 MB
__device__ float  g_Z[DD * KK];

// ---------------- helpers ----------------
__device__ __forceinline__ float sigm(float x) { return 1.0f / (1.0f + expf(-x)); }

__device__ __forceinline__ unsigned f2tf32(float f) {
    unsigned r;
    asm("cvt.rna.tf32.f32 %0, %1;" : "=r"(r) : "f"(f));
    return r;
}
__device__ __forceinline__ void mma_tf32(float* c, const unsigned* a, const unsigned* b) {
    asm volatile(
        "mma.sync.aligned.m16n8k8.row.col.f32.tf32.tf32.f32 "
        "{%0,%1,%2,%3}, {%4,%5,%6,%7}, {%8,%9}, {%0,%1,%2,%3};"
        : "+f"(c[0]), "+f"(c[1]), "+f"(c[2]), "+f"(c[3])
        : "r"(a[0]), "r"(a[1]), "r"(a[2]), "r"(a[3]), "r"(b[0]), "r"(b[1]));
}
__device__ __forceinline__ void st_release_gpu(unsigned* p, unsigned v) {
    asm volatile("st.release.gpu.global.u32 [%0], %1;" :: "l"(p), "r"(v) : "memory");
}
__device__ __forceinline__ unsigned ld_acquire_gpu(unsigned* p) {
    unsigned v;
    asm volatile("ld.acquire.gpu.global.u32 %0, [%1];" : "=r"(v) : "l"(p) : "memory");
    return v;
}

__device__ __forceinline__ float block_reduce_256(float v, float* sr) {
    int tid = threadIdx.x;
#pragma unroll
    for (int off = 16; off; off >>= 1) v += __shfl_down_sync(0xffffffffu, v, off);
    if ((tid & 31) == 0) sr[tid >> 5] = v;
    __syncthreads();
    if (tid < 8) {
        v = sr[tid];
#pragma unroll
        for (int off = 4; off; off >>= 1) v += __shfl_down_sync(0xffu, v, off);
    }
    return v;
}

// ---------------- init ----------------
__global__ void k_warm() {}

__global__ void k_zero() {
    int idx = blockIdx.x * 256 + threadIdx.x;
    if (idx < DD * KK) g_Z[idx] = 0.0f;
    if (idx < 4) g_acc[idx] = 0.0;
    if (idx < 2) g_lbar[idx] = 0u;
    if (idx < 8) ((unsigned*)g_lrdy)[idx] = 0u;
}

// kl_alpha: elementwise over (K,T,L)
__global__ void k_kl_alpha(const float* __restrict__ mu, const float* __restrict__ ls) {
    const int N = KK * TT * LL;
    int idx = blockIdx.x * 256 + threadIdx.x;
    float c = 0.0f;
    if (idx < N) {
        int r = idx % (TT * LL);
        int t = r / LL;
        float qm = mu[idx], ql = ls[idx];
        if (t == 0) {
            c = (expf(ql) + qm * qm) / (1.0f + 1e-6f) - 1.0f - ql;
        } else {
            const float LOGD = -5.2983174f;
            float den = expf(LOGD) + 1e-6f;
            float dm = qm - mu[idx - LL];
            c = (expf(ql) + dm * dm) / den - 1.0f + LOGD - ql;
        }
    }
    __shared__ float sr[8];
    float s = block_reduce_256(c, sr);
    if (threadIdx.x == 0) atomicAdd(&g_acc[1], 0.5 * (double)s);
}

// generic transpose: B[n*M+m] = A[m*N+n]
__global__ void k_transpose(const float* __restrict__ A, float* __restrict__ B,
                            int M, int N) {
    __shared__ float tile[32][33];
    int m0 = blockIdx.x * 32, n0 = blockIdx.y * 32;
    int tx = threadIdx.x, ty = threadIdx.y;
    int m = m0 + ty, n = n0 + tx;
    if (m < M && n < N) tile[ty][tx] = A[m * N + n];
    __syncthreads();
    int nb = n0 + ty, mb = m0 + tx;
    if (nb < N && mb < M) B[nb * M + mb] = tile[tx][ty];
}

__global__ void k_fill(float* __restrict__ C, const float* __restrict__ bias,
                       int M, int N) {
    int idx = blockIdx.x * 256 + threadIdx.x;
    if (idx < M * N) C[idx] = bias[idx % N];
}

__global__ void k_relu(float* __restrict__ C, int n) {
    int idx = blockIdx.x * 256 + threadIdx.x;
    if (idx < n) C[idx] = fmaxf(C[idx], 0.0f);
}

// split-K tiled GEMM: C += A(MxK) @ B(KxN) over k-slice, atomic epilogue
__global__ void k_gemm_sk(const float* __restrict__ A, const float* __restrict__ B,
                          float* __restrict__ C, int M, int N, int Kd, int kchunk) {
    __shared__ float sA[16][65];
    __shared__ float sB[16][64];
    int tid = threadIdx.x;
    int tx = tid & 15, ty = tid >> 4;
    int row0 = blockIdx.y * 64 + ty * 4;
    int col0 = blockIdx.x * 64 + tx * 4;
    int kb = blockIdx.z * kchunk;
    int ke = min(kb + kchunk, Kd);
    float acc[4][4];
#pragma unroll
    for (int i = 0; i < 4; i++)
#pragma unroll
        for (int j = 0; j < 4; j++) acc[i][j] = 0.0f;

    for (int k0 = kb; k0 < ke; k0 += 16) {
#pragma unroll
        for (int i = 0; i < 4; i++) {
            int idx = tid + i * 256;
            int m = idx >> 4, kk = idx & 15;
            int gm = blockIdx.y * 64 + m, gk = k0 + kk;
            float v = 0.0f;
            if (gm < M && gk < ke) v = A[gm * Kd + gk];
            sA[kk][m] = v;
        }
#pragma unroll
        for (int i = 0; i < 4; i++) {
            int idx = tid + i * 256;
            int kk = idx >> 6, n = idx & 63;
            int gk = k0 + kk, gn = blockIdx.x * 64 + n;
            float v = 0.0f;
            if (gk < ke && gn < N) v = B[gk * N + gn];
            sB[kk][n] = v;
        }
        __syncthreads();
#pragma unroll
        for (int kk = 0; kk < 16; kk++) {
            float a[4], b[4];
#pragma unroll
            for (int i = 0; i < 4; i++) a[i] = sA[kk][ty * 4 + i];
#pragma unroll
            for (int j = 0; j < 4; j++) b[j] = sB[kk][tx * 4 + j];
#pragma unroll
            for (int i = 0; i < 4; i++)
#pragma unroll
                for (int j = 0; j < 4; j++) acc[i][j] += a[i] * b[j];
        }
        __syncthreads();
    }
#pragma unroll
    for (int i = 0; i < 4; i++)
#pragma unroll
        for (int j = 0; j < 4; j++) {
            int m = row0 + i, n = col0 + j;
            if (m < M && n < N) atomicAdd(&C[m * N + n], acc[i][j]);
        }
}

// ---------------- LSTM: element-partitioned, weights in SMEM ----------------
// 4 blocks x 416 threads. Block b owns h[b*50 .. b*50+50), all 4 gates.
// Whh slice (160KB) staged in dynamic smem once. Per-step sync via scoped
// release/acquire counters (no MEMBAR.ALL.GPU).
__global__ void __launch_bounds__(416) k_lstm_smem(const float* __restrict__ xw,
                                                   const float* __restrict__ Whh,
                                                   float* __restrict__ hs, int L) {
    extern __shared__ float s_w[];                 // [200][200], row-major by output
    __shared__ __align__(16) float h_s[EH];
    __shared__ float c_s[50];
    __shared__ float g_loc[200];
    const int b = blockIdx.x;
    const int tid = threadIdx.x;

    for (int idx = tid; idx < 200 * 200; idx += 416) {
        int i = idx / 200, o = idx - (idx / 200) * 200;
        int gi = o / 50, e = o - gi * 50;
        int col = gi * 200 + b * 50 + e;
        s_w[o * 200 + i] = Whh[i * 800 + col];
    }
    if (tid < EH) h_s[tid] = 0.0f;
    if (tid < 50) c_s[tid] = 0.0f;
    __syncthreads();

    const int o = ((tid >> 1) % 200);
    const int half = tid & 1;
    const int gi = o / 50, e = o - gi * 50;
    const int col = gi * 200 + b * 50 + e;
    unsigned* rdy = g_lrdy[L];

    for (int t = 0; t < TT; t++) {
        const float4* wv = (const float4*)(s_w + o * 200 + half * 100);
        const float4* hv = ((const float4*)h_s) + half * 25;
        float4 a = make_float4(0.f, 0.f, 0.f, 0.f);
#pragma unroll
        for (int j = 0; j < 25; j++) {
            float4 w = wv[j], h4 = hv[j];
            a.x = fmaf(w.x, h4.x, a.x);
            a.y = fmaf(w.y, h4.y, a.y);
            a.z = fmaf(w.z, h4.z, a.z);
            a.w = fmaf(w.w, h4.w, a.w);
        }
        float s = (a.x + a.y) + (a.z + a.w);
        s += __shfl_down_sync(0xffffffffu, s, 1);
        if (half == 0 && tid < 400) g_loc[o] = s + xw[t * 800 + col];
        __syncthreads();
        if (tid < 50) {
            float ig = sigm(g_loc[tid]);
            float fg = sigm(g_loc[50 + tid]);
            float gg = tanhf(g_loc[100 + tid]);
            float og = sigm(g_loc[150 + tid]);
            float c = fg * c_s[tid] + ig * gg;
            float h = og * tanhf(c);
            c_s[tid] = c;
            __stcg(&hs[t * EH + b * 50 + tid], h);
        }
        __syncthreads();
        if (tid == 0) {
            st_release_gpu(&rdy[b], (unsigned)(t + 1));  // orders prior CTA writes (post-bar)
        } else if (tid <= 3) {
            int p = (b + tid) & 3;
            while (ld_acquire_gpu(&rdy[p]) < (unsigned)(t + 1)) __nanosleep(20);
        }
        __syncthreads();
        if (tid < EH) h_s[tid] = __ldcg(&hs[t * EH + tid]);
        __syncthreads();
    }
}

// ---------------- LSTM fallback ----------------
__global__ void __launch_bounds__(512) k_lstm4(const float* __restrict__ xw,
                                               const float* __restrict__ Whh,
                                               float* __restrict__ hs, int L) {
    __shared__ float h_s[EH];
    __shared__ float c_s[EH];
    __shared__ float4 p_s[8][52];
    const int b = blockIdx.x;
    const int tid = threadIdx.x;
    const int iq = tid / 50, c4 = tid % 50;
    if (tid < EH) { h_s[tid] = 0.0f; c_s[tid] = 0.0f; }
    __syncthreads();
    const float4* W4 = (const float4*)Whh;
    unsigned* bar = &g_lbar[L];
    for (int t = 0; t < TT; t++) {
        if (tid < 400) {
            float4 a = make_float4(0.f, 0.f, 0.f, 0.f);
            int base = b * 50 + c4;
#pragma unroll
            for (int u = 0; u < 25; u++) {
                int i = iq * 25 + u;
                float hv = h_s[i];
                float4 w = W4[i * 200 + base];
                a.x += hv * w.x; a.y += hv * w.y; a.z += hv * w.z; a.w += hv * w.w;
            }
            p_s[iq][c4] = a;
        }
        __syncthreads();
        if (tid < 200) {
            const float* ps = (const float*)p_s;
            float g = xw[t * 800 + b * 200 + tid];
#pragma unroll
            for (int q = 0; q < 8; q++) g += ps[q * 208 + tid];
            __stcg(&g_gbuf[t & 1][b * 200 + tid], g);
        }
        __threadfence();
        __syncthreads();
        if (tid == 0) {
            atomicAdd(bar, 1u);
            while (atomicAdd(bar, 0u) < 4u * (unsigned)(t + 1)) {}
        }
        __syncthreads();
        __threadfence();
        if (tid < EH) {
            const float* gb = g_gbuf[t & 1];
            float ig = sigm(__ldcg(&gb[tid]));
            float fg = sigm(__ldcg(&gb[EH + tid]));
            float gg = tanhf(__ldcg(&gb[2 * EH + tid]));
            float og = sigm(__ldcg(&gb[3 * EH + tid]));
            float c = fg * c_s[tid] + ig * gg;
            float h = og * tanhf(c);
            c_s[tid] = c;
            h_s[tid] = h;
            if (b == 0) hs[t * EH + tid] = h;
        }
        __syncthreads();
    }
}

// eta scan v2
__global__ void __launch_bounds__(128) k_eta2(const float* __restrict__ Amu,
                                              const float* __restrict__ Als) {
    __shared__ float eta_s[KK];
    __shared__ float mu_s[KK], ls_s[KK];
    __shared__ float kl_sh[2];
    int tid = threadIdx.x;
    int warp = tid >> 5;
    if (tid < KK) eta_s[tid] = 0.0f;
    __syncthreads();
    double kl_acc = 0.0;
    const float LOGD = -5.2983174f;
    for (int t = 0; t < TT; t++) {
        if (tid < KK) {
            float s = Amu[t * KK + tid];
            const float* W = &g_WmueT[tid * (EH + KK) + EH];
#pragma unroll
            for (int j = 0; j < KK; j++) s += eta_s[j] * W[j];
            mu_s[tid] = s;
        } else if (tid >= 64 && tid < 64 + KK) {
            int k = tid - 64;
            float s = Als[t * KK + k];
            const float* W = &g_WlseT[k * (EH + KK) + EH];
#pragma unroll
            for (int j = 0; j < KK; j++) s += eta_s[j] * W[j];
            ls_s[k] = s;
        }
        __syncthreads();
        if (tid < 64) {
            float term = 0.0f;
            if (tid < KK) {
                float pls = (t == 0) ? 0.0f : LOGD;
                float den = expf(pls) + 1e-6f;
                float dm = mu_s[tid] - eta_s[tid];
                term = (expf(ls_s[tid]) + dm * dm) / den - 1.0f + pls - ls_s[tid];
            }
#pragma unroll
            for (int off = 16; off; off >>= 1) term += __shfl_down_sync(0xffffffffu, term, off);
            if ((tid & 31) == 0) kl_sh[warp] = term;
        }
        __syncthreads();
        if (tid == 0) kl_acc += (double)(kl_sh[0] + kl_sh[1]);
        if (tid < KK) {
            eta_s[tid] = mu_s[tid];
            g_etas[t * KK + tid] = mu_s[tid];
        }
        __syncthreads();
    }
    if (tid == 0) g_acc[2] = 0.5 * kl_acc;
}

// eta_td scatter
__global__ void k_etatd(const int* __restrict__ times) {
    int idx = blockIdx.x * 256 + threadIdx.x;
    if (idx >= DD * KK) return;
    int d = idx / KK, k = idx - d * KK;
    g_eta_td[idx] = g_etas[times[d] * KK + k];
}

// mu_th / ls_th + softmax theta + kl_theta
__global__ void __launch_bounds__(128) k_muls(const float* __restrict__ bmu,
                                              const float* __restrict__ bls) {
    int d = blockIdx.x;
    __shared__ float h_s[TH];
    __shared__ float mu_s[KK], ls_s[KK];
    int tid = threadIdx.x, warp = tid >> 5, lane = tid & 31;
    for (int i = tid; i < TH; i += 128) h_s[i] = g_h2[d * TH + i];
    __syncthreads();
    for (int job = warp; job < 2 * KK; job += 4) {
        int k = job >> 1, isls = job & 1;
        const float* W = isls ? g_WlsthT : g_WmuthT;
        float s = 0.0f;
        for (int i = lane; i < TH; i += 32) s += h_s[i] * W[k * TH + i];
#pragma unroll
        for (int off = 16; off; off >>= 1) s += __shfl_down_sync(0xffffffffu, s, off);
        if (lane == 0) {
            s += isls ? bls[k] : bmu[k];
            if (isls) ls_s[k] = s; else mu_s[k] = s;
        }
    }
    __syncthreads();
    if (tid == 0) {
        float m = -1e30f;
        for (int k = 0; k < KK; k++) m = fmaxf(m, mu_s[k]);
        float sum = 0.0f;
        for (int k = 0; k < KK; k++) sum += expf(mu_s[k] - m);
        float inv = 1.0f / sum;
        double kl = 0.0;
        for (int k = 0; k < KK; k++) {
            g_theta[d * KK + k] = expf(mu_s[k] - m) * inv;
            float mu = mu_s[k], ls = ls_s[k], eta = g_eta_td[d * KK + k];
            float dm = mu - eta;
            kl += (double)((expf(ls) + dm * dm) / (1.0f + 1e-6f) - 1.0f - ls);
        }
        atomicAdd(&g_acc[3], 0.5 * kl);
    }
}

// wa[d,k,l] = alpha[k, t_d, l] * lam[s_d, l]
__global__ void k_wa(const float* __restrict__ alpha, const float* __restrict__ lam,
                     const int* __restrict__ times, const int* __restrict__ sources) {
    int idx = blockIdx.x * 256 + threadIdx.x;
    if (idx >= DD * KK * LL) return;
    int d = idx / (KK * LL);
    int r = idx - d * (KK * LL);
    int k = r / LL;
    int l = r - k * LL;
    int t = times[d], s = sources[d];
    g_wa[idx] = alpha[(k * TT + t) * LL + l] * lam[s * LL + l];
}

// ---------------- tf32 tensor-core batched GEMM + exp + Z ----------------
// E[d,k,v] = exp( wa[d,k,:] . rho[v,:] );  Z[d,k] += sum_v E.
// Block: (vtile of 256, d). 256 threads = 8 warps, warp grid 2(m) x 4(n).
// M=64 (50 topics padded), N=256, K=320 (300 padded), KC=32 per chunk.
#define GK 32
#define GST 36   // smem k-stride (pad): bank = (4*(lane>>2) + lane&3) % 32, conflict-free
__global__ void __launch_bounds__(256) k_g1_mma(const float* __restrict__ rho) {
    __shared__ unsigned wa_s[64 * GST];     //  9216 B
    __shared__ unsigned rho_s[256 * GST];   // 36864 B
    __shared__ float zsh[64];
    const int d = blockIdx.y;
    const int v0 = blockIdx.x * 256;
    const int tid = threadIdx.x;
    const int warp = tid >> 5, lane = tid & 31;
    const int g = lane >> 2, tg = lane & 3;
    const int mhalf = warp >> 2, nq = warp & 3;

    if (tid < 64) zsh[tid] = 0.0f;

    float c[2][8][4];
#pragma unroll
    for (int mi = 0; mi < 2; mi++)
#pragma unroll
        for (int ni = 0; ni < 8; ni++)
#pragma unroll
            for (int j = 0; j < 4; j++) c[mi][ni][j] = 0.0f;

    const float* __restrict__ wa = g_wa + d * KK * LL;

    for (int chunk = 0; chunk < 10; chunk++) {
        const int l0 = chunk * GK;
        // fill wa tile: 64 x 32 (float4 granules)
#pragma unroll
        for (int it = 0; it < 2; it++) {
            int i = tid + it * 256;             // 0..511 : m = i>>3, kk4 = (i&7)*4
            int m = i >> 3, kk4 = (i & 7) * 4;
            float4 v = make_float4(0.f, 0.f, 0.f, 0.f);
            if (m < KK && l0 + kk4 + 3 < LL)
                v = *(const float4*)(wa + m * LL + l0 + kk4);
            unsigned* ws = wa_s + m * GST + kk4;
            ws[0] = f2tf32(v.x); ws[1] = f2tf32(v.y);
            ws[2] = f2tf32(v.z); ws[3] = f2tf32(v.w);
        }
        // fill rho tile: 256 x 32
#pragma unroll
        for (int it = 0; it < 8; it++) {
            int i = tid + it * 256;             // 0..2047 : n = i>>3, kk4 = (i&7)*4
            int n = i >> 3, kk4 = (i & 7) * 4;
            int v = v0 + n;
            float4 val = make_float4(0.f, 0.f, 0.f, 0.f);
            if (v < VV && l0 + kk4 + 3 < LL)
                val = *(const float4*)(rho + v * LL + l0 + kk4);
            unsigned* rs = rho_s + n * GST + kk4;
            rs[0] = f2tf32(val.x); rs[1] = f2tf32(val.y);
            rs[2] = f2tf32(val.z); rs[3] = f2tf32(val.w);
        }
        __syncthreads();
#pragma unroll
        for (int ks = 0; ks < 4; ks++) {
            const int k0 = ks * 8;
            unsigned a[2][4], b[8][2];
#pragma unroll
            for (int mi = 0; mi < 2; mi++) {
                int rb = (mhalf * 2 + mi) * 16 + g;
                a[mi][0] = wa_s[rb * GST + k0 + tg];
                a[mi][1] = wa_s[(rb + 8) * GST + k0 + tg];
                a[mi][2] = wa_s[rb * GST + k0 + tg + 4];
                a[mi][3] = wa_s[(rb + 8) * GST + k0 + tg + 4];
            }
#pragma unroll
            for (int ni = 0; ni < 8; ni++) {
                int nb = (nq * 8 + ni) * 8 + g;
                b[ni][0] = rho_s[nb * GST + k0 + tg];
                b[ni][1] = rho_s[nb * GST + k0 + tg + 4];
            }
#pragma unroll
            for (int mi = 0; mi < 2; mi++)
#pragma unroll
                for (int ni = 0; ni < 8; ni++)
                    mma_tf32(c[mi][ni], a[mi], b[ni]);
        }
        __syncthreads();
    }

    // epilogue: exp, store E, reduce Z
    float* Ebase = g_E + (size_t)d * KK * VV;
    float zlo[2] = {0.f, 0.f}, zhi[2] = {0.f, 0.f};
#pragma unroll
    for (int mi = 0; mi < 2; mi++) {
        int row_lo = (mhalf * 2 + mi) * 16 + g;
        int row_hi = row_lo + 8;
#pragma unroll
        for (int ni = 0; ni < 8; ni++) {
            int v = v0 + (nq * 8 + ni) * 8 + tg * 2;
            bool vok = (v < VV);
            float e0 = vok ? __expf(c[mi][ni][0]) : 0.0f;
            float e1 = vok ? __expf(c[mi][ni][1]) : 0.0f;
            float e2 = vok ? __expf(c[mi][ni][2]) : 0.0f;
            float e3 = vok ? __expf(c[mi][ni][3]) : 0.0f;
            if (row_lo < KK) {
                if (vok) *(float2*)(Ebase + (size_t)row_lo * VV + v) = make_float2(e0, e1);
                zlo[mi] += e0 + e1;
            }
            if (row_hi < KK) {
                if (vok) *(float2*)(Ebase + (size_t)row_hi * VV + v) = make_float2(e2, e3);
                zhi[mi] += e2 + e3;
            }
        }
        // reduce across the 4 lanes sharing this row (tg = 0..3)
        zlo[mi] += __shfl_xor_sync(0xffffffffu, zlo[mi], 1);
        zlo[mi] += __shfl_xor_sync(0xffffffffu, zlo[mi], 2);
        zhi[mi] += __shfl_xor_sync(0xffffffffu, zhi[mi], 1);
        zhi[mi] += __shfl_xor_sync(0xffffffffu, zhi[mi], 2);
        if (tg == 0) {
            if (row_lo < KK) atomicAdd(&zsh[row_lo], zlo[mi]);
            if (row_hi < KK) atomicAdd(&zsh[row_hi], zhi[mi]);
        }
    }
    __syncthreads();
    if (tid < KK) atomicAdd(&g_Z[d * KK + tid], zsh[tid]);
}

// nll: lik[d,v] = sum_k (theta/Z) * E ;  acc -= log(lik+1e-6)*bows
__global__ void k_nll(const float* __restrict__ bows) {
    int d = blockIdx.y;
    int v = blockIdx.x * 256 + threadIdx.x;
    __shared__ float wk[KK];
    if (threadIdx.x < KK)
        wk[threadIdx.x] = g_theta[d * KK + threadIdx.x] / g_Z[d * KK + threadIdx.x];
    __syncthreads();
    float term = 0.0f;
    if (v < VV) {
        const float* E = g_E + (size_t)d * KK * VV + v;
        float lik = 0.0f;
#pragma unroll
        for (int k = 0; k < KK; k++) lik += wk[k] * E[k * VV];
        term = __logf(lik + 1e-6f) * bows[d * VV + v];
    }
    __shared__ float sr[8];
    float s = block_reduce_256(term, sr);
    if (threadIdx.x == 0) atomicAdd(&g_acc[0], -(double)s);
}

__global__ void k_final(float* out) {
    int i = threadIdx.x;
    if (i < 4) out[i] = (float)g_acc[i];
}

// ---------------- static setup (outside measured window) ----------------
#define LSTM_SMEM (200 * 200 * 4)
struct StreamRes {
    cudaStream_t sB;
    cudaEvent_t evFork, evJoin, evH1;
    bool ok;
    bool lstm_ok;
    StreamRes() {
        ok = true; lstm_ok = false;
        int loPri = 0, hiPri = 0;
        cudaDeviceGetStreamPriorityRange(&loPri, &hiPri);
        if (cudaStreamCreateWithPriority(&sB, cudaStreamNonBlocking, loPri) != cudaSuccess)
            ok = false;
        if (ok && cudaEventCreateWithFlags(&evFork, cudaEventDisableTiming) != cudaSuccess) ok = false;
        if (ok && cudaEventCreateWithFlags(&evJoin, cudaEventDisableTiming) != cudaSuccess) ok = false;
        if (ok && cudaEventCreateWithFlags(&evH1, cudaEventDisableTiming) != cudaSuccess) ok = false;
        if (cudaFuncSetAttribute(k_lstm_smem,
                                 cudaFuncAttributeMaxDynamicSharedMemorySize,
                                 LSTM_SMEM) == cudaSuccess)
            lstm_ok = true;
        if (ok) {
            k_warm<<<1, 1, 0, sB>>>();
            if (cudaStreamSynchronize(sB) != cudaSuccess) ok = false;
        }
        (void)cudaGetLastError();
    }
};
static StreamRes g_sr;

// ---------------- launch ----------------
extern "C" void kernel_launch(void* const* d_in, const int* in_sizes, int n_in,
                              void* d_out, int out_size) {
    const float* bows    = (const float*)d_in[0];
    const float* rnn_inp = (const float*)d_in[1];
    const int*   times   = (const int*)d_in[2];
    const int*   sources = (const int*)d_in[3];
    const float* rho     = (const float*)d_in[4];
    const float* lam     = (const float*)d_in[5];
    const float* mu_qa   = (const float*)d_in[6];
    const float* ls_qa   = (const float*)d_in[7];
    const float* W_t1    = (const float*)d_in[8];
    const float* b_t1    = (const float*)d_in[9];
    const float* W_t2    = (const float*)d_in[10];
    const float* b_t2    = (const float*)d_in[11];
    const float* W_mu_th = (const float*)d_in[12];
    const float* b_mu_th = (const float*)d_in[13];
    const float* W_ls_th = (const float*)d_in[14];
    const float* b_ls_th = (const float*)d_in[15];
    const float* W_em    = (const float*)d_in[16];
    const float* b_em    = (const float*)d_in[17];
    const float* Wih0    = (const float*)d_in[18];
    const float* Whh0    = (const float*)d_in[19];
    const float* bl0     = (const float*)d_in[20];
    const float* Wih1    = (const float*)d_in[21];
    const float* Whh1    = (const float*)d_in[22];
    const float* bl1     = (const float*)d_in[23];
    const float* W_mu_e  = (const float*)d_in[24];
    const float* b_mu_e  = (const float*)d_in[25];
    const float* W_ls_e  = (const float*)d_in[26];
    const float* b_ls_e  = (const float*)d_in[27];

    float *p_x, *p_xw0, *p_xw1, *p_hs0, *p_hs1, *p_h1, *p_h2;
    float *p_WmueT, *p_WlseT, *p_WmuthT, *p_WlsthT, *p_Amu, *p_Als, *p_etd;
    cudaGetSymbolAddress((void**)&p_x, g_x);
    cudaGetSymbolAddress((void**)&p_xw0, g_xw0);
    cudaGetSymbolAddress((void**)&p_xw1, g_xw1);
    cudaGetSymbolAddress((void**)&p_hs0, g_hs0);
    cudaGetSymbolAddress((void**)&p_hs1, g_hs1);
    cudaGetSymbolAddress((void**)&p_h1, g_h1);
    cudaGetSymbolAddress((void**)&p_h2, g_h2);
    cudaGetSymbolAddress((void**)&p_WmueT, g_WmueT);
    cudaGetSymbolAddress((void**)&p_WlseT, g_WlseT);
    cudaGetSymbolAddress((void**)&p_WmuthT, g_WmuthT);
    cudaGetSymbolAddress((void**)&p_WlsthT, g_WlsthT);
    cudaGetSymbolAddress((void**)&p_Amu, g_Amu);
    cudaGetSymbolAddress((void**)&p_Als, g_Als);
    cudaGetSymbolAddress((void**)&p_etd, g_eta_td);

    dim3 t32(32, 32);
    cudaStream_t sA = 0;
    cudaStream_t sB = g_sr.ok ? g_sr.sB : (cudaStream_t)0;

    // ---- common prologue ----
    k_zero<<<(DD * KK + 255) / 256, 256, 0, sA>>>();

    if (g_sr.ok) {
        cudaEventRecord(g_sr.evFork, sA);
        cudaStreamWaitEvent(sB, g_sr.evFork, 0);
    }

    // ---- chain B (low-priority stream): kl_alpha + wa + h1(bows) + g1_mma ----
    k_kl_alpha<<<(KK * TT * LL + 255) / 256, 256, 0, sB>>>(mu_qa, ls_qa);
    k_wa<<<(DD * KK * LL + 255) / 256, 256, 0, sB>>>(mu_qa, lam, times, sources);
    k_fill<<<(DD * TH + 255) / 256, 256, 0, sB>>>(p_h1, b_t1, DD, TH);
    k_gemm_sk<<<dim3((TH + 63) / 64, (DD + 63) / 64, 6), 256, 0, sB>>>(bows, W_t1, p_h1, DD, TH, VV, (VV + 5) / 6);
    if (g_sr.ok) cudaEventRecord(g_sr.evH1, sB);
    k_g1_mma<<<dim3(12, DD), 256, 0, sB>>>(rho);
    if (g_sr.ok) cudaEventRecord(g_sr.evJoin, sB);

    // ---- chain A (default stream, higher priority): sequential path ----
    k_transpose<<<dim3((EH + KK + 31) / 32, (KK + 31) / 32), t32, 0, sA>>>(W_mu_e, p_WmueT, EH + KK, KK);
    k_transpose<<<dim3((EH + KK + 31) / 32, (KK + 31) / 32), t32, 0, sA>>>(W_ls_e, p_WlseT, EH + KK, KK);
    k_transpose<<<dim3((TH + 31) / 32, (KK + 31) / 32), t32, 0, sA>>>(W_mu_th, p_WmuthT, TH, KK);
    k_transpose<<<dim3((TH + 31) / 32, (KK + 31) / 32), t32, 0, sA>>>(W_ls_th, p_WlsthT, TH, KK);

    k_fill<<<(TT * EH + 255) / 256, 256, 0, sA>>>(p_x, b_em, TT, EH);
    k_gemm_sk<<<dim3((EH + 63) / 64, 1, 12), 256, 0, sA>>>(rnn_inp, W_em, p_x, TT, EH, VV, (VV + 11) / 12);

    k_fill<<<(TT * 4 * EH + 255) / 256, 256, 0, sA>>>(p_xw0, bl0, TT, 4 * EH);
    k_gemm_sk<<<dim3((4 * EH + 63) / 64, 1, 4), 256, 0, sA>>>(p_x, Wih0, p_xw0, TT, 4 * EH, EH, EH / 4);
    if (g_sr.lstm_ok) k_lstm_smem<<<4, 416, LSTM_SMEM, sA>>>(p_xw0, Whh0, p_hs0, 0);
    else              k_lstm4<<<4, 512, 0, sA>>>(p_xw0, Whh0, p_hs0, 0);

    k_fill<<<(TT * 4 * EH + 255) / 256, 256, 0, sA>>>(p_xw1, bl1, TT, 4 * EH);
    k_gemm_sk<<<dim3((4 * EH + 63) / 64, 1, 4), 256, 0, sA>>>(p_hs0, Wih1, p_xw1, TT, 4 * EH, EH, EH / 4);
    if (g_sr.lstm_ok) k_lstm_smem<<<4, 416, LSTM_SMEM, sA>>>(p_xw1, Whh1, p_hs1, 1);
    else              k_lstm4<<<4, 512, 0, sA>>>(p_xw1, Whh1, p_hs1, 1);

    // eta precompute + scan
    k_fill<<<(TT * KK + 255) / 256, 256, 0, sA>>>(p_Amu, b_mu_e, TT, KK);
    k_gemm_sk<<<dim3(1, 1, 2), 256, 0, sA>>>(p_hs1, W_mu_e, p_Amu, TT, KK, EH, EH / 2);
    k_fill<<<(TT * KK + 255) / 256, 256, 0, sA>>>(p_Als, b_ls_e, TT, KK);
    k_gemm_sk<<<dim3(1, 1, 2), 256, 0, sA>>>(p_hs1, W_ls_e, p_Als, TT, KK, EH, EH / 2);
    k_eta2<<<1, 128, 0, sA>>>(p_Amu, p_Als);
    k_etatd<<<(DD * KK + 255) / 256, 256, 0, sA>>>(times);

    // theta MLP: add eta part to h1, relu, h2, muls
    if (g_sr.ok) cudaStreamWaitEvent(sA, g_sr.evH1, 0);
    k_gemm_sk<<<dim3((TH + 63) / 64, (DD + 63) / 64, 1), 256, 0, sA>>>(p_etd, W_t1 + VV * TH, p_h1, DD, TH, KK, KK);
    k_relu<<<(DD * TH + 255) / 256, 256, 0, sA>>>(p_h1, DD * TH);
    k_fill<<<(DD * TH + 255) / 256, 256, 0, sA>>>(p_h2, b_t2, DD, TH);
    k_gemm_sk<<<dim3((TH + 63) / 64, (DD + 63) / 64, 3), 256, 0, sA>>>(p_h1, W_t2, p_h2, DD, TH, TH, (TH + 2) / 3);
    k_relu<<<(DD * TH + 255) / 256, 256, 0, sA>>>(p_h2, DD * TH);
    k_muls<<<DD, 128, 0, sA>>>(b_mu_th, b_ls_th);

    // ---- join, then nll + output ----
    if (g_sr.ok) cudaStreamWaitEvent(sA, g_sr.evJoin, 0);
    k_nll<<<dim3((VV + 255) / 256, DD), 256, 0, sA>>>(bows);
    k_final<<<1, 4, 0, sA>>>((float*)d_out);
    (void)in_sizes; (void)n_in; (void)out_size;
}

// round 13
// speedup vs baseline: 5.5362x; 1.0138x over previous
#include <cuda_runtime.h>
#include <math.h>

// ---------------- problem constants ----------------
#define KK 50
#define TT 50
#define VV 3000
#define LL 300
#define TH 800
#define EH 200
#define DD 256
#define SS 8

// ---------------- device scratch (static, no allocs) ----------------
__device__ double   g_acc[4];                 // nll, kl_alpha, kl_eta, kl_theta
__device__ unsigned g_lbar[2];                // legacy lstm spin barriers (fallback)
__device__ unsigned g_lrdy[2][4];             // per-layer per-block ready counters
__device__ float  g_x[TT * EH];
__device__ float  g_xw0[TT * 4 * EH];
__device__ float  g_xw1[TT * 4 * EH];
__device__ float  g_hs0[TT * EH];
__device__ float  g_hs1[TT * EH];
__device__ float  g_gbuf[2][4 * EH];          // fallback gate exchange
__device__ float  g_etas[TT * KK];
__device__ float  g_Amu[TT * KK];
__device__ float  g_Als[TT * KK];
__device__ float  g_eta_td[DD * KK];
__device__ float  g_h1[DD * TH];
__device__ float  g_h2[DD * TH];
__device__ float  g_theta[DD * KK];
__device__ float  g_wa[DD * KK * LL];
__device__ float  g_WmueT[KK * (EH + KK)];
__device__ float  g_WlseT[KK * (EH + KK)];
__device__ float  g_WmuthT[KK * TH];
__device__ float  g_WlsthT[KK * TH];
__device__ float  g_E[DD * KK * VV];          // exp(logit), 153.6 MB
__device__ float  g_Z[DD * KK];

// ---------------- helpers ----------------
__device__ __forceinline__ float sigm(float x) { return 1.0f / (1.0f + expf(-x)); }

__device__ __forceinline__ unsigned f2tf32(float f) {
    unsigned r;
    asm("cvt.rna.tf32.f32 %0, %1;" : "=r"(r) : "f"(f));
    return r;
}
__device__ __forceinline__ void mma_tf32(float* c, const unsigned* a, const unsigned* b) {
    asm volatile(
        "mma.sync.aligned.m16n8k8.row.col.f32.tf32.tf32.f32 "
        "{%0,%1,%2,%3}, {%4,%5,%6,%7}, {%8,%9}, {%0,%1,%2,%3};"
        : "+f"(c[0]), "+f"(c[1]), "+f"(c[2]), "+f"(c[3])
        : "r"(a[0]), "r"(a[1]), "r"(a[2]), "r"(a[3]), "r"(b[0]), "r"(b[1]));
}
__device__ __forceinline__ void st_release_gpu(unsigned* p, unsigned v) {
    asm volatile("st.release.gpu.global.u32 [%0], %1;" :: "l"(p), "r"(v) : "memory");
}
__device__ __forceinline__ unsigned ld_acquire_gpu(unsigned* p) {
    unsigned v;
    asm volatile("ld.acquire.gpu.global.u32 %0, [%1];" : "=r"(v) : "l"(p) : "memory");
    return v;
}

__device__ __forceinline__ float block_reduce_256(float v, float* sr) {
    int tid = threadIdx.x;
#pragma unroll
    for (int off = 16; off; off >>= 1) v += __shfl_down_sync(0xffffffffu, v, off);
    if ((tid & 31) == 0) sr[tid >> 5] = v;
    __syncthreads();
    if (tid < 8) {
        v = sr[tid];
#pragma unroll
        for (int off = 4; off; off >>= 1) v += __shfl_down_sync(0xffu, v, off);
    }
    return v;
}

// ---------------- init ----------------
__global__ void k_warm() {}

__global__ void k_zero() {
    int idx = blockIdx.x * 256 + threadIdx.x;
    if (idx < DD * KK) g_Z[idx] = 0.0f;
    if (idx < 4) g_acc[idx] = 0.0;
    if (idx < 2) g_lbar[idx] = 0u;
    if (idx < 8) ((unsigned*)g_lrdy)[idx] = 0u;
}

// all bias fills in one launch: x, xw0, xw1, Amu, Als
__global__ void k_fill_all(const float* __restrict__ b_em, const float* __restrict__ bl0,
                           const float* __restrict__ bl1, const float* __restrict__ bmu,
                           const float* __restrict__ bls) {
    int idx = blockIdx.x * 256 + threadIdx.x;
    if (idx < TT * EH) { g_x[idx] = b_em[idx % EH]; return; }
    idx -= TT * EH;
    if (idx < TT * 4 * EH) { g_xw0[idx] = bl0[idx % (4 * EH)]; return; }
    idx -= TT * 4 * EH;
    if (idx < TT * 4 * EH) { g_xw1[idx] = bl1[idx % (4 * EH)]; return; }
    idx -= TT * 4 * EH;
    if (idx < TT * KK) { g_Amu[idx] = bmu[idx % KK]; return; }
    idx -= TT * KK;
    if (idx < TT * KK) { g_Als[idx] = bls[idx % KK]; return; }
}
#define FILL_ALL_N (TT * EH + 2 * TT * 4 * EH + 2 * TT * KK)

// kl_alpha: elementwise over (K,T,L)
__global__ void k_kl_alpha(const float* __restrict__ mu, const float* __restrict__ ls) {
    const int N = KK * TT * LL;
    int idx = blockIdx.x * 256 + threadIdx.x;
    float c = 0.0f;
    if (idx < N) {
        int r = idx % (TT * LL);
        int t = r / LL;
        float qm = mu[idx], ql = ls[idx];
        if (t == 0) {
            c = (expf(ql) + qm * qm) / (1.0f + 1e-6f) - 1.0f - ql;
        } else {
            const float LOGD = -5.2983174f;
            float den = expf(LOGD) + 1e-6f;
            float dm = qm - mu[idx - LL];
            c = (expf(ql) + dm * dm) / den - 1.0f + LOGD - ql;
        }
    }
    __shared__ float sr[8];
    float s = block_reduce_256(c, sr);
    if (threadIdx.x == 0) atomicAdd(&g_acc[1], 0.5 * (double)s);
}

// batched transpose of the 4 small weight matrices (z selects)
__global__ void k_transpose4(const float* __restrict__ A0, float* __restrict__ B0,
                             const float* __restrict__ A1, float* __restrict__ B1,
                             const float* __restrict__ A2, float* __restrict__ B2,
                             const float* __restrict__ A3, float* __restrict__ B3) {
    const float* A; float* B; int M, N;
    switch (blockIdx.z) {
        case 0:  A = A0; B = B0; M = EH + KK; N = KK; break;
        case 1:  A = A1; B = B1; M = EH + KK; N = KK; break;
        case 2:  A = A2; B = B2; M = TH;      N = KK; break;
        default: A = A3; B = B3; M = TH;      N = KK; break;
    }
    int m0 = blockIdx.x * 32, n0 = blockIdx.y * 32;
    if (m0 >= M || n0 >= N) return;
    __shared__ float tile[32][33];
    int tx = threadIdx.x, ty = threadIdx.y;
    int m = m0 + ty, n = n0 + tx;
    if (m < M && n < N) tile[ty][tx] = A[m * N + n];
    __syncthreads();
    int nb = n0 + ty, mb = m0 + tx;
    if (nb < N && mb < M) B[nb * M + mb] = tile[tx][ty];
}

__global__ void k_fill(float* __restrict__ C, const float* __restrict__ bias,
                       int M, int N) {
    int idx = blockIdx.x * 256 + threadIdx.x;
    if (idx < M * N) C[idx] = bias[idx % N];
}

__global__ void k_relu(float* __restrict__ C, int n) {
    int idx = blockIdx.x * 256 + threadIdx.x;
    if (idx < n) C[idx] = fmaxf(C[idx], 0.0f);
}

// split-K tiled GEMM: C += A(MxK) @ B(KxN) over k-slice, atomic epilogue
__global__ void k_gemm_sk(const float* __restrict__ A, const float* __restrict__ B,
                          float* __restrict__ C, int M, int N, int Kd, int kchunk) {
    __shared__ float sA[16][65];
    __shared__ float sB[16][64];
    int tid = threadIdx.x;
    int tx = tid & 15, ty = tid >> 4;
    int row0 = blockIdx.y * 64 + ty * 4;
    int col0 = blockIdx.x * 64 + tx * 4;
    int kb = blockIdx.z * kchunk;
    int ke = min(kb + kchunk, Kd);
    float acc[4][4];
#pragma unroll
    for (int i = 0; i < 4; i++)
#pragma unroll
        for (int j = 0; j < 4; j++) acc[i][j] = 0.0f;

    for (int k0 = kb; k0 < ke; k0 += 16) {
#pragma unroll
        for (int i = 0; i < 4; i++) {
            int idx = tid + i * 256;
            int m = idx >> 4, kk = idx & 15;
            int gm = blockIdx.y * 64 + m, gk = k0 + kk;
            float v = 0.0f;
            if (gm < M && gk < ke) v = A[gm * Kd + gk];
            sA[kk][m] = v;
        }
#pragma unroll
        for (int i = 0; i < 4; i++) {
            int idx = tid + i * 256;
            int kk = idx >> 6, n = idx & 63;
            int gk = k0 + kk, gn = blockIdx.x * 64 + n;
            float v = 0.0f;
            if (gk < ke && gn < N) v = B[gk * N + gn];
            sB[kk][n] = v;
        }
        __syncthreads();
#pragma unroll
        for (int kk = 0; kk < 16; kk++) {
            float a[4], b[4];
#pragma unroll
            for (int i = 0; i < 4; i++) a[i] = sA[kk][ty * 4 + i];
#pragma unroll
            for (int j = 0; j < 4; j++) b[j] = sB[kk][tx * 4 + j];
#pragma unroll
            for (int i = 0; i < 4; i++)
#pragma unroll
                for (int j = 0; j < 4; j++) acc[i][j] += a[i] * b[j];
        }
        __syncthreads();
    }
#pragma unroll
    for (int i = 0; i < 4; i++)
#pragma unroll
        for (int j = 0; j < 4; j++) {
            int m = row0 + i, n = col0 + j;
            if (m < M && n < N) atomicAdd(&C[m * N + n], acc[i][j]);
        }
}

// ---------------- LSTM: element-partitioned, weights + xw in SMEM ----------------
// 4 blocks x 416 threads. Block b owns h[b*50 .. b*50+50), all 4 gates.
// Whh slice (160KB) + xw slice (40KB) staged in dynamic smem once. Per-step sync
// via scoped release/acquire counters, tight spin (no nanosleep).
__global__ void __launch_bounds__(416) k_lstm_smem(const float* __restrict__ xw,
                                                   const float* __restrict__ Whh,
                                                   float* __restrict__ hs, int L) {
    extern __shared__ float s_w[];                 // [200][200] weights + [50][200] xw
    float* s_xw = s_w + 200 * 200;
    __shared__ __align__(16) float h_s[EH];
    __shared__ float c_s[50];
    __shared__ float g_loc[200];
    const int b = blockIdx.x;
    const int tid = threadIdx.x;

    for (int idx = tid; idx < 200 * 200; idx += 416) {
        int i = idx / 200, o = idx - (idx / 200) * 200;
        int gi = o / 50, e = o - gi * 50;
        int col = gi * 200 + b * 50 + e;
        s_w[o * 200 + i] = Whh[i * 800 + col];
    }
    for (int idx = tid; idx < TT * 200; idx += 416) {
        int t = idx / 200, o = idx - (idx / 200) * 200;
        int gi = o / 50, e = o - gi * 50;
        s_xw[idx] = xw[t * 800 + gi * 200 + b * 50 + e];
    }
    if (tid < EH) h_s[tid] = 0.0f;
    if (tid < 50) c_s[tid] = 0.0f;
    __syncthreads();

    const int o = ((tid >> 1) % 200);
    const int half = tid & 1;
    unsigned* rdy = g_lrdy[L];

    for (int t = 0; t < TT; t++) {
        const float4* wv = (const float4*)(s_w + o * 200 + half * 100);
        const float4* hv = ((const float4*)h_s) + half * 25;
        float4 a = make_float4(0.f, 0.f, 0.f, 0.f);
#pragma unroll
        for (int j = 0; j < 25; j++) {
            float4 w = wv[j], h4 = hv[j];
            a.x = fmaf(w.x, h4.x, a.x);
            a.y = fmaf(w.y, h4.y, a.y);
            a.z = fmaf(w.z, h4.z, a.z);
            a.w = fmaf(w.w, h4.w, a.w);
        }
        float s = (a.x + a.y) + (a.z + a.w);
        s += __shfl_down_sync(0xffffffffu, s, 1);
        if (half == 0 && tid < 400) g_loc[o] = s + s_xw[t * 200 + o];
        __syncthreads();
        if (tid < 50) {
            float ig = sigm(g_loc[tid]);
            float fg = sigm(g_loc[50 + tid]);
            float gg = tanhf(g_loc[100 + tid]);
            float og = sigm(g_loc[150 + tid]);
            float c = fg * c_s[tid] + ig * gg;
            float h = og * tanhf(c);
            c_s[tid] = c;
            __stcg(&hs[t * EH + b * 50 + tid], h);
        }
        __syncthreads();
        if (tid == 0) {
            st_release_gpu(&rdy[b], (unsigned)(t + 1));
        } else if (tid <= 3) {
            int p = (b + tid) & 3;
            while (ld_acquire_gpu(&rdy[p]) < (unsigned)(t + 1)) {}
        }
        __syncthreads();
        if (tid < EH) h_s[tid] = __ldcg(&hs[t * EH + tid]);
        __syncthreads();
    }
}

// ---------------- LSTM fallback ----------------
__global__ void __launch_bounds__(512) k_lstm4(const float* __restrict__ xw,
                                               const float* __restrict__ Whh,
                                               float* __restrict__ hs, int L) {
    __shared__ float h_s[EH];
    __shared__ float c_s[EH];
    __shared__ float4 p_s[8][52];
    const int b = blockIdx.x;
    const int tid = threadIdx.x;
    const int iq = tid / 50, c4 = tid % 50;
    if (tid < EH) { h_s[tid] = 0.0f; c_s[tid] = 0.0f; }
    __syncthreads();
    const float4* W4 = (const float4*)Whh;
    unsigned* bar = &g_lbar[L];
    for (int t = 0; t < TT; t++) {
        if (tid < 400) {
            float4 a = make_float4(0.f, 0.f, 0.f, 0.f);
            int base = b * 50 + c4;
#pragma unroll
            for (int u = 0; u < 25; u++) {
                int i = iq * 25 + u;
                float hv = h_s[i];
                float4 w = W4[i * 200 + base];
                a.x += hv * w.x; a.y += hv * w.y; a.z += hv * w.z; a.w += hv * w.w;
            }
            p_s[iq][c4] = a;
        }
        __syncthreads();
        if (tid < 200) {
            const float* ps = (const float*)p_s;
            float g = xw[t * 800 + b * 200 + tid];
#pragma unroll
            for (int q = 0; q < 8; q++) g += ps[q * 208 + tid];
            __stcg(&g_gbuf[t & 1][b * 200 + tid], g);
        }
        __threadfence();
        __syncthreads();
        if (tid == 0) {
            atomicAdd(bar, 1u);
            while (atomicAdd(bar, 0u) < 4u * (unsigned)(t + 1)) {}
        }
        __syncthreads();
        __threadfence();
        if (tid < EH) {
            const float* gb = g_gbuf[t & 1];
            float ig = sigm(__ldcg(&gb[tid]));
            float fg = sigm(__ldcg(&gb[EH + tid]));
            float gg = tanhf(__ldcg(&gb[2 * EH + tid]));
            float og = sigm(__ldcg(&gb[3 * EH + tid]));
            float c = fg * c_s[tid] + ig * gg;
            float h = og * tanhf(c);
            c_s[tid] = c;
            h_s[tid] = h;
            if (b == 0) hs[t * EH + tid] = h;
        }
        __syncthreads();
    }
}

// eta scan v2
__global__ void __launch_bounds__(128) k_eta2(const float* __restrict__ Amu,
                                              const float* __restrict__ Als) {
    __shared__ float eta_s[KK];
    __shared__ float mu_s[KK], ls_s[KK];
    __shared__ float kl_sh[2];
    int tid = threadIdx.x;
    int warp = tid >> 5;
    if (tid < KK) eta_s[tid] = 0.0f;
    __syncthreads();
    double kl_acc = 0.0;
    const float LOGD = -5.2983174f;
    for (int t = 0; t < TT; t++) {
        if (tid < KK) {
            float s = Amu[t * KK + tid];
            const float* W = &g_WmueT[tid * (EH + KK) + EH];
#pragma unroll
            for (int j = 0; j < KK; j++) s += eta_s[j] * W[j];
            mu_s[tid] = s;
        } else if (tid >= 64 && tid < 64 + KK) {
            int k = tid - 64;
            float s = Als[t * KK + k];
            const float* W = &g_WlseT[k * (EH + KK) + EH];
#pragma unroll
            for (int j = 0; j < KK; j++) s += eta_s[j] * W[j];
            ls_s[k] = s;
        }
        __syncthreads();
        if (tid < 64) {
            float term = 0.0f;
            if (tid < KK) {
                float pls = (t == 0) ? 0.0f : LOGD;
                float den = expf(pls) + 1e-6f;
                float dm = mu_s[tid] - eta_s[tid];
                term = (expf(ls_s[tid]) + dm * dm) / den - 1.0f + pls - ls_s[tid];
            }
#pragma unroll
            for (int off = 16; off; off >>= 1) term += __shfl_down_sync(0xffffffffu, term, off);
            if ((tid & 31) == 0) kl_sh[warp] = term;
        }
        __syncthreads();
        if (tid == 0) kl_acc += (double)(kl_sh[0] + kl_sh[1]);
        if (tid < KK) {
            eta_s[tid] = mu_s[tid];
            g_etas[t * KK + tid] = mu_s[tid];
        }
        __syncthreads();
    }
    if (tid == 0) g_acc[2] = 0.5 * kl_acc;
}

// eta_td scatter
__global__ void k_etatd(const int* __restrict__ times) {
    int idx = blockIdx.x * 256 + threadIdx.x;
    if (idx >= DD * KK) return;
    int d = idx / KK, k = idx - d * KK;
    g_eta_td[idx] = g_etas[times[d] * KK + k];
}

// mu_th / ls_th + softmax theta + kl_theta
__global__ void __launch_bounds__(128) k_muls(const float* __restrict__ bmu,
                                              const float* __restrict__ bls) {
    int d = blockIdx.x;
    __shared__ float h_s[TH];
    __shared__ float mu_s[KK], ls_s[KK];
    int tid = threadIdx.x, warp = tid >> 5, lane = tid & 31;
    for (int i = tid; i < TH; i += 128) h_s[i] = g_h2[d * TH + i];
    __syncthreads();
    for (int job = warp; job < 2 * KK; job += 4) {
        int k = job >> 1, isls = job & 1;
        const float* W = isls ? g_WlsthT : g_WmuthT;
        float s = 0.0f;
        for (int i = lane; i < TH; i += 32) s += h_s[i] * W[k * TH + i];
#pragma unroll
        for (int off = 16; off; off >>= 1) s += __shfl_down_sync(0xffffffffu, s, off);
        if (lane == 0) {
            s += isls ? bls[k] : bmu[k];
            if (isls) ls_s[k] = s; else mu_s[k] = s;
        }
    }
    __syncthreads();
    if (tid == 0) {
        float m = -1e30f;
        for (int k = 0; k < KK; k++) m = fmaxf(m, mu_s[k]);
        float sum = 0.0f;
        for (int k = 0; k < KK; k++) sum += expf(mu_s[k] - m);
        float inv = 1.0f / sum;
        double kl = 0.0;
        for (int k = 0; k < KK; k++) {
            g_theta[d * KK + k] = expf(mu_s[k] - m) * inv;
            float mu = mu_s[k], ls = ls_s[k], eta = g_eta_td[d * KK + k];
            float dm = mu - eta;
            kl += (double)((expf(ls) + dm * dm) / (1.0f + 1e-6f) - 1.0f - ls);
        }
        atomicAdd(&g_acc[3], 0.5 * kl);
    }
}

// wa[d,k,l] = alpha[k, t_d, l] * lam[s_d, l]
__global__ void k_wa(const float* __restrict__ alpha, const float* __restrict__ lam,
                     const int* __restrict__ times, const int* __restrict__ sources) {
    int idx = blockIdx.x * 256 + threadIdx.x;
    if (idx >= DD * KK * LL) return;
    int d = idx / (KK * LL);
    int r = idx - d * (KK * LL);
    int k = r / LL;
    int l = r - k * LL;
    int t = times[d], s = sources[d];
    g_wa[idx] = alpha[(k * TT + t) * LL + l] * lam[s * LL + l];
}

// ---------------- tf32 tensor-core batched GEMM + exp + Z ----------------
#define GK 32
#define GST 36
__global__ void __launch_bounds__(256) k_g1_mma(const float* __restrict__ rho) {
    __shared__ unsigned wa_s[64 * GST];
    __shared__ unsigned rho_s[256 * GST];
    __shared__ float zsh[64];
    const int d = blockIdx.y;
    const int v0 = blockIdx.x * 256;
    const int tid = threadIdx.x;
    const int warp = tid >> 5, lane = tid & 31;
    const int g = lane >> 2, tg = lane & 3;
    const int mhalf = warp >> 2, nq = warp & 3;

    if (tid < 64) zsh[tid] = 0.0f;

    float c[2][8][4];
#pragma unroll
    for (int mi = 0; mi < 2; mi++)
#pragma unroll
        for (int ni = 0; ni < 8; ni++)
#pragma unroll
            for (int j = 0; j < 4; j++) c[mi][ni][j] = 0.0f;

    const float* __restrict__ wa = g_wa + d * KK * LL;

    for (int chunk = 0; chunk < 10; chunk++) {
        const int l0 = chunk * GK;
#pragma unroll
        for (int it = 0; it < 2; it++) {
            int i = tid + it * 256;
            int m = i >> 3, kk4 = (i & 7) * 4;
            float4 v = make_float4(0.f, 0.f, 0.f, 0.f);
            if (m < KK && l0 + kk4 + 3 < LL)
                v = *(const float4*)(wa + m * LL + l0 + kk4);
            unsigned* ws = wa_s + m * GST + kk4;
            ws[0] = f2tf32(v.x); ws[1] = f2tf32(v.y);
            ws[2] = f2tf32(v.z); ws[3] = f2tf32(v.w);
        }
#pragma unroll
        for (int it = 0; it < 8; it++) {
            int i = tid + it * 256;
            int n = i >> 3, kk4 = (i & 7) * 4;
            int v = v0 + n;
            float4 val = make_float4(0.f, 0.f, 0.f, 0.f);
            if (v < VV && l0 + kk4 + 3 < LL)
                val = *(const float4*)(rho + v * LL + l0 + kk4);
            unsigned* rs = rho_s + n * GST + kk4;
            rs[0] = f2tf32(val.x); rs[1] = f2tf32(val.y);
            rs[2] = f2tf32(val.z); rs[3] = f2tf32(val.w);
        }
        __syncthreads();
#pragma unroll
        for (int ks = 0; ks < 4; ks++) {
            const int k0 = ks * 8;
            unsigned a[2][4], b[8][2];
#pragma unroll
            for (int mi = 0; mi < 2; mi++) {
                int rb = (mhalf * 2 + mi) * 16 + g;
                a[mi][0] = wa_s[rb * GST + k0 + tg];
                a[mi][1] = wa_s[(rb + 8) * GST + k0 + tg];
                a[mi][2] = wa_s[rb * GST + k0 + tg + 4];
                a[mi][3] = wa_s[(rb + 8) * GST + k0 + tg + 4];
            }
#pragma unroll
            for (int ni = 0; ni < 8; ni++) {
                int nb = (nq * 8 + ni) * 8 + g;
                b[ni][0] = rho_s[nb * GST + k0 + tg];
                b[ni][1] = rho_s[nb * GST + k0 + tg + 4];
            }
#pragma unroll
            for (int mi = 0; mi < 2; mi++)
#pragma unroll
                for (int ni = 0; ni < 8; ni++)
                    mma_tf32(c[mi][ni], a[mi], b[ni]);
        }
        __syncthreads();
    }

    float* Ebase = g_E + (size_t)d * KK * VV;
    float zlo[2] = {0.f, 0.f}, zhi[2] = {0.f, 0.f};
#pragma unroll
    for (int mi = 0; mi < 2; mi++) {
        int row_lo = (mhalf * 2 + mi) * 16 + g;
        int row_hi = row_lo + 8;
#pragma unroll
        for (int ni = 0; ni < 8; ni++) {
            int v = v0 + (nq * 8 + ni) * 8 + tg * 2;
            bool vok = (v < VV);
            float e0 = vok ? __expf(c[mi][ni][0]) : 0.0f;
            float e1 = vok ? __expf(c[mi][ni][1]) : 0.0f;
            float e2 = vok ? __expf(c[mi][ni][2]) : 0.0f;
            float e3 = vok ? __expf(c[mi][ni][3]) : 0.0f;
            if (row_lo < KK) {
                if (vok) *(float2*)(Ebase + (size_t)row_lo * VV + v) = make_float2(e0, e1);
                zlo[mi] += e0 + e1;
            }
            if (row_hi < KK) {
                if (vok) *(float2*)(Ebase + (size_t)row_hi * VV + v) = make_float2(e2, e3);
                zhi[mi] += e2 + e3;
            }
        }
        zlo[mi] += __shfl_xor_sync(0xffffffffu, zlo[mi], 1);
        zlo[mi] += __shfl_xor_sync(0xffffffffu, zlo[mi], 2);
        zhi[mi] += __shfl_xor_sync(0xffffffffu, zhi[mi], 1);
        zhi[mi] += __shfl_xor_sync(0xffffffffu, zhi[mi], 2);
        if (tg == 0) {
            if (row_lo < KK) atomicAdd(&zsh[row_lo], zlo[mi]);
            if (row_hi < KK) atomicAdd(&zsh[row_hi], zhi[mi]);
        }
    }
    __syncthreads();
    if (tid < KK) atomicAdd(&g_Z[d * KK + tid], zsh[tid]);
}

// nll: lik[d,v] = sum_k (theta/Z) * E ;  acc -= log(lik+1e-6)*bows
__global__ void k_nll(const float* __restrict__ bows) {
    int d = blockIdx.y;
    int v = blockIdx.x * 256 + threadIdx.x;
    __shared__ float wk[KK];
    if (threadIdx.x < KK)
        wk[threadIdx.x] = g_theta[d * KK + threadIdx.x] / g_Z[d * KK + threadIdx.x];
    __syncthreads();
    float term = 0.0f;
    if (v < VV) {
        const float* E = g_E + (size_t)d * KK * VV + v;
        float lik = 0.0f;
#pragma unroll
        for (int k = 0; k < KK; k++) lik += wk[k] * E[k * VV];
        term = __logf(lik + 1e-6f) * bows[d * VV + v];
    }
    __shared__ float sr[8];
    float s = block_reduce_256(term, sr);
    if (threadIdx.x == 0) atomicAdd(&g_acc[0], -(double)s);
}

__global__ void k_final(float* out) {
    int i = threadIdx.x;
    if (i < 4) out[i] = (float)g_acc[i];
}

// ---------------- static setup (outside measured window) ----------------
#define LSTM_SMEM ((200 * 200 + TT * 200) * 4)
struct StreamRes {
    cudaStream_t sB;
    cudaEvent_t evFork, evJoin, evH1, evT;
    bool ok;
    bool lstm_ok;
    StreamRes() {
        ok = true; lstm_ok = false;
        int loPri = 0, hiPri = 0;
        cudaDeviceGetStreamPriorityRange(&loPri, &hiPri);
        if (cudaStreamCreateWithPriority(&sB, cudaStreamNonBlocking, loPri) != cudaSuccess)
            ok = false;
        if (ok && cudaEventCreateWithFlags(&evFork, cudaEventDisableTiming) != cudaSuccess) ok = false;
        if (ok && cudaEventCreateWithFlags(&evJoin, cudaEventDisableTiming) != cudaSuccess) ok = false;
        if (ok && cudaEventCreateWithFlags(&evH1, cudaEventDisableTiming) != cudaSuccess) ok = false;
        if (ok && cudaEventCreateWithFlags(&evT, cudaEventDisableTiming) != cudaSuccess) ok = false;
        if (cudaFuncSetAttribute(k_lstm_smem,
                                 cudaFuncAttributeMaxDynamicSharedMemorySize,
                                 LSTM_SMEM) == cudaSuccess)
            lstm_ok = true;
        if (ok) {
            k_warm<<<1, 1, 0, sB>>>();
            if (cudaStreamSynchronize(sB) != cudaSuccess) ok = false;
        }
        (void)cudaGetLastError();
    }
};
static StreamRes g_sr;

// ---------------- launch ----------------
extern "C" void kernel_launch(void* const* d_in, const int* in_sizes, int n_in,
                              void* d_out, int out_size) {
    const float* bows    = (const float*)d_in[0];
    const float* rnn_inp = (const float*)d_in[1];
    const int*   times   = (const int*)d_in[2];
    const int*   sources = (const int*)d_in[3];
    const float* rho     = (const float*)d_in[4];
    const float* lam     = (const float*)d_in[5];
    const float* mu_qa   = (const float*)d_in[6];
    const float* ls_qa   = (const float*)d_in[7];
    const float* W_t1    = (const float*)d_in[8];
    const float* b_t1    = (const float*)d_in[9];
    const float* W_t2    = (const float*)d_in[10];
    const float* b_t2    = (const float*)d_in[11];
    const float* W_mu_th = (const float*)d_in[12];
    const float* b_mu_th = (const float*)d_in[13];
    const float* W_ls_th = (const float*)d_in[14];
    const float* b_ls_th = (const float*)d_in[15];
    const float* W_em    = (const float*)d_in[16];
    const float* b_em    = (const float*)d_in[17];
    const float* Wih0    = (const float*)d_in[18];
    const float* Whh0    = (const float*)d_in[19];
    const float* bl0     = (const float*)d_in[20];
    const float* Wih1    = (const float*)d_in[21];
    const float* Whh1    = (const float*)d_in[22];
    const float* bl1     = (const float*)d_in[23];
    const float* W_mu_e  = (const float*)d_in[24];
    const float* b_mu_e  = (const float*)d_in[25];
    const float* W_ls_e  = (const float*)d_in[26];
    const float* b_ls_e  = (const float*)d_in[27];

    float *p_x, *p_xw0, *p_xw1, *p_hs0, *p_hs1, *p_h1, *p_h2;
    float *p_WmueT, *p_WlseT, *p_WmuthT, *p_WlsthT, *p_Amu, *p_Als, *p_etd;
    cudaGetSymbolAddress((void**)&p_x, g_x);
    cudaGetSymbolAddress((void**)&p_xw0, g_xw0);
    cudaGetSymbolAddress((void**)&p_xw1, g_xw1);
    cudaGetSymbolAddress((void**)&p_hs0, g_hs0);
    cudaGetSymbolAddress((void**)&p_hs1, g_hs1);
    cudaGetSymbolAddress((void**)&p_h1, g_h1);
    cudaGetSymbolAddress((void**)&p_h2, g_h2);
    cudaGetSymbolAddress((void**)&p_WmueT, g_WmueT);
    cudaGetSymbolAddress((void**)&p_WlseT, g_WlseT);
    cudaGetSymbolAddress((void**)&p_WmuthT, g_WmuthT);
    cudaGetSymbolAddress((void**)&p_WlsthT, g_WlsthT);
    cudaGetSymbolAddress((void**)&p_Amu, g_Amu);
    cudaGetSymbolAddress((void**)&p_Als, g_Als);
    cudaGetSymbolAddress((void**)&p_etd, g_eta_td);

    cudaStream_t sA = 0;
    cudaStream_t sB = g_sr.ok ? g_sr.sB : (cudaStream_t)0;

    // ---- common prologue ----
    k_zero<<<(DD * KK + 255) / 256, 256, 0, sA>>>();

    if (g_sr.ok) {
        cudaEventRecord(g_sr.evFork, sA);
        cudaStreamWaitEvent(sB, g_sr.evFork, 0);
    }

    // ---- chain B (low-priority stream) ----
    k_transpose4<<<dim3((TH + 31) / 32, (KK + 31) / 32, 4), dim3(32, 32), 0, sB>>>(
        W_mu_e, p_WmueT, W_ls_e, p_WlseT, W_mu_th, p_WmuthT, W_ls_th, p_WlsthT);
    if (g_sr.ok) cudaEventRecord(g_sr.evT, sB);
    k_kl_alpha<<<(KK * TT * LL + 255) / 256, 256, 0, sB>>>(mu_qa, ls_qa);
    k_wa<<<(DD * KK * LL + 255) / 256, 256, 0, sB>>>(mu_qa, lam, times, sources);
    k_fill<<<(DD * TH + 255) / 256, 256, 0, sB>>>(p_h1, b_t1, DD, TH);
    k_gemm_sk<<<dim3((TH + 63) / 64, (DD + 63) / 64, 6), 256, 0, sB>>>(bows, W_t1, p_h1, DD, TH, VV, (VV + 5) / 6);
    if (g_sr.ok) cudaEventRecord(g_sr.evH1, sB);
    k_g1_mma<<<dim3(12, DD), 256, 0, sB>>>(rho);
    if (g_sr.ok) cudaEventRecord(g_sr.evJoin, sB);

    // ---- chain A (default stream, higher priority): sequential path ----
    k_fill_all<<<(FILL_ALL_N + 255) / 256, 256, 0, sA>>>(b_em, bl0, bl1, b_mu_e, b_ls_e);
    k_gemm_sk<<<dim3((EH + 63) / 64, 1, 12), 256, 0, sA>>>(rnn_inp, W_em, p_x, TT, EH, VV, (VV + 11) / 12);

    k_gemm_sk<<<dim3((4 * EH + 63) / 64, 1, 4), 256, 0, sA>>>(p_x, Wih0, p_xw0, TT, 4 * EH, EH, EH / 4);
    if (g_sr.lstm_ok) k_lstm_smem<<<4, 416, LSTM_SMEM, sA>>>(p_xw0, Whh0, p_hs0, 0);
    else              k_lstm4<<<4, 512, 0, sA>>>(p_xw0, Whh0, p_hs0, 0);

    k_gemm_sk<<<dim3((4 * EH + 63) / 64, 1, 4), 256, 0, sA>>>(p_hs0, Wih1, p_xw1, TT, 4 * EH, EH, EH / 4);
    if (g_sr.lstm_ok) k_lstm_smem<<<4, 416, LSTM_SMEM, sA>>>(p_xw1, Whh1, p_hs1, 1);
    else              k_lstm4<<<4, 512, 0, sA>>>(p_xw1, Whh1, p_hs1, 1);

    // eta precompute + scan (needs transposed weights from chain B)
    k_gemm_sk<<<dim3(1, 1, 1), 256, 0, sA>>>(p_hs1, W_mu_e, p_Amu, TT, KK, EH, EH);
    k_gemm_sk<<<dim3(1, 1, 1), 256, 0, sA>>>(p_hs1, W_ls_e, p_Als, TT, KK, EH, EH);
    if (g_sr.ok) cudaStreamWaitEvent(sA, g_sr.evT, 0);
    k_eta2<<<1, 128, 0, sA>>>(p_Amu, p_Als);
    k_etatd<<<(DD * KK + 255) / 256, 256, 0, sA>>>(times);

    // theta MLP: add eta part to h1, relu, h2, muls
    if (g_sr.ok) cudaStreamWaitEvent(sA, g_sr.evH1, 0);
    k_gemm_sk<<<dim3((TH + 63) / 64, (DD + 63) / 64, 1), 256, 0, sA>>>(p_etd, W_t1 + VV * TH, p_h1, DD, TH, KK, KK);
    k_relu<<<(DD * TH + 255) / 256, 256, 0, sA>>>(p_h1, DD * TH);
    k_fill<<<(DD * TH + 255) / 256, 256, 0, sA>>>(p_h2, b_t2, DD, TH);
    k_gemm_sk<<<dim3((TH + 63) / 64, (DD + 63) / 64, 3), 256, 0, sA>>>(p_h1, W_t2, p_h2, DD, TH, TH, (TH + 2) / 3);
    k_relu<<<(DD * TH + 255) / 256, 256, 0, sA>>>(p_h2, DD * TH);
    k_muls<<<DD, 128, 0, sA>>>(b_mu_th, b_ls_th);

    // ---- join, then nll + output ----
    if (g_sr.ok) cudaStreamWaitEvent(sA, g_sr.evJoin, 0);
    k_nll<<<dim3((VV + 255) / 256, DD), 256, 0, sA>>>(bows);
    k_final<<<1, 4, 0, sA>>>((float*)d_out);
    (void)in_sizes; (void)n_in; (void)out_size;
}

// round 15
// speedup vs baseline: 5.7650x; 1.0413x over previous
#include <cuda_runtime.h>
#include <math.h>

// ---------------- problem constants ----------------
#define KK 50
#define TT 50
#define VV 3000
#define LL 300
#define TH 800
#define EH 200
#define DD 256
#define SS 8

// ---------------- device scratch (static, no allocs) ----------------
__device__ double   g_acc[4];                 // nll, kl_alpha, kl_eta, kl_theta
__device__ unsigned g_lrdy[2][4];             // per-layer per-block ready counters
__device__ float  g_x[TT * EH];
__device__ float  g_xw0[TT * 4 * EH];
__device__ float  g_xw1[TT * 4 * EH];
__device__ float  g_hs0[TT * EH];
__device__ float  g_hs1[TT * EH];
__device__ float  g_etas[TT * KK];
__device__ float  g_Amu[TT * KK];
__device__ float  g_Als[TT * KK];
__device__ float  g_eta_td[DD * KK];
__device__ float  g_h1[DD * TH];
__device__ float  g_h2[DD * TH];
__device__ float  g_theta[DD * KK];
__device__ float  g_wa[DD * KK * LL];
__device__ float  g_WmueT[KK * (EH + KK)];
__device__ float  g_WlseT[KK * (EH + KK)];
__device__ float  g_WmuthT[KK * TH];
__device__ float  g_WlsthT[KK * TH];
__device__ float  g_E[DD * KK * VV];          // exp(logit), 153.6 MB
__device__ float  g_Z[DD * KK];

// ---------------- helpers ----------------
__device__ __forceinline__ float sigm(float x) { return 1.0f / (1.0f + expf(-x)); }

__device__ __forceinline__ unsigned f2tf32(float f) {
    unsigned r;
    asm("cvt.rna.tf32.f32 %0, %1;" : "=r"(r) : "f"(f));
    return r;
}
__device__ __forceinline__ void mma_tf32(float* c, const unsigned* a, const unsigned* b) {
    asm volatile(
        "mma.sync.aligned.m16n8k8.row.col.f32.tf32.tf32.f32 "
        "{%0,%1,%2,%3}, {%4,%5,%6,%7}, {%8,%9}, {%0,%1,%2,%3};"
        : "+f"(c[0]), "+f"(c[1]), "+f"(c[2]), "+f"(c[3])
        : "r"(a[0]), "r"(a[1]), "r"(a[2]), "r"(a[3]), "r"(b[0]), "r"(b[1]));
}
__device__ __forceinline__ void st_release_gpu(unsigned* p, unsigned v) {
    asm volatile("st.release.gpu.global.u32 [%0], %1;" :: "l"(p), "r"(v) : "memory");
}
__device__ __forceinline__ unsigned ld_acquire_gpu(unsigned* p) {
    unsigned v;
    asm volatile("ld.acquire.gpu.global.u32 %0, [%1];" : "=r"(v) : "l"(p) : "memory");
    return v;
}

__device__ __forceinline__ float block_reduce_256(float v, float* sr) {
    int tid = threadIdx.x;
#pragma unroll
    for (int off = 16; off; off >>= 1) v += __shfl_down_sync(0xffffffffu, v, off);
    if ((tid & 31) == 0) sr[tid >> 5] = v;
    __syncthreads();
    if (tid < 8) {
        v = sr[tid];
#pragma unroll
        for (int off = 4; off; off >>= 1) v += __shfl_down_sync(0xffu, v, off);
    }
    return v;
}

// ---------------- init ----------------
__global__ void k_warm() {}

__global__ void k_zero() {
    int idx = blockIdx.x * 256 + threadIdx.x;
    if (idx < DD * KK) g_Z[idx] = 0.0f;
    if (idx < 4) g_acc[idx] = 0.0;
    if (idx < 8) ((unsigned*)g_lrdy)[idx] = 0u;
}

// all bias fills in one launch: x, xw0, xw1, Amu, Als, h2
__global__ void k_fill_all(const float* __restrict__ b_em, const float* __restrict__ bl0,
                           const float* __restrict__ bl1, const float* __restrict__ bmu,
                           const float* __restrict__ bls, const float* __restrict__ b_t2) {
    int idx = blockIdx.x * 256 + threadIdx.x;
    if (idx < TT * EH) { g_x[idx] = b_em[idx % EH]; return; }
    idx -= TT * EH;
    if (idx < TT * 4 * EH) { g_xw0[idx] = bl0[idx % (4 * EH)]; return; }
    idx -= TT * 4 * EH;
    if (idx < TT * 4 * EH) { g_xw1[idx] = bl1[idx % (4 * EH)]; return; }
    idx -= TT * 4 * EH;
    if (idx < TT * KK) { g_Amu[idx] = bmu[idx % KK]; return; }
    idx -= TT * KK;
    if (idx < TT * KK) { g_Als[idx] = bls[idx % KK]; return; }
    idx -= TT * KK;
    if (idx < DD * TH) { g_h2[idx] = b_t2[idx % TH]; return; }
}
#define FILL_ALL_N (TT * EH + 2 * TT * 4 * EH + 2 * TT * KK + DD * TH)

// kl_alpha: elementwise over (K,T,L)
__global__ void k_kl_alpha(const float* __restrict__ mu, const float* __restrict__ ls) {
    const int N = KK * TT * LL;
    int idx = blockIdx.x * 256 + threadIdx.x;
    float c = 0.0f;
    if (idx < N) {
        int r = idx % (TT * LL);
        int t = r / LL;
        float qm = mu[idx], ql = ls[idx];
        if (t == 0) {
            c = (expf(ql) + qm * qm) / (1.0f + 1e-6f) - 1.0f - ql;
        } else {
            const float LOGD = -5.2983174f;
            float den = expf(LOGD) + 1e-6f;
            float dm = qm - mu[idx - LL];
            c = (expf(ql) + dm * dm) / den - 1.0f + LOGD - ql;
        }
    }
    __shared__ float sr[8];
    float s = block_reduce_256(c, sr);
    if (threadIdx.x == 0) atomicAdd(&g_acc[1], 0.5 * (double)s);
}

// batched transpose of the 4 small weight matrices (z selects)
__global__ void k_transpose4(const float* __restrict__ A0, float* __restrict__ B0,
                             const float* __restrict__ A1, float* __restrict__ B1,
                             const float* __restrict__ A2, float* __restrict__ B2,
                             const float* __restrict__ A3, float* __restrict__ B3) {
    const float* A; float* B; int M, N;
    switch (blockIdx.z) {
        case 0:  A = A0; B = B0; M = EH + KK; N = KK; break;
        case 1:  A = A1; B = B1; M = EH + KK; N = KK; break;
        case 2:  A = A2; B = B2; M = TH;      N = KK; break;
        default: A = A3; B = B3; M = TH;      N = KK; break;
    }
    int m0 = blockIdx.x * 32, n0 = blockIdx.y * 32;
    if (m0 >= M || n0 >= N) return;
    __shared__ float tile[32][33];
    int tx = threadIdx.x, ty = threadIdx.y;
    int m = m0 + ty, n = n0 + tx;
    if (m < M && n < N) tile[ty][tx] = A[m * N + n];
    __syncthreads();
    int nb = n0 + ty, mb = m0 + tx;
    if (nb < N && mb < M) B[nb * M + mb] = tile[tx][ty];
}

__global__ void k_fill(float* __restrict__ C, const float* __restrict__ bias,
                       int M, int N) {
    int idx = blockIdx.x * 256 + threadIdx.x;
    if (idx < M * N) C[idx] = bias[idx % N];
}

__global__ void k_relu(float* __restrict__ C, int n) {
    int idx = blockIdx.x * 256 + threadIdx.x;
    if (idx < n) C[idx] = fmaxf(C[idx], 0.0f);
}

// split-K tiled GEMM: C += A(MxK) @ B(KxN) over k-slice, atomic epilogue
__global__ void k_gemm_sk(const float* __restrict__ A, const float* __restrict__ B,
                          float* __restrict__ C, int M, int N, int Kd, int kchunk) {
    __shared__ float sA[16][65];
    __shared__ float sB[16][64];
    int tid = threadIdx.x;
    int tx = tid & 15, ty = tid >> 4;
    int row0 = blockIdx.y * 64 + ty * 4;
    int col0 = blockIdx.x * 64 + tx * 4;
    int kb = blockIdx.z * kchunk;
    int ke = min(kb + kchunk, Kd);
    float acc[4][4];
#pragma unroll
    for (int i = 0; i < 4; i++)
#pragma unroll
        for (int j = 0; j < 4; j++) acc[i][j] = 0.0f;

    for (int k0 = kb; k0 < ke; k0 += 16) {
#pragma unroll
        for (int i = 0; i < 4; i++) {
            int idx = tid + i * 256;
            int m = idx >> 4, kk = idx & 15;
            int gm = blockIdx.y * 64 + m, gk = k0 + kk;
            float v = 0.0f;
            if (gm < M && gk < ke) v = A[gm * Kd + gk];
            sA[kk][m] = v;
        }
#pragma unroll
        for (int i = 0; i < 4; i++) {
            int idx = tid + i * 256;
            int kk = idx >> 6, n = idx & 63;
            int gk = k0 + kk, gn = blockIdx.x * 64 + n;
            float v = 0.0f;
            if (gk < ke && gn < N) v = B[gk * N + gn];
            sB[kk][n] = v;
        }
        __syncthreads();
#pragma unroll
        for (int kk = 0; kk < 16; kk++) {
            float a[4], b[4];
#pragma unroll
            for (int i = 0; i < 4; i++) a[i] = sA[kk][ty * 4 + i];
#pragma unroll
            for (int j = 0; j < 4; j++) b[j] = sB[kk][tx * 4 + j];
#pragma unroll
            for (int i = 0; i < 4; i++)
#pragma unroll
                for (int j = 0; j < 4; j++) acc[i][j] += a[i] * b[j];
        }
        __syncthreads();
    }
#pragma unroll
    for (int i = 0; i < 4; i++)
#pragma unroll
        for (int j = 0; j < 4; j++) {
            int m = row0 + i, n = col0 + j;
            if (m < M && n < N) atomicAdd(&C[m * N + n], acc[i][j]);
        }
}

// ---------------- LSTM v4: register-resident weights ----------------
// 4 blocks x 416 threads. Block b owns h[b*50 .. b*50+50), all 4 gates.
// Each thread (o, half) holds its 100 Whh values in REGISTERS (loaded once).
// Per step: 100 FFMA from regs + broadcast LDS of h; xw slice in static smem;
// h exchange via global + scoped release/acquire counters.
__global__ void __launch_bounds__(416) k_lstm_reg(const float* __restrict__ xw,
                                                  const float* __restrict__ Whh,
                                                  float* __restrict__ hs, int L) {
    __shared__ float s_xw[TT * 200];               // 40 KB
    __shared__ __align__(16) float h_s[EH];
    __shared__ float c_s[50];
    __shared__ float g_loc[200];
    const int b = blockIdx.x;
    const int tid = threadIdx.x;
    const int o = ((tid >> 1) % 200);
    const int half = tid & 1;
    const int gi = o / 50, e = o - gi * 50;
    const int col = gi * 200 + b * 50 + e;

    // weights to registers (one-time)
    float w[100];
    if (tid < 400) {
#pragma unroll
        for (int j = 0; j < 100; j++)
            w[j] = Whh[(half * 100 + j) * 800 + col];
    }
    // stage xw slice
    for (int idx = tid; idx < TT * 200; idx += 416) {
        int t = idx / 200, oo = idx - (idx / 200) * 200;
        int gg = oo / 50, ee = oo - gg * 50;
        s_xw[idx] = xw[t * 800 + gg * 200 + b * 50 + ee];
    }
    if (tid < EH) h_s[tid] = 0.0f;
    if (tid < 50) c_s[tid] = 0.0f;
    __syncthreads();

    unsigned* rdy = g_lrdy[L];

    for (int t = 0; t < TT; t++) {
        float s = 0.0f;
        if (tid < 400) {
            const float4* hv = ((const float4*)h_s) + half * 25;
            float4 a = make_float4(0.f, 0.f, 0.f, 0.f);
#pragma unroll
            for (int j = 0; j < 25; j++) {
                float4 h4 = hv[j];
                a.x = fmaf(w[4 * j + 0], h4.x, a.x);
                a.y = fmaf(w[4 * j + 1], h4.y, a.y);
                a.z = fmaf(w[4 * j + 2], h4.z, a.z);
                a.w = fmaf(w[4 * j + 3], h4.w, a.w);
            }
            s = (a.x + a.y) + (a.z + a.w);
        }
        s += __shfl_down_sync(0xffffffffu, s, 1);
        if (half == 0 && tid < 400) g_loc[o] = s + s_xw[t * 200 + o];
        __syncthreads();
        if (tid < 50) {
            float ig = sigm(g_loc[tid]);
            float fg = sigm(g_loc[50 + tid]);
            float gg = tanhf(g_loc[100 + tid]);
            float og = sigm(g_loc[150 + tid]);
            float c = fg * c_s[tid] + ig * gg;
            float h = og * tanhf(c);
            c_s[tid] = c;
            __stcg(&hs[t * EH + b * 50 + tid], h);
        }
        __syncthreads();
        if (tid == 0) {
            st_release_gpu(&rdy[b], (unsigned)(t + 1));
        } else if (tid <= 3) {
            int p = (b + tid) & 3;
            while (ld_acquire_gpu(&rdy[p]) < (unsigned)(t + 1)) {}
        }
        __syncthreads();
        if (tid < EH) h_s[tid] = __ldcg(&hs[t * EH + tid]);
        __syncthreads();
    }
}

// eta scan v2
__global__ void __launch_bounds__(128) k_eta2(const float* __restrict__ Amu,
                                              const float* __restrict__ Als) {
    __shared__ float eta_s[KK];
    __shared__ float mu_s[KK], ls_s[KK];
    __shared__ float kl_sh[2];
    int tid = threadIdx.x;
    int warp = tid >> 5;
    if (tid < KK) eta_s[tid] = 0.0f;
    __syncthreads();
    double kl_acc = 0.0;
    const float LOGD = -5.2983174f;
    for (int t = 0; t < TT; t++) {
        if (tid < KK) {
            float s = Amu[t * KK + tid];
            const float* W = &g_WmueT[tid * (EH + KK) + EH];
#pragma unroll
            for (int j = 0; j < KK; j++) s += eta_s[j] * W[j];
            mu_s[tid] = s;
        } else if (tid >= 64 && tid < 64 + KK) {
            int k = tid - 64;
            float s = Als[t * KK + k];
            const float* W = &g_WlseT[k * (EH + KK) + EH];
#pragma unroll
            for (int j = 0; j < KK; j++) s += eta_s[j] * W[j];
            ls_s[k] = s;
        }
        __syncthreads();
        if (tid < 64) {
            float term = 0.0f;
            if (tid < KK) {
                float pls = (t == 0) ? 0.0f : LOGD;
                float den = expf(pls) + 1e-6f;
                float dm = mu_s[tid] - eta_s[tid];
                term = (expf(ls_s[tid]) + dm * dm) / den - 1.0f + pls - ls_s[tid];
            }
#pragma unroll
            for (int off = 16; off; off >>= 1) term += __shfl_down_sync(0xffffffffu, term, off);
            if ((tid & 31) == 0) kl_sh[warp] = term;
        }
        __syncthreads();
        if (tid == 0) kl_acc += (double)(kl_sh[0] + kl_sh[1]);
        if (tid < KK) {
            eta_s[tid] = mu_s[tid];
            g_etas[t * KK + tid] = mu_s[tid];
        }
        __syncthreads();
    }
    if (tid == 0) g_acc[2] = 0.5 * kl_acc;
}

// eta_td scatter
__global__ void k_etatd(const int* __restrict__ times) {
    int idx = blockIdx.x * 256 + threadIdx.x;
    if (idx >= DD * KK) return;
    int d = idx / KK, k = idx - d * KK;
    g_eta_td[idx] = g_etas[times[d] * KK + k];
}

// mu_th / ls_th + softmax theta + kl_theta
__global__ void __launch_bounds__(128) k_muls(const float* __restrict__ bmu,
                                              const float* __restrict__ bls) {
    int d = blockIdx.x;
    __shared__ float h_s[TH];
    __shared__ float mu_s[KK], ls_s[KK];
    int tid = threadIdx.x, warp = tid >> 5, lane = tid & 31;
    for (int i = tid; i < TH; i += 128) h_s[i] = g_h2[d * TH + i];
    __syncthreads();
    for (int job = warp; job < 2 * KK; job += 4) {
        int k = job >> 1, isls = job & 1;
        const float* W = isls ? g_WlsthT : g_WmuthT;
        float s = 0.0f;
        for (int i = lane; i < TH; i += 32) s += h_s[i] * W[k * TH + i];
#pragma unroll
        for (int off = 16; off; off >>= 1) s += __shfl_down_sync(0xffffffffu, s, off);
        if (lane == 0) {
            s += isls ? bls[k] : bmu[k];
            if (isls) ls_s[k] = s; else mu_s[k] = s;
        }
    }
    __syncthreads();
    if (tid == 0) {
        float m = -1e30f;
        for (int k = 0; k < KK; k++) m = fmaxf(m, mu_s[k]);
        float sum = 0.0f;
        for (int k = 0; k < KK; k++) sum += expf(mu_s[k] - m);
        float inv = 1.0f / sum;
        double kl = 0.0;
        for (int k = 0; k < KK; k++) {
            g_theta[d * KK + k] = expf(mu_s[k] - m) * inv;
            float mu = mu_s[k], ls = ls_s[k], eta = g_eta_td[d * KK + k];
            float dm = mu - eta;
            kl += (double)((expf(ls) + dm * dm) / (1.0f + 1e-6f) - 1.0f - ls);
        }
        atomicAdd(&g_acc[3], 0.5 * kl);
    }
}

// wa[d,k,l] = alpha[k, t_d, l] * lam[s_d, l]
__global__ void k_wa(const float* __restrict__ alpha, const float* __restrict__ lam,
                     const int* __restrict__ times, const int* __restrict__ sources) {
    int idx = blockIdx.x * 256 + threadIdx.x;
    if (idx >= DD * KK * LL) return;
    int d = idx / (KK * LL);
    int r = idx - d * (KK * LL);
    int k = r / LL;
    int l = r - k * LL;
    int t = times[d], s = sources[d];
    g_wa[idx] = alpha[(k * TT + t) * LL + l] * lam[s * LL + l];
}

// ---------------- tf32 tensor-core batched GEMM + exp + Z ----------------
#define GK 32
#define GST 36
__global__ void __launch_bounds__(256) k_g1_mma(const float* __restrict__ rho) {
    __shared__ unsigned wa_s[64 * GST];
    __shared__ unsigned rho_s[256 * GST];
    __shared__ float zsh[64];
    const int d = blockIdx.y;
    const int v0 = blockIdx.x * 256;
    const int tid = threadIdx.x;
    const int warp = tid >> 5, lane = tid & 31;
    const int g = lane >> 2, tg = lane & 3;
    const int mhalf = warp >> 2, nq = warp & 3;

    if (tid < 64) zsh[tid] = 0.0f;

    float c[2][8][4];
#pragma unroll
    for (int mi = 0; mi < 2; mi++)
#pragma unroll
        for (int ni = 0; ni < 8; ni++)
#pragma unroll
            for (int j = 0; j < 4; j++) c[mi][ni][j] = 0.0f;

    const float* __restrict__ wa = g_wa + d * KK * LL;

    for (int chunk = 0; chunk < 10; chunk++) {
        const int l0 = chunk * GK;
#pragma unroll
        for (int it = 0; it < 2; it++) {
            int i = tid + it * 256;
            int m = i >> 3, kk4 = (i & 7) * 4;
            float4 v = make_float4(0.f, 0.f, 0.f, 0.f);
            if (m < KK && l0 + kk4 + 3 < LL)
                v = *(const float4*)(wa + m * LL + l0 + kk4);
            unsigned* ws = wa_s + m * GST + kk4;
            ws[0] = f2tf32(v.x); ws[1] = f2tf32(v.y);
            ws[2] = f2tf32(v.z); ws[3] = f2tf32(v.w);
        }
#pragma unroll
        for (int it = 0; it < 8; it++) {
            int i = tid + it * 256;
            int n = i >> 3, kk4 = (i & 7) * 4;
            int v = v0 + n;
            float4 val = make_float4(0.f, 0.f, 0.f, 0.f);
            if (v < VV && l0 + kk4 + 3 < LL)
                val = *(const float4*)(rho + v * LL + l0 + kk4);
            unsigned* rs = rho_s + n * GST + kk4;
            rs[0] = f2tf32(val.x); rs[1] = f2tf32(val.y);
            rs[2] = f2tf32(val.z); rs[3] = f2tf32(val.w);
        }
        __syncthreads();
#pragma unroll
        for (int ks = 0; ks < 4; ks++) {
            const int k0 = ks * 8;
            unsigned a[2][4], b[8][2];
#pragma unroll
            for (int mi = 0; mi < 2; mi++) {
                int rb = (mhalf * 2 + mi) * 16 + g;
                a[mi][0] = wa_s[rb * GST + k0 + tg];
                a[mi][1] = wa_s[(rb + 8) * GST + k0 + tg];
                a[mi][2] = wa_s[rb * GST + k0 + tg + 4];
                a[mi][3] = wa_s[(rb + 8) * GST + k0 + tg + 4];
            }
#pragma unroll
            for (int ni = 0; ni < 8; ni++) {
                int nb = (nq * 8 + ni) * 8 + g;
                b[ni][0] = rho_s[nb * GST + k0 + tg];
                b[ni][1] = rho_s[nb * GST + k0 + tg + 4];
            }
#pragma unroll
            for (int mi = 0; mi < 2; mi++)
#pragma unroll
                for (int ni = 0; ni < 8; ni++)
                    mma_tf32(c[mi][ni], a[mi], b[ni]);
        }
        __syncthreads();
    }

    float* Ebase = g_E + (size_t)d * KK * VV;
    float zlo[2] = {0.f, 0.f}, zhi[2] = {0.f, 0.f};
#pragma unroll
    for (int mi = 0; mi < 2; mi++) {
        int row_lo = (mhalf * 2 + mi) * 16 + g;
        int row_hi = row_lo + 8;
#pragma unroll
        for (int ni = 0; ni < 8; ni++) {
            int v = v0 + (nq * 8 + ni) * 8 + tg * 2;
            bool vok = (v < VV);
            float e0 = vok ? __expf(c[mi][ni][0]) : 0.0f;
            float e1 = vok ? __expf(c[mi][ni][1]) : 0.0f;
            float e2 = vok ? __expf(c[mi][ni][2]) : 0.0f;
            float e3 = vok ? __expf(c[mi][ni][3]) : 0.0f;
            if (row_lo < KK) {
                if (vok) *(float2*)(Ebase + (size_t)row_lo * VV + v) = make_float2(e0, e1);
                zlo[mi] += e0 + e1;
            }
            if (row_hi < KK) {
                if (vok) *(float2*)(Ebase + (size_t)row_hi * VV + v) = make_float2(e2, e3);
                zhi[mi] += e2 + e3;
            }
        }
        zlo[mi] += __shfl_xor_sync(0xffffffffu, zlo[mi], 1);
        zlo[mi] += __shfl_xor_sync(0xffffffffu, zlo[mi], 2);
        zhi[mi] += __shfl_xor_sync(0xffffffffu, zhi[mi], 1);
        zhi[mi] += __shfl_xor_sync(0xffffffffu, zhi[mi], 2);
        if (tg == 0) {
            if (row_lo < KK) atomicAdd(&zsh[row_lo], zlo[mi]);
            if (row_hi < KK) atomicAdd(&zsh[row_hi], zhi[mi]);
        }
    }
    __syncthreads();
    if (tid < KK) atomicAdd(&g_Z[d * KK + tid], zsh[tid]);
}

// nll: lik[d,v] = sum_k (theta/Z) * E ;  acc -= log(lik+1e-6)*bows
__global__ void k_nll(const float* __restrict__ bows) {
    int d = blockIdx.y;
    int v = blockIdx.x * 256 + threadIdx.x;
    __shared__ float wk[KK];
    if (threadIdx.x < KK)
        wk[threadIdx.x] = g_theta[d * KK + threadIdx.x] / g_Z[d * KK + threadIdx.x];
    __syncthreads();
    float term = 0.0f;
    if (v < VV) {
        const float* E = g_E + (size_t)d * KK * VV + v;
        float lik = 0.0f;
#pragma unroll
        for (int k = 0; k < KK; k++) lik += wk[k] * E[k * VV];
        term = __logf(lik + 1e-6f) * bows[d * VV + v];
    }
    __shared__ float sr[8];
    float s = block_reduce_256(term, sr);
    if (threadIdx.x == 0) atomicAdd(&g_acc[0], -(double)s);
}

__global__ void k_final(float* out) {
    int i = threadIdx.x;
    if (i < 4) out[i] = (float)g_acc[i];
}

// ---------------- static setup (outside measured window) ----------------
struct StreamRes {
    cudaStream_t sB;
    cudaEvent_t evFork, evJoin, evH1, evT;
    bool ok;
    StreamRes() {
        ok = true;
        int loPri = 0, hiPri = 0;
        cudaDeviceGetStreamPriorityRange(&loPri, &hiPri);
        if (cudaStreamCreateWithPriority(&sB, cudaStreamNonBlocking, loPri) != cudaSuccess)
            ok = false;
        if (ok && cudaEventCreateWithFlags(&evFork, cudaEventDisableTiming) != cudaSuccess) ok = false;
        if (ok && cudaEventCreateWithFlags(&evJoin, cudaEventDisableTiming) != cudaSuccess) ok = false;
        if (ok && cudaEventCreateWithFlags(&evH1, cudaEventDisableTiming) != cudaSuccess) ok = false;
        if (ok && cudaEventCreateWithFlags(&evT, cudaEventDisableTiming) != cudaSuccess) ok = false;
        if (ok) {
            k_warm<<<1, 1, 0, sB>>>();
            if (cudaStreamSynchronize(sB) != cudaSuccess) ok = false;
        }
        (void)cudaGetLastError();
    }
};
static StreamRes g_sr;

// ---------------- launch ----------------
extern "C" void kernel_launch(void* const* d_in, const int* in_sizes, int n_in,
                              void* d_out, int out_size) {
    const float* bows    = (const float*)d_in[0];
    const float* rnn_inp = (const float*)d_in[1];
    const int*   times   = (const int*)d_in[2];
    const int*   sources = (const int*)d_in[3];
    const float* rho     = (const float*)d_in[4];
    const float* lam     = (const float*)d_in[5];
    const float* mu_qa   = (const float*)d_in[6];
    const float* ls_qa   = (const float*)d_in[7];
    const float* W_t1    = (const float*)d_in[8];
    const float* b_t1    = (const float*)d_in[9];
    const float* W_t2    = (const float*)d_in[10];
    const float* b_t2    = (const float*)d_in[11];
    const float* W_mu_th = (const float*)d_in[12];
    const float* b_mu_th = (const float*)d_in[13];
    const float* W_ls_th = (const float*)d_in[14];
    const float* b_ls_th = (const float*)d_in[15];
    const float* W_em    = (const float*)d_in[16];
    const float* b_em    = (const float*)d_in[17];
    const float* Wih0    = (const float*)d_in[18];
    const float* Whh0    = (const float*)d_in[19];
    const float* bl0     = (const float*)d_in[20];
    const float* Wih1    = (const float*)d_in[21];
    const float* Whh1    = (const float*)d_in[22];
    const float* bl1     = (const float*)d_in[23];
    const float* W_mu_e  = (const float*)d_in[24];
    const float* b_mu_e  = (const float*)d_in[25];
    const float* W_ls_e  = (const float*)d_in[26];
    const float* b_ls_e  = (const float*)d_in[27];

    float *p_x, *p_xw0, *p_xw1, *p_hs0, *p_hs1, *p_h1, *p_h2;
    float *p_WmueT, *p_WlseT, *p_WmuthT, *p_WlsthT, *p_Amu, *p_Als, *p_etd;
    cudaGetSymbolAddress((void**)&p_x, g_x);
    cudaGetSymbolAddress((void**)&p_xw0, g_xw0);
    cudaGetSymbolAddress((void**)&p_xw1, g_xw1);
    cudaGetSymbolAddress((void**)&p_hs0, g_hs0);
    cudaGetSymbolAddress((void**)&p_hs1, g_hs1);
    cudaGetSymbolAddress((void**)&p_h1, g_h1);
    cudaGetSymbolAddress((void**)&p_h2, g_h2);
    cudaGetSymbolAddress((void**)&p_WmueT, g_WmueT);
    cudaGetSymbolAddress((void**)&p_WlseT, g_WlseT);
    cudaGetSymbolAddress((void**)&p_WmuthT, g_WmuthT);
    cudaGetSymbolAddress((void**)&p_WlsthT, g_WlsthT);
    cudaGetSymbolAddress((void**)&p_Amu, g_Amu);
    cudaGetSymbolAddress((void**)&p_Als, g_Als);
    cudaGetSymbolAddress((void**)&p_etd, g_eta_td);

    cudaStream_t sA = 0;
    cudaStream_t sB = g_sr.ok ? g_sr.sB : (cudaStream_t)0;

    // ---- common prologue ----
    k_zero<<<(DD * KK + 255) / 256, 256, 0, sA>>>();

    if (g_sr.ok) {
        cudaEventRecord(g_sr.evFork, sA);
        cudaStreamWaitEvent(sB, g_sr.evFork, 0);
    }

    // ---- chain B (low-priority stream) ----
    k_transpose4<<<dim3((TH + 31) / 32, (KK + 31) / 32, 4), dim3(32, 32), 0, sB>>>(
        W_mu_e, p_WmueT, W_ls_e, p_WlseT, W_mu_th, p_WmuthT, W_ls_th, p_WlsthT);
    if (g_sr.ok) cudaEventRecord(g_sr.evT, sB);
    k_kl_alpha<<<(KK * TT * LL + 255) / 256, 256, 0, sB>>>(mu_qa, ls_qa);
    k_wa<<<(DD * KK * LL + 255) / 256, 256, 0, sB>>>(mu_qa, lam, times, sources);
    k_fill<<<(DD * TH + 255) / 256, 256, 0, sB>>>(p_h1, b_t1, DD, TH);
    k_gemm_sk<<<dim3((TH + 63) / 64, (DD + 63) / 64, 6), 256, 0, sB>>>(bows, W_t1, p_h1, DD, TH, VV, (VV + 5) / 6);
    if (g_sr.ok) cudaEventRecord(g_sr.evH1, sB);
    k_g1_mma<<<dim3(12, DD), 256, 0, sB>>>(rho);
    if (g_sr.ok) cudaEventRecord(g_sr.evJoin, sB);

    // ---- chain A (default stream, higher priority): sequential path ----
    k_fill_all<<<(FILL_ALL_N + 255) / 256, 256, 0, sA>>>(b_em, bl0, bl1, b_mu_e, b_ls_e, b_t2);
    k_gemm_sk<<<dim3((EH + 63) / 64, 1, 12), 256, 0, sA>>>(rnn_inp, W_em, p_x, TT, EH, VV, (VV + 11) / 12);

    k_gemm_sk<<<dim3((4 * EH + 63) / 64, 1, 4), 256, 0, sA>>>(p_x, Wih0, p_xw0, TT, 4 * EH, EH, EH / 4);
    k_lstm_reg<<<4, 416, 0, sA>>>(p_xw0, Whh0, p_hs0, 0);

    k_gemm_sk<<<dim3((4 * EH + 63) / 64, 1, 4), 256, 0, sA>>>(p_hs0, Wih1, p_xw1, TT, 4 * EH, EH, EH / 4);
    k_lstm_reg<<<4, 416, 0, sA>>>(p_xw1, Whh1, p_hs1, 1);

    // eta precompute + scan (needs transposed weights from chain B)
    k_gemm_sk<<<dim3(1, 1, 1), 256, 0, sA>>>(p_hs1, W_mu_e, p_Amu, TT, KK, EH, EH);
    k_gemm_sk<<<dim3(1, 1, 1), 256, 0, sA>>>(p_hs1, W_ls_e, p_Als, TT, KK, EH, EH);
    if (g_sr.ok) cudaStreamWaitEvent(sA, g_sr.evT, 0);
    k_eta2<<<1, 128, 0, sA>>>(p_Amu, p_Als);
    k_etatd<<<(DD * KK + 255) / 256, 256, 0, sA>>>(times);

    // theta MLP: add eta part to h1, relu, h2 (bias prefilled), relu, muls
    if (g_sr.ok) cudaStreamWaitEvent(sA, g_sr.evH1, 0);
    k_gemm_sk<<<dim3((TH + 63) / 64, (DD + 63) / 64, 1), 256, 0, sA>>>(p_etd, W_t1 + VV * TH, p_h1, DD, TH, KK, KK);
    k_relu<<<(DD * TH + 255) / 256, 256, 0, sA>>>(p_h1, DD * TH);
    k_gemm_sk<<<dim3((TH + 63) / 64, (DD + 63) / 64, 3), 256, 0, sA>>>(p_h1, W_t2, p_h2, DD, TH, TH, (TH + 2) / 3);
    k_relu<<<(DD * TH + 255) / 256, 256, 0, sA>>>(p_h2, DD * TH);
    k_muls<<<DD, 128, 0, sA>>>(b_mu_th, b_ls_th);

    // ---- join, then nll + output ----
    if (g_sr.ok) cudaStreamWaitEvent(sA, g_sr.evJoin, 0);
    k_nll<<<dim3((VV + 255) / 256, DD), 256, 0, sA>>>(bows);
    k_final<<<1, 4, 0, sA>>>((float*)d_out);
    (void)in_sizes; (void)n_in; (void)out_size;
}

// round 16
// speedup vs baseline: 6.1445x; 1.0658x over previous
#include <cuda_runtime.h>
#include <math.h>

// ---------------- problem constants ----------------
#define KK 50
#define TT 50
#define VV 3000
#define LL 300
#define TH 800
#define EH 200
#define DD 256
#define SS 8

// ---------------- device scratch (static, no allocs) ----------------
__device__ double   g_acc[4];                 // nll, kl_alpha, kl_eta, kl_theta
__device__ float  g_x[TT * EH];
__device__ float  g_xw0[TT * 4 * EH];
__device__ float  g_xw1[TT * 4 * EH];
__device__ float  g_hs0[TT * EH];
__device__ float  g_hs1[TT * EH];
__device__ float  g_etas[TT * KK];
__device__ float  g_Amu[TT * KK];
__device__ float  g_Als[TT * KK];
__device__ float  g_eta_td[DD * KK];
__device__ float  g_h1[DD * TH];
__device__ float  g_h2[DD * TH];
__device__ float  g_theta[DD * KK];
__device__ float  g_wa[DD * KK * LL];
__device__ float  g_WmueT[KK * (EH + KK)];
__device__ float  g_WlseT[KK * (EH + KK)];
__device__ float  g_WmuthT[KK * TH];
__device__ float  g_WlsthT[KK * TH];
__device__ float  g_E[DD * KK * VV];          // exp(logit), 153.6 MB
__device__ float  g_Z[DD * KK];

// ---------------- helpers ----------------
__device__ __forceinline__ float sigm(float x) { return 1.0f / (1.0f + expf(-x)); }

__device__ __forceinline__ unsigned f2tf32(float f) {
    unsigned r;
    asm("cvt.rna.tf32.f32 %0, %1;" : "=r"(r) : "f"(f));
    return r;
}
__device__ __forceinline__ void mma_tf32(float* c, const unsigned* a, const unsigned* b) {
    asm volatile(
        "mma.sync.aligned.m16n8k8.row.col.f32.tf32.tf32.f32 "
        "{%0,%1,%2,%3}, {%4,%5,%6,%7}, {%8,%9}, {%0,%1,%2,%3};"
        : "+f"(c[0]), "+f"(c[1]), "+f"(c[2]), "+f"(c[3])
        : "r"(a[0]), "r"(a[1]), "r"(a[2]), "r"(a[3]), "r"(b[0]), "r"(b[1]));
}
__device__ __forceinline__ unsigned smem_u32(const void* p) {
    unsigned a;
    asm("{ .reg .u64 t; cvta.to.shared.u64 t, %1; cvt.u32.u64 %0, t; }"
        : "=r"(a) : "l"(p));
    return a;
}
__device__ __forceinline__ void dsmem_st(unsigned local_addr, int rank, float v) {
    asm volatile(
        "{ .reg .b32 r; mapa.shared::cluster.u32 r, %0, %1; "
        "st.shared::cluster.f32 [r], %2; }"
        :: "r"(local_addr), "r"(rank), "f"(v) : "memory");
}

__device__ __forceinline__ float block_reduce_256(float v, float* sr) {
    int tid = threadIdx.x;
#pragma unroll
    for (int off = 16; off; off >>= 1) v += __shfl_down_sync(0xffffffffu, v, off);
    if ((tid & 31) == 0) sr[tid >> 5] = v;
    __syncthreads();
    if (tid < 8) {
        v = sr[tid];
#pragma unroll
        for (int off = 4; off; off >>= 1) v += __shfl_down_sync(0xffu, v, off);
    }
    return v;
}

// ---------------- init ----------------
__global__ void k_warm() {}

__global__ void k_zero() {
    int idx = blockIdx.x * 256 + threadIdx.x;
    if (idx < DD * KK) g_Z[idx] = 0.0f;
    if (idx < 4) g_acc[idx] = 0.0;
}

// all bias fills in one launch: x, xw0, xw1, Amu, Als, h2
__global__ void k_fill_all(const float* __restrict__ b_em, const float* __restrict__ bl0,
                           const float* __restrict__ bl1, const float* __restrict__ bmu,
                           const float* __restrict__ bls, const float* __restrict__ b_t2) {
    int idx = blockIdx.x * 256 + threadIdx.x;
    if (idx < TT * EH) { g_x[idx] = b_em[idx % EH]; return; }
    idx -= TT * EH;
    if (idx < TT * 4 * EH) { g_xw0[idx] = bl0[idx % (4 * EH)]; return; }
    idx -= TT * 4 * EH;
    if (idx < TT * 4 * EH) { g_xw1[idx] = bl1[idx % (4 * EH)]; return; }
    idx -= TT * 4 * EH;
    if (idx < TT * KK) { g_Amu[idx] = bmu[idx % KK]; return; }
    idx -= TT * KK;
    if (idx < TT * KK) { g_Als[idx] = bls[idx % KK]; return; }
    idx -= TT * KK;
    if (idx < DD * TH) { g_h2[idx] = b_t2[idx % TH]; return; }
}
#define FILL_ALL_N (TT * EH + 2 * TT * 4 * EH + 2 * TT * KK + DD * TH)

// kl_alpha: elementwise over (K,T,L)
__global__ void k_kl_alpha(const float* __restrict__ mu, const float* __restrict__ ls) {
    const int N = KK * TT * LL;
    int idx = blockIdx.x * 256 + threadIdx.x;
    float c = 0.0f;
    if (idx < N) {
        int r = idx % (TT * LL);
        int t = r / LL;
        float qm = mu[idx], ql = ls[idx];
        if (t == 0) {
            c = (expf(ql) + qm * qm) / (1.0f + 1e-6f) - 1.0f - ql;
        } else {
            const float LOGD = -5.2983174f;
            float den = expf(LOGD) + 1e-6f;
            float dm = qm - mu[idx - LL];
            c = (expf(ql) + dm * dm) / den - 1.0f + LOGD - ql;
        }
    }
    __shared__ float sr[8];
    float s = block_reduce_256(c, sr);
    if (threadIdx.x == 0) atomicAdd(&g_acc[1], 0.5 * (double)s);
}

// batched transpose of the 4 small weight matrices (z selects)
__global__ void k_transpose4(const float* __restrict__ A0, float* __restrict__ B0,
                             const float* __restrict__ A1, float* __restrict__ B1,
                             const float* __restrict__ A2, float* __restrict__ B2,
                             const float* __restrict__ A3, float* __restrict__ B3) {
    const float* A; float* B; int M, N;
    switch (blockIdx.z) {
        case 0:  A = A0; B = B0; M = EH + KK; N = KK; break;
        case 1:  A = A1; B = B1; M = EH + KK; N = KK; break;
        case 2:  A = A2; B = B2; M = TH;      N = KK; break;
        default: A = A3; B = B3; M = TH;      N = KK; break;
    }
    int m0 = blockIdx.x * 32, n0 = blockIdx.y * 32;
    if (m0 >= M || n0 >= N) return;
    __shared__ float tile[32][33];
    int tx = threadIdx.x, ty = threadIdx.y;
    int m = m0 + ty, n = n0 + tx;
    if (m < M && n < N) tile[ty][tx] = A[m * N + n];
    __syncthreads();
    int nb = n0 + ty, mb = m0 + tx;
    if (nb < N && mb < M) B[nb * M + mb] = tile[tx][ty];
}

__global__ void k_fill(float* __restrict__ C, const float* __restrict__ bias,
                       int M, int N) {
    int idx = blockIdx.x * 256 + threadIdx.x;
    if (idx < M * N) C[idx] = bias[idx % N];
}

__global__ void k_relu(float* __restrict__ C, int n) {
    int idx = blockIdx.x * 256 + threadIdx.x;
    if (idx < n) C[idx] = fmaxf(C[idx], 0.0f);
}

// split-K tiled GEMM: C += A(MxK) @ B(KxN) over k-slice, atomic epilogue
__global__ void k_gemm_sk(const float* __restrict__ A, const float* __restrict__ B,
                          float* __restrict__ C, int M, int N, int Kd, int kchunk) {
    __shared__ float sA[16][65];
    __shared__ float sB[16][64];
    int tid = threadIdx.x;
    int tx = tid & 15, ty = tid >> 4;
    int row0 = blockIdx.y * 64 + ty * 4;
    int col0 = blockIdx.x * 64 + tx * 4;
    int kb = blockIdx.z * kchunk;
    int ke = min(kb + kchunk, Kd);
    float acc[4][4];
#pragma unroll
    for (int i = 0; i < 4; i++)
#pragma unroll
        for (int j = 0; j < 4; j++) acc[i][j] = 0.0f;

    for (int k0 = kb; k0 < ke; k0 += 16) {
#pragma unroll
        for (int i = 0; i < 4; i++) {
            int idx = tid + i * 256;
            int m = idx >> 4, kk = idx & 15;
            int gm = blockIdx.y * 64 + m, gk = k0 + kk;
            float v = 0.0f;
            if (gm < M && gk < ke) v = A[gm * Kd + gk];
            sA[kk][m] = v;
        }
#pragma unroll
        for (int i = 0; i < 4; i++) {
            int idx = tid + i * 256;
            int kk = idx >> 6, n = idx & 63;
            int gk = k0 + kk, gn = blockIdx.x * 64 + n;
            float v = 0.0f;
            if (gk < ke && gn < N) v = B[gk * N + gn];
            sB[kk][n] = v;
        }
        __syncthreads();
#pragma unroll
        for (int kk = 0; kk < 16; kk++) {
            float a[4], b[4];
#pragma unroll
            for (int i = 0; i < 4; i++) a[i] = sA[kk][ty * 4 + i];
#pragma unroll
            for (int j = 0; j < 4; j++) b[j] = sB[kk][tx * 4 + j];
#pragma unroll
            for (int i = 0; i < 4; i++)
#pragma unroll
                for (int j = 0; j < 4; j++) acc[i][j] += a[i] * b[j];
        }
        __syncthreads();
    }
#pragma unroll
    for (int i = 0; i < 4; i++)
#pragma unroll
        for (int j = 0; j < 4; j++) {
            int m = row0 + i, n = col0 + j;
            if (m < M && n < N) atomicAdd(&C[m * N + n], acc[i][j]);
        }
}

// ---------------- LSTM v5: cluster + DSMEM h-broadcast ----------------
// Cluster of 4 CTAs x 416 threads. Block b owns h[b*50 .. b*50+50), all 4 gates,
// weights in registers. Per step: reg-FFMA dot; each owner thread writes its h
// into ALL four CTAs' h_s replicas via st.shared::cluster; one cluster barrier
// (release/acquire) replaces the L2 flag dance entirely.
__global__ void __launch_bounds__(416) __cluster_dims__(4, 1, 1)
k_lstm_cluster(const float* __restrict__ xw, const float* __restrict__ Whh,
               float* __restrict__ hs) {
    __shared__ float s_xw[TT * 200];               // 40 KB
    __shared__ __align__(16) float h_s[EH];
    __shared__ float c_s[50];
    __shared__ float g_loc[200];
    const int b = blockIdx.x;                      // == cluster rank (1 cluster)
    const int tid = threadIdx.x;
    const int o = ((tid >> 1) % 200);
    const int half = tid & 1;
    const int gi = o / 50, e = o - gi * 50;
    const int col = gi * 200 + b * 50 + e;

    // weights to registers (one-time)
    float w[100];
    if (tid < 400) {
#pragma unroll
        for (int j = 0; j < 100; j++)
            w[j] = Whh[(half * 100 + j) * 800 + col];
    }
    // stage xw slice (gate-major layout per block)
    for (int idx = tid; idx < TT * 200; idx += 416) {
        int t = idx / 200, oo = idx - (idx / 200) * 200;
        int gg = oo / 50, ee = oo - gg * 50;
        s_xw[idx] = xw[t * 800 + gg * 200 + b * 50 + ee];
    }
    if (tid < EH) h_s[tid] = 0.0f;
    if (tid < 50) c_s[tid] = 0.0f;
    __syncthreads();
    // all replicas initialized before any peer DSMEM write can land
    asm volatile("barrier.cluster.arrive.aligned;" ::: "memory");
    asm volatile("barrier.cluster.wait.aligned;" ::: "memory");

    const unsigned h_addr = smem_u32(h_s);

    for (int t = 0; t < TT; t++) {
        float s = 0.0f;
        if (tid < 400) {
            const float4* hv = ((const float4*)h_s) + half * 25;
            float4 a = make_float4(0.f, 0.f, 0.f, 0.f);
#pragma unroll
            for (int j = 0; j < 25; j++) {
                float4 h4 = hv[j];
                a.x = fmaf(w[4 * j + 0], h4.x, a.x);
                a.y = fmaf(w[4 * j + 1], h4.y, a.y);
                a.z = fmaf(w[4 * j + 2], h4.z, a.z);
                a.w = fmaf(w[4 * j + 3], h4.w, a.w);
            }
            s = (a.x + a.y) + (a.z + a.w);
        }
        s += __shfl_down_sync(0xffffffffu, s, 1);
        if (half == 0 && tid < 400) g_loc[o] = s + s_xw[t * 200 + o];
        __syncthreads();
        if (tid < 50) {
            float ig = sigm(g_loc[tid]);
            float fg = sigm(g_loc[50 + tid]);
            float gg = tanhf(g_loc[100 + tid]);
            float og = sigm(g_loc[150 + tid]);
            float c = fg * c_s[tid] + ig * gg;
            float h = og * tanhf(c);
            c_s[tid] = c;
            __stcg(&hs[t * EH + b * 50 + tid], h);   // downstream consumer
            unsigned dst = h_addr + (unsigned)(b * 50 + tid) * 4u;
#pragma unroll
            for (int r = 0; r < 4; r++) dsmem_st(dst, r, h);
        }
        // release own writes / acquire peers' writes
        asm volatile("barrier.cluster.arrive.aligned;" ::: "memory");
        asm volatile("barrier.cluster.wait.aligned;" ::: "memory");
    }
}

// eta scan v2
__global__ void __launch_bounds__(128) k_eta2(const float* __restrict__ Amu,
                                              const float* __restrict__ Als) {
    __shared__ float eta_s[KK];
    __shared__ float mu_s[KK], ls_s[KK];
    __shared__ float kl_sh[2];
    int tid = threadIdx.x;
    int warp = tid >> 5;
    if (tid < KK) eta_s[tid] = 0.0f;
    __syncthreads();
    double kl_acc = 0.0;
    const float LOGD = -5.2983174f;
    for (int t = 0; t < TT; t++) {
        if (tid < KK) {
            float s = Amu[t * KK + tid];
            const float* W = &g_WmueT[tid * (EH + KK) + EH];
#pragma unroll
            for (int j = 0; j < KK; j++) s += eta_s[j] * W[j];
            mu_s[tid] = s;
        } else if (tid >= 64 && tid < 64 + KK) {
            int k = tid - 64;
            float s = Als[t * KK + k];
            const float* W = &g_WlseT[k * (EH + KK) + EH];
#pragma unroll
            for (int j = 0; j < KK; j++) s += eta_s[j] * W[j];
            ls_s[k] = s;
        }
        __syncthreads();
        if (tid < 64) {
            float term = 0.0f;
            if (tid < KK) {
                float pls = (t == 0) ? 0.0f : LOGD;
                float den = expf(pls) + 1e-6f;
                float dm = mu_s[tid] - eta_s[tid];
                term = (expf(ls_s[tid]) + dm * dm) / den - 1.0f + pls - ls_s[tid];
            }
#pragma unroll
            for (int off = 16; off; off >>= 1) term += __shfl_down_sync(0xffffffffu, term, off);
            if ((tid & 31) == 0) kl_sh[warp] = term;
        }
        __syncthreads();
        if (tid == 0) kl_acc += (double)(kl_sh[0] + kl_sh[1]);
        if (tid < KK) {
            eta_s[tid] = mu_s[tid];
            g_etas[t * KK + tid] = mu_s[tid];
        }
        __syncthreads();
    }
    if (tid == 0) g_acc[2] = 0.5 * kl_acc;
}

// eta_td scatter
__global__ void k_etatd(const int* __restrict__ times) {
    int idx = blockIdx.x * 256 + threadIdx.x;
    if (idx >= DD * KK) return;
    int d = idx / KK, k = idx - d * KK;
    g_eta_td[idx] = g_etas[times[d] * KK + k];
}

// mu_th / ls_th + softmax theta + kl_theta
__global__ void __launch_bounds__(128) k_muls(const float* __restrict__ bmu,
                                              const float* __restrict__ bls) {
    int d = blockIdx.x;
    __shared__ float h_s[TH];
    __shared__ float mu_s[KK], ls_s[KK];
    int tid = threadIdx.x, warp = tid >> 5, lane = tid & 31;
    for (int i = tid; i < TH; i += 128) h_s[i] = g_h2[d * TH + i];
    __syncthreads();
    for (int job = warp; job < 2 * KK; job += 4) {
        int k = job >> 1, isls = job & 1;
        const float* W = isls ? g_WlsthT : g_WmuthT;
        float s = 0.0f;
        for (int i = lane; i < TH; i += 32) s += h_s[i] * W[k * TH + i];
#pragma unroll
        for (int off = 16; off; off >>= 1) s += __shfl_down_sync(0xffffffffu, s, off);
        if (lane == 0) {
            s += isls ? bls[k] : bmu[k];
            if (isls) ls_s[k] = s; else mu_s[k] = s;
        }
    }
    __syncthreads();
    if (tid == 0) {
        float m = -1e30f;
        for (int k = 0; k < KK; k++) m = fmaxf(m, mu_s[k]);
        float sum = 0.0f;
        for (int k = 0; k < KK; k++) sum += expf(mu_s[k] - m);
        float inv = 1.0f / sum;
        double kl = 0.0;
        for (int k = 0; k < KK; k++) {
            g_theta[d * KK + k] = expf(mu_s[k] - m) * inv;
            float mu = mu_s[k], ls = ls_s[k], eta = g_eta_td[d * KK + k];
            float dm = mu - eta;
            kl += (double)((expf(ls) + dm * dm) / (1.0f + 1e-6f) - 1.0f - ls);
        }
        atomicAdd(&g_acc[3], 0.5 * kl);
    }
}

// wa[d,k,l] = alpha[k, t_d, l] * lam[s_d, l]
__global__ void k_wa(const float* __restrict__ alpha, const float* __restrict__ lam,
                     const int* __restrict__ times, const int* __restrict__ sources) {
    int idx = blockIdx.x * 256 + threadIdx.x;
    if (idx >= DD * KK * LL) return;
    int d = idx / (KK * LL);
    int r = idx - d * (KK * LL);
    int k = r / LL;
    int l = r - k * LL;
    int t = times[d], s = sources[d];
    g_wa[idx] = alpha[(k * TT + t) * LL + l] * lam[s * LL + l];
}

// ---------------- tf32 tensor-core batched GEMM + exp + Z ----------------
#define GK 32
#define GST 36
__global__ void __launch_bounds__(256) k_g1_mma(const float* __restrict__ rho) {
    __shared__ unsigned wa_s[64 * GST];
    __shared__ unsigned rho_s[256 * GST];
    __shared__ float zsh[64];
    const int d = blockIdx.y;
    const int v0 = blockIdx.x * 256;
    const int tid = threadIdx.x;
    const int warp = tid >> 5, lane = tid & 31;
    const int g = lane >> 2, tg = lane & 3;
    const int mhalf = warp >> 2, nq = warp & 3;

    if (tid < 64) zsh[tid] = 0.0f;

    float c[2][8][4];
#pragma unroll
    for (int mi = 0; mi < 2; mi++)
#pragma unroll
        for (int ni = 0; ni < 8; ni++)
#pragma unroll
            for (int j = 0; j < 4; j++) c[mi][ni][j] = 0.0f;

    const float* __restrict__ wa = g_wa + d * KK * LL;

    for (int chunk = 0; chunk < 10; chunk++) {
        const int l0 = chunk * GK;
#pragma unroll
        for (int it = 0; it < 2; it++) {
            int i = tid + it * 256;
            int m = i >> 3, kk4 = (i & 7) * 4;
            float4 v = make_float4(0.f, 0.f, 0.f, 0.f);
            if (m < KK && l0 + kk4 + 3 < LL)
                v = *(const float4*)(wa + m * LL + l0 + kk4);
            unsigned* ws = wa_s + m * GST + kk4;
            ws[0] = f2tf32(v.x); ws[1] = f2tf32(v.y);
            ws[2] = f2tf32(v.z); ws[3] = f2tf32(v.w);
        }
#pragma unroll
        for (int it = 0; it < 8; it++) {
            int i = tid + it * 256;
            int n = i >> 3, kk4 = (i & 7) * 4;
            int v = v0 + n;
            float4 val = make_float4(0.f, 0.f, 0.f, 0.f);
            if (v < VV && l0 + kk4 + 3 < LL)
                val = *(const float4*)(rho + v * LL + l0 + kk4);
            unsigned* rs = rho_s + n * GST + kk4;
            rs[0] = f2tf32(val.x); rs[1] = f2tf32(val.y);
            rs[2] = f2tf32(val.z); rs[3] = f2tf32(val.w);
        }
        __syncthreads();
#pragma unroll
        for (int ks = 0; ks < 4; ks++) {
            const int k0 = ks * 8;
            unsigned a[2][4], b[8][2];
#pragma unroll
            for (int mi = 0; mi < 2; mi++) {
                int rb = (mhalf * 2 + mi) * 16 + g;
                a[mi][0] = wa_s[rb * GST + k0 + tg];
                a[mi][1] = wa_s[(rb + 8) * GST + k0 + tg];
                a[mi][2] = wa_s[rb * GST + k0 + tg + 4];
                a[mi][3] = wa_s[(rb + 8) * GST + k0 + tg + 4];
            }
#pragma unroll
            for (int ni = 0; ni < 8; ni++) {
                int nb = (nq * 8 + ni) * 8 + g;
                b[ni][0] = rho_s[nb * GST + k0 + tg];
                b[ni][1] = rho_s[nb * GST + k0 + tg + 4];
            }
#pragma unroll
            for (int mi = 0; mi < 2; mi++)
#pragma unroll
                for (int ni = 0; ni < 8; ni++)
                    mma_tf32(c[mi][ni], a[mi], b[ni]);
        }
        __syncthreads();
    }

    float* Ebase = g_E + (size_t)d * KK * VV;
    float zlo[2] = {0.f, 0.f}, zhi[2] = {0.f, 0.f};
#pragma unroll
    for (int mi = 0; mi < 2; mi++) {
        int row_lo = (mhalf * 2 + mi) * 16 + g;
        int row_hi = row_lo + 8;
#pragma unroll
        for (int ni = 0; ni < 8; ni++) {
            int v = v0 + (nq * 8 + ni) * 8 + tg * 2;
            bool vok = (v < VV);
            float e0 = vok ? __expf(c[mi][ni][0]) : 0.0f;
            float e1 = vok ? __expf(c[mi][ni][1]) : 0.0f;
            float e2 = vok ? __expf(c[mi][ni][2]) : 0.0f;
            float e3 = vok ? __expf(c[mi][ni][3]) : 0.0f;
            if (row_lo < KK) {
                if (vok) *(float2*)(Ebase + (size_t)row_lo * VV + v) = make_float2(e0, e1);
                zlo[mi] += e0 + e1;
            }
            if (row_hi < KK) {
                if (vok) *(float2*)(Ebase + (size_t)row_hi * VV + v) = make_float2(e2, e3);
                zhi[mi] += e2 + e3;
            }
        }
        zlo[mi] += __shfl_xor_sync(0xffffffffu, zlo[mi], 1);
        zlo[mi] += __shfl_xor_sync(0xffffffffu, zlo[mi], 2);
        zhi[mi] += __shfl_xor_sync(0xffffffffu, zhi[mi], 1);
        zhi[mi] += __shfl_xor_sync(0xffffffffu, zhi[mi], 2);
        if (tg == 0) {
            if (row_lo < KK) atomicAdd(&zsh[row_lo], zlo[mi]);
            if (row_hi < KK) atomicAdd(&zsh[row_hi], zhi[mi]);
        }
    }
    __syncthreads();
    if (tid < KK) atomicAdd(&g_Z[d * KK + tid], zsh[tid]);
}

// nll: lik[d,v] = sum_k (theta/Z) * E ;  acc -= log(lik+1e-6)*bows
__global__ void k_nll(const float* __restrict__ bows) {
    int d = blockIdx.y;
    int v = blockIdx.x * 256 + threadIdx.x;
    __shared__ float wk[KK];
    if (threadIdx.x < KK)
        wk[threadIdx.x] = g_theta[d * KK + threadIdx.x] / g_Z[d * KK + threadIdx.x];
    __syncthreads();
    float term = 0.0f;
    if (v < VV) {
        const float* E = g_E + (size_t)d * KK * VV + v;
        float lik = 0.0f;
#pragma unroll
        for (int k = 0; k < KK; k++) lik += wk[k] * E[k * VV];
        term = __logf(lik + 1e-6f) * bows[d * VV + v];
    }
    __shared__ float sr[8];
    float s = block_reduce_256(term, sr);
    if (threadIdx.x == 0) atomicAdd(&g_acc[0], -(double)s);
}

__global__ void k_final(float* out) {
    int i = threadIdx.x;
    if (i < 4) out[i] = (float)g_acc[i];
}

// ---------------- static setup (outside measured window) ----------------
struct StreamRes {
    cudaStream_t sB;
    cudaEvent_t evFork, evJoin, evH1, evT;
    bool ok;
    StreamRes() {
        ok = true;
        int loPri = 0, hiPri = 0;
        cudaDeviceGetStreamPriorityRange(&loPri, &hiPri);
        if (cudaStreamCreateWithPriority(&sB, cudaStreamNonBlocking, loPri) != cudaSuccess)
            ok = false;
        if (ok && cudaEventCreateWithFlags(&evFork, cudaEventDisableTiming) != cudaSuccess) ok = false;
        if (ok && cudaEventCreateWithFlags(&evJoin, cudaEventDisableTiming) != cudaSuccess) ok = false;
        if (ok && cudaEventCreateWithFlags(&evH1, cudaEventDisableTiming) != cudaSuccess) ok = false;
        if (ok && cudaEventCreateWithFlags(&evT, cudaEventDisableTiming) != cudaSuccess) ok = false;
        if (ok) {
            k_warm<<<1, 1, 0, sB>>>();
            if (cudaStreamSynchronize(sB) != cudaSuccess) ok = false;
        }
        (void)cudaGetLastError();
    }
};
static StreamRes g_sr;

// ---------------- launch ----------------
extern "C" void kernel_launch(void* const* d_in, const int* in_sizes, int n_in,
                              void* d_out, int out_size) {
    const float* bows    = (const float*)d_in[0];
    const float* rnn_inp = (const float*)d_in[1];
    const int*   times   = (const int*)d_in[2];
    const int*   sources = (const int*)d_in[3];
    const float* rho     = (const float*)d_in[4];
    const float* lam     = (const float*)d_in[5];
    const float* mu_qa   = (const float*)d_in[6];
    const float* ls_qa   = (const float*)d_in[7];
    const float* W_t1    = (const float*)d_in[8];
    const float* b_t1    = (const float*)d_in[9];
    const float* W_t2    = (const float*)d_in[10];
    const float* b_t2    = (const float*)d_in[11];
    const float* W_mu_th = (const float*)d_in[12];
    const float* b_mu_th = (const float*)d_in[13];
    const float* W_ls_th = (const float*)d_in[14];
    const float* b_ls_th = (const float*)d_in[15];
    const float* W_em    = (const float*)d_in[16];
    const float* b_em    = (const float*)d_in[17];
    const float* Wih0    = (const float*)d_in[18];
    const float* Whh0    = (const float*)d_in[19];
    const float* bl0     = (const float*)d_in[20];
    const float* Wih1    = (const float*)d_in[21];
    const float* Whh1    = (const float*)d_in[22];
    const float* bl1     = (const float*)d_in[23];
    const float* W_mu_e  = (const float*)d_in[24];
    const float* b_mu_e  = (const float*)d_in[25];
    const float* W_ls_e  = (const float*)d_in[26];
    const float* b_ls_e  = (const float*)d_in[27];

    float *p_x, *p_xw0, *p_xw1, *p_hs0, *p_hs1, *p_h1, *p_h2;
    float *p_WmueT, *p_WlseT, *p_WmuthT, *p_WlsthT, *p_Amu, *p_Als, *p_etd;
    cudaGetSymbolAddress((void**)&p_x, g_x);
    cudaGetSymbolAddress((void**)&p_xw0, g_xw0);
    cudaGetSymbolAddress((void**)&p_xw1, g_xw1);
    cudaGetSymbolAddress((void**)&p_hs0, g_hs0);
    cudaGetSymbolAddress((void**)&p_hs1, g_hs1);
    cudaGetSymbolAddress((void**)&p_h1, g_h1);
    cudaGetSymbolAddress((void**)&p_h2, g_h2);
    cudaGetSymbolAddress((void**)&p_WmueT, g_WmueT);
    cudaGetSymbolAddress((void**)&p_WlseT, g_WlseT);
    cudaGetSymbolAddress((void**)&p_WmuthT, g_WmuthT);
    cudaGetSymbolAddress((void**)&p_WlsthT, g_WlsthT);
    cudaGetSymbolAddress((void**)&p_Amu, g_Amu);
    cudaGetSymbolAddress((void**)&p_Als, g_Als);
    cudaGetSymbolAddress((void**)&p_etd, g_eta_td);

    cudaStream_t sA = 0;
    cudaStream_t sB = g_sr.ok ? g_sr.sB : (cudaStream_t)0;

    // ---- common prologue ----
    k_zero<<<(DD * KK + 255) / 256, 256, 0, sA>>>();

    if (g_sr.ok) {
        cudaEventRecord(g_sr.evFork, sA);
        cudaStreamWaitEvent(sB, g_sr.evFork, 0);
    }

    // ---- chain B (low-priority stream) ----
    k_transpose4<<<dim3((TH + 31) / 32, (KK + 31) / 32, 4), dim3(32, 32), 0, sB>>>(
        W_mu_e, p_WmueT, W_ls_e, p_WlseT, W_mu_th, p_WmuthT, W_ls_th, p_WlsthT);
    if (g_sr.ok) cudaEventRecord(g_sr.evT, sB);
    k_kl_alpha<<<(KK * TT * LL + 255) / 256, 256, 0, sB>>>(mu_qa, ls_qa);
    k_wa<<<(DD * KK * LL + 255) / 256, 256, 0, sB>>>(mu_qa, lam, times, sources);
    k_fill<<<(DD * TH + 255) / 256, 256, 0, sB>>>(p_h1, b_t1, DD, TH);
    k_gemm_sk<<<dim3((TH + 63) / 64, (DD + 63) / 64, 6), 256, 0, sB>>>(bows, W_t1, p_h1, DD, TH, VV, (VV + 5) / 6);
    if (g_sr.ok) cudaEventRecord(g_sr.evH1, sB);
    k_g1_mma<<<dim3(12, DD), 256, 0, sB>>>(rho);
    if (g_sr.ok) cudaEventRecord(g_sr.evJoin, sB);

    // ---- chain A (default stream, higher priority): sequential path ----
    k_fill_all<<<(FILL_ALL_N + 255) / 256, 256, 0, sA>>>(b_em, bl0, bl1, b_mu_e, b_ls_e, b_t2);
    k_gemm_sk<<<dim3((EH + 63) / 64, 1, 12), 256, 0, sA>>>(rnn_inp, W_em, p_x, TT, EH, VV, (VV + 11) / 12);

    k_gemm_sk<<<dim3((4 * EH + 63) / 64, 1, 4), 256, 0, sA>>>(p_x, Wih0, p_xw0, TT, 4 * EH, EH, EH / 4);
    k_lstm_cluster<<<4, 416, 0, sA>>>(p_xw0, Whh0, p_hs0);

    k_gemm_sk<<<dim3((4 * EH + 63) / 64, 1, 4), 256, 0, sA>>>(p_hs0, Wih1, p_xw1, TT, 4 * EH, EH, EH / 4);
    k_lstm_cluster<<<4, 416, 0, sA>>>(p_xw1, Whh1, p_hs1);

    // eta precompute + scan (needs transposed weights from chain B)
    k_gemm_sk<<<dim3(1, 1, 1), 256, 0, sA>>>(p_hs1, W_mu_e, p_Amu, TT, KK, EH, EH);
    k_gemm_sk<<<dim3(1, 1, 1), 256, 0, sA>>>(p_hs1, W_ls_e, p_Als, TT, KK, EH, EH);
    if (g_sr.ok) cudaStreamWaitEvent(sA, g_sr.evT, 0);
    k_eta2<<<1, 128, 0, sA>>>(p_Amu, p_Als);
    k_etatd<<<(DD * KK + 255) / 256, 256, 0, sA>>>(times);

    // theta MLP: add eta part to h1, relu, h2 (bias prefilled), relu, muls
    if (g_sr.ok) cudaStreamWaitEvent(sA, g_sr.evH1, 0);
    k_gemm_sk<<<dim3((TH + 63) / 64, (DD + 63) / 64, 1), 256, 0, sA>>>(p_etd, W_t1 + VV * TH, p_h1, DD, TH, KK, KK);
    k_relu<<<(DD * TH + 255) / 256, 256, 0, sA>>>(p_h1, DD * TH);
    k_gemm_sk<<<dim3((TH + 63) / 64, (DD + 63) / 64, 3), 256, 0, sA>>>(p_h1, W_t2, p_h2, DD, TH, TH, (TH + 2) / 3);
    k_relu<<<(DD * TH + 255) / 256, 256, 0, sA>>>(p_h2, DD * TH);
    k_muls<<<DD, 128, 0, sA>>>(b_mu_th, b_ls_th);

    // ---- join, then nll + output ----
    if (g_sr.ok) cudaStreamWaitEvent(sA, g_sr.evJoin, 0);
    k_nll<<<dim3((VV + 255) / 256, DD), 256, 0, sA>>>(bows);
    k_final<<<1, 4, 0, sA>>>((float*)d_out);
    (void)in_sizes; (void)n_in; (void)out_size;
}